// round 6
// baseline (speedup 1.0000x reference)
#include <cuda_runtime.h>
#include <math.h>
#include <stdint.h>

#define D_MODEL 1024
#define NHEAD 16
#define HEAD_DIM 64
#define MOE_HIDDEN 2048
#define NUM_EXPERTS 4
#define BATCH 8
#define SEQ 1024
#define TOKENS (BATCH*SEQ)          /* 8192  */
#define BND (TOKENS*D_MODEL)        /* 8388608 */
#define LN_EPS 1e-5f

// ---------------- scratch (device globals; no allocation) ----------------
__device__ float g_Tr[BND];
__device__ float g_S[BND];
__device__ float g_buf[BND];
__device__ float g_q[BND];
__device__ float g_k[BND];
__device__ float g_v[BND];
__device__ float g_y[BND];
__device__ float g_xs[BND];
__device__ float g_h[TOKENS*MOE_HIDDEN];
__device__ float g_w[TOKENS*NUM_EXPERTS];
__device__ float g_gates[TOKENS*NUM_EXPERTS];
__device__ int   g_elist[NUM_EXPERTS*TOKENS];   // per-expert token lists (padded)
__device__ int   g_ecnt[NUM_EXPERTS];

// ============================================================
// tf32 helpers (sm_80+ PTX, no 'a'-suffix gating)
// ============================================================
__device__ __forceinline__ uint32_t f2tf32(float f) {
    uint32_t u; asm("cvt.rna.tf32.f32 %0, %1;" : "=r"(u) : "f"(f)); return u;
}
__device__ __forceinline__ void mma_tf32(float* c, const uint32_t* a, const uint32_t* b) {
    asm volatile(
        "mma.sync.aligned.m16n8k8.row.col.f32.tf32.tf32.f32 "
        "{%0,%1,%2,%3}, {%4,%5,%6,%7}, {%8,%9}, {%0,%1,%2,%3};"
        : "+f"(c[0]), "+f"(c[1]), "+f"(c[2]), "+f"(c[3])
        : "r"(a[0]), "r"(a[1]), "r"(a[2]), "r"(a[3]), "r"(b[0]), "r"(b[1]));
}

// ============================================================
// tf32 mma.sync GEMM: C[m,n] = sum_k A[m,k]*B[n,k] (+bias, epilogue)
// CTA tile 128x128, BK=16, 128 thr (4 warps 2x2, warp tile 64x64),
// double-buffered smem [128][20], register-prefetch, 1 sync/K-iter,
// 2 CTAs/SM. Raised AI: 16.4 flop per smem byte (was 10.9).
// Optional row gather (aidx) for A, row scatter+guard (cidx,cnt) for C.
// EPI: 0 plain, 1 GELU, 2 +resid, 3 scatter C[row] += v*w[row,e]
// ============================================================
#define TCG_LDA 20
#define TCG_BUF (128*TCG_LDA)
#define TCG_SMEM (4*TCG_BUF*4)   /* 40960 B */

template<int EPI>
__global__ void __launch_bounds__(128, 2) tc_gemm(
    const float* __restrict__ A, const float* __restrict__ B,
    const float* __restrict__ bias, float* __restrict__ C,
    int K, int Nn,
    const float* __restrict__ resid, const float* __restrict__ wts, int expert,
    const int* __restrict__ aidx, const int* __restrict__ cidx,
    const int* __restrict__ cntp)
{
    extern __shared__ uint32_t smu[];
    const int tid = threadIdx.x;
    const int bm = blockIdx.y * 128, bn = blockIdx.x * 128;
    int cnt = 0x7fffffff;
    if (cntp) { cnt = *cntp; if (bm >= ((cnt + 127) & ~127)) return; }

    uint32_t* As = smu;                 // [2][128*20]
    uint32_t* Bs = smu + 2*TCG_BUF;
    const int warp = tid >> 5, lane = tid & 31;
    const int wm = (warp >> 1) * 64, wn = (warp & 1) * 64;
    const int g = lane >> 2, t = lane & 3;

    const int lr = tid >> 1;            // staging row 0..63 (and +64)
    const int lc = (tid & 1) * 2;       // float4 col 0 or 2 (handles lc, lc+1)
    int ra0 = bm + lr, ra1 = bm + lr + 64;
    if (aidx) { ra0 = aidx[ra0]; ra1 = aidx[ra1]; }
    const float* Ag0 = A + (size_t)ra0 * K + lc * 4;
    const float* Ag1 = A + (size_t)ra1 * K + lc * 4;
    const float* Bg0 = B + (size_t)(bn + lr) * K + lc * 4;
    const float* Bg1 = B + (size_t)(bn + lr + 64) * K + lc * 4;

    float acc[4][8][4];
    #pragma unroll
    for (int i = 0; i < 4; i++)
        #pragma unroll
        for (int j = 0; j < 8; j++)
            #pragma unroll
            for (int r = 0; r < 4; r++) acc[i][j][r] = 0.f;

    const int NT = K >> 4;
    float4 pa[2][2], pb[2][2];
    #pragma unroll
    for (int cc = 0; cc < 2; cc++) {
        pa[0][cc] = *(const float4*)(Ag0 + cc*4);
        pa[1][cc] = *(const float4*)(Ag1 + cc*4);
        pb[0][cc] = *(const float4*)(Bg0 + cc*4);
        pb[1][cc] = *(const float4*)(Bg1 + cc*4);
    }
    #pragma unroll
    for (int cc = 0; cc < 2; cc++) {
        uint4 a0 = { f2tf32(pa[0][cc].x), f2tf32(pa[0][cc].y), f2tf32(pa[0][cc].z), f2tf32(pa[0][cc].w) };
        uint4 a1 = { f2tf32(pa[1][cc].x), f2tf32(pa[1][cc].y), f2tf32(pa[1][cc].z), f2tf32(pa[1][cc].w) };
        uint4 b0 = { f2tf32(pb[0][cc].x), f2tf32(pb[0][cc].y), f2tf32(pb[0][cc].z), f2tf32(pb[0][cc].w) };
        uint4 b1 = { f2tf32(pb[1][cc].x), f2tf32(pb[1][cc].y), f2tf32(pb[1][cc].z), f2tf32(pb[1][cc].w) };
        *(uint4*)&As[lr*TCG_LDA + (lc+cc)*4]      = a0;
        *(uint4*)&As[(lr+64)*TCG_LDA + (lc+cc)*4] = a1;
        *(uint4*)&Bs[lr*TCG_LDA + (lc+cc)*4]      = b0;
        *(uint4*)&Bs[(lr+64)*TCG_LDA + (lc+cc)*4] = b1;
    }
    __syncthreads();

    for (int kt = 0; kt < NT; kt++) {
        const uint32_t* Ab = As + (kt & 1)*TCG_BUF;
        const uint32_t* Bb = Bs + (kt & 1)*TCG_BUF;
        if (kt + 1 < NT) {
            const int ko = (kt + 1) * 16;
            #pragma unroll
            for (int cc = 0; cc < 2; cc++) {
                pa[0][cc] = *(const float4*)(Ag0 + ko + cc*4);
                pa[1][cc] = *(const float4*)(Ag1 + ko + cc*4);
                pb[0][cc] = *(const float4*)(Bg0 + ko + cc*4);
                pb[1][cc] = *(const float4*)(Bg1 + ko + cc*4);
            }
        }
        #pragma unroll
        for (int ks = 0; ks < 2; ks++) {
            const int kb = ks * 8;
            uint32_t af[4][4], bf[8][2];
            #pragma unroll
            for (int mf = 0; mf < 4; mf++) {
                const uint32_t* base = Ab + (wm + mf*16 + g)*TCG_LDA + kb + t;
                af[mf][0] = base[0];
                af[mf][1] = base[8*TCG_LDA];
                af[mf][2] = base[4];
                af[mf][3] = base[8*TCG_LDA + 4];
            }
            #pragma unroll
            for (int nf = 0; nf < 8; nf++) {
                const uint32_t* base = Bb + (wn + nf*8 + g)*TCG_LDA + kb + t;
                bf[nf][0] = base[0];
                bf[nf][1] = base[4];
            }
            #pragma unroll
            for (int mf = 0; mf < 4; mf++)
                #pragma unroll
                for (int nf = 0; nf < 8; nf++)
                    mma_tf32(acc[mf][nf], af[mf], bf[nf]);
        }
        if (kt + 1 < NT) {
            uint32_t* Ad = As + ((kt+1) & 1)*TCG_BUF;
            uint32_t* Bd = Bs + ((kt+1) & 1)*TCG_BUF;
            #pragma unroll
            for (int cc = 0; cc < 2; cc++) {
                uint4 a0 = { f2tf32(pa[0][cc].x), f2tf32(pa[0][cc].y), f2tf32(pa[0][cc].z), f2tf32(pa[0][cc].w) };
                uint4 a1 = { f2tf32(pa[1][cc].x), f2tf32(pa[1][cc].y), f2tf32(pa[1][cc].z), f2tf32(pa[1][cc].w) };
                uint4 b0 = { f2tf32(pb[0][cc].x), f2tf32(pb[0][cc].y), f2tf32(pb[0][cc].z), f2tf32(pb[0][cc].w) };
                uint4 b1 = { f2tf32(pb[1][cc].x), f2tf32(pb[1][cc].y), f2tf32(pb[1][cc].z), f2tf32(pb[1][cc].w) };
                *(uint4*)&Ad[lr*TCG_LDA + (lc+cc)*4]      = a0;
                *(uint4*)&Ad[(lr+64)*TCG_LDA + (lc+cc)*4] = a1;
                *(uint4*)&Bd[lr*TCG_LDA + (lc+cc)*4]      = b0;
                *(uint4*)&Bd[(lr+64)*TCG_LDA + (lc+cc)*4] = b1;
            }
            __syncthreads();
        }
    }

    // ---- epilogue ----
    #pragma unroll
    for (int mf = 0; mf < 4; mf++) {
        const int mp0 = bm + wm + mf*16 + g;
        const int mp1 = mp0 + 8;
        if (EPI == 3) {
            const int r0 = cidx[mp0], r1 = cidx[mp1];
            const float w0 = wts[r0*NUM_EXPERTS + expert];
            const float w1 = wts[r1*NUM_EXPERTS + expert];
            const bool ok0 = mp0 < cnt, ok1 = mp1 < cnt;
            #pragma unroll
            for (int nf = 0; nf < 8; nf++) {
                const int n0 = bn + wn + nf*8 + 2*t;
                const float b0 = bias[n0], b1 = bias[n0 + 1];
                const float v0 = acc[mf][nf][0] + b0;
                const float v1 = acc[mf][nf][1] + b1;
                const float v2 = acc[mf][nf][2] + b0;
                const float v3 = acc[mf][nf][3] + b1;
                if (ok0) {
                    const size_t i0 = (size_t)r0 * Nn + n0;
                    C[i0]   += v0 * w0;
                    C[i0+1] += v1 * w0;
                }
                if (ok1) {
                    const size_t i1 = (size_t)r1 * Nn + n0;
                    C[i1]   += v2 * w1;
                    C[i1+1] += v3 * w1;
                }
            }
        } else {
            #pragma unroll
            for (int nf = 0; nf < 8; nf++) {
                const int n0 = bn + wn + nf*8 + 2*t;
                const float b0 = bias[n0], b1 = bias[n0 + 1];
                float v0 = acc[mf][nf][0] + b0;
                float v1 = acc[mf][nf][1] + b1;
                float v2 = acc[mf][nf][2] + b0;
                float v3 = acc[mf][nf][3] + b1;
                const size_t i0 = (size_t)mp0 * Nn + n0;
                const size_t i1 = (size_t)mp1 * Nn + n0;
                if (EPI == 0) {
                    C[i0] = v0; C[i0+1] = v1; C[i1] = v2; C[i1+1] = v3;
                } else if (EPI == 1) {
                    C[i0]   = 0.5f*v0*(1.0f + erff(v0*0.70710678118654752f));
                    C[i0+1] = 0.5f*v1*(1.0f + erff(v1*0.70710678118654752f));
                    C[i1]   = 0.5f*v2*(1.0f + erff(v2*0.70710678118654752f));
                    C[i1+1] = 0.5f*v3*(1.0f + erff(v3*0.70710678118654752f));
                } else {
                    C[i0] = v0 + resid[i0]; C[i0+1] = v1 + resid[i0+1];
                    C[i1] = v2 + resid[i1]; C[i1+1] = v3 + resid[i1+1];
                }
            }
        }
    }
}

// ---------------- Decomp1D ----------------
#define DC_NT 128
#define DC_DT 32
#define DC_HALO 24
__global__ void __launch_bounds__(256) decomp_kernel(
    const float* __restrict__ x, const float* __restrict__ alpha,
    const float* __restrict__ dw7, const float* __restrict__ dw25,
    const float* __restrict__ dw49)
{
    __shared__ float sx[DC_NT + 2*DC_HALO][DC_DT];
    __shared__ float sw7[DC_DT][7];
    __shared__ float sw25[DC_DT][25];
    __shared__ float sw49[DC_DT][49];
    const int b  = blockIdx.z;
    const int n0 = blockIdx.y * DC_NT;
    const int d0 = blockIdx.x * DC_DT;
    const int tid = threadIdx.x;

    for (int i = tid; i < DC_DT*7;  i += 256) sw7 [i/7 ][i%7 ] = dw7 [(d0 + i/7 )*7  + i%7 ];
    for (int i = tid; i < DC_DT*25; i += 256) sw25[i/25][i%25] = dw25[(d0 + i/25)*25 + i%25];
    for (int i = tid; i < DC_DT*49; i += 256) sw49[i/49][i%49] = dw49[(d0 + i/49)*49 + i%49];

    for (int i = tid; i < (DC_NT + 2*DC_HALO)*DC_DT; i += 256) {
        int r = i / DC_DT, c = i % DC_DT;
        int n = n0 + r - DC_HALO;
        if (n < 0)    n = -n;
        if (n >= SEQ) n = 2*SEQ - 2 - n;
        sx[r][c] = x[((size_t)b*SEQ + n)*D_MODEL + d0 + c];
    }
    __syncthreads();

    const float a0 = alpha[0], a1 = alpha[1], a2 = alpha[2];
    const float mx = fmaxf(a0, fmaxf(a1, a2));
    const float e0 = __expf(a0-mx), e1 = __expf(a1-mx), e2 = __expf(a2-mx);
    const float inv = 1.f/(e0+e1+e2);
    const float w0 = e0*inv, w1 = e1*inv, w2 = e2*inv;

    for (int i = tid; i < DC_NT*DC_DT; i += 256) {
        const int p = i / DC_DT, c = i % DC_DT;
        float t7 = 0.f, t25 = 0.f, t49 = 0.f;
        #pragma unroll
        for (int j = 0; j < 7;  j++) t7  = fmaf(sx[p + DC_HALO - 3  + j][c], sw7 [c][j], t7 );
        #pragma unroll
        for (int j = 0; j < 25; j++) t25 = fmaf(sx[p + DC_HALO - 12 + j][c], sw25[c][j], t25);
        #pragma unroll
        for (int j = 0; j < 49; j++) t49 = fmaf(sx[p + j][c],                sw49[c][j], t49);
        const float tr = w0*t7 + w1*t25 + w2*t49;
        const size_t idx = ((size_t)b*SEQ + n0 + p)*D_MODEL + d0 + c;
        g_Tr[idx] = tr;
        g_S[idx]  = sx[p + DC_HALO][c] - tr;
    }
}

// ---------------- LayerNorm ----------------
__global__ void __launch_bounds__(256) ln_kernel(
    const float* __restrict__ in, const float* __restrict__ gam,
    const float* __restrict__ bet, float* __restrict__ out)
{
    __shared__ float row[D_MODEL];
    __shared__ float red[256];
    const int t = blockIdx.x, tid = threadIdx.x;
    const float* ip = in + (size_t)t*D_MODEL;
    float s = 0.f;
    for (int d = tid; d < D_MODEL; d += 256) { float v = ip[d]; row[d] = v; s += v; }
    red[tid] = s; __syncthreads();
    for (int o = 128; o > 0; o >>= 1) { if (tid < o) red[tid] += red[tid+o]; __syncthreads(); }
    const float mean = red[0] * (1.f/D_MODEL);
    __syncthreads();
    float vs = 0.f;
    for (int d = tid; d < D_MODEL; d += 256) { float dv = row[d]-mean; vs += dv*dv; }
    red[tid] = vs; __syncthreads();
    for (int o = 128; o > 0; o >>= 1) { if (tid < o) red[tid] += red[tid+o]; __syncthreads(); }
    const float rstd = rsqrtf(red[0] * (1.f/D_MODEL) + LN_EPS);
    for (int d = tid; d < D_MODEL; d += 256)
        out[(size_t)t*D_MODEL + d] = (row[d]-mean)*rstd*gam[d] + bet[d];
}

// ---------------- ALiBi attention ----------------
__global__ void __launch_bounds__(64) attn_kernel()
{
    __shared__ float Ks[64][64];
    __shared__ float Vs[64][64];
    const int bh = blockIdx.x;
    const int b = bh / NHEAD, h = bh % NHEAD;
    const int q0 = blockIdx.y * 64;
    const int tid = threadIdx.x;
    const int qg = q0 + tid;

    float q[64], o[64];
    const float* qp = g_q + ((size_t)(b*SEQ + qg))*D_MODEL + h*HEAD_DIM;
    #pragma unroll
    for (int d = 0; d < 64; d++) { q[d] = qp[d]*0.125f; o[d] = 0.f; }
    float l = 0.f;
    const float slope = exp2f(-0.5f*(float)(h+1));

    for (int k0 = 0; k0 < SEQ; k0 += 64) {
        const float* kp = g_k + ((size_t)(b*SEQ + k0))*D_MODEL + h*HEAD_DIM;
        const float* vp = g_v + ((size_t)(b*SEQ + k0))*D_MODEL + h*HEAD_DIM;
        __syncthreads();
        for (int r = 0; r < 64; r++) {
            Ks[r][tid] = kp[(size_t)r*D_MODEL + tid];
            Vs[r][tid] = vp[(size_t)r*D_MODEL + tid];
        }
        __syncthreads();
        #pragma unroll 4
        for (int j = 0; j < 64; j++) {
            float s = 0.f;
            #pragma unroll
            for (int d = 0; d < 64; d++) s = fmaf(q[d], Ks[j][d], s);
            const int dist = k0 + j - qg;
            if (dist > 0) s -= slope * (float)dist;
            const float p = __expf(s);
            l += p;
            #pragma unroll
            for (int d = 0; d < 64; d++) o[d] = fmaf(p, Vs[j][d], o[d]);
        }
    }
    const float invl = 1.f/l;
    float* yp = g_y + ((size_t)(b*SEQ + qg))*D_MODEL + h*HEAD_DIM;
    #pragma unroll
    for (int d = 0; d < 64; d++) yp[d] = o[d]*invl;
}

// ---------------- Router ----------------
__global__ void __launch_bounds__(256) router_kernel(
    const float* __restrict__ xf, const float* __restrict__ rw)
{
    const int warp = threadIdx.x / 32, lane = threadIdx.x % 32;
    const int t = blockIdx.x*8 + warp;
    const float* xp = xf + (size_t)t*D_MODEL;
    float logit[NUM_EXPERTS];
    #pragma unroll
    for (int e = 0; e < NUM_EXPERTS; e++) {
        float p = 0.f;
        for (int d = lane; d < D_MODEL; d += 32) p = fmaf(xp[d], rw[e*D_MODEL + d], p);
        #pragma unroll
        for (int o = 16; o > 0; o >>= 1) p += __shfl_xor_sync(0xffffffffu, p, o);
        logit[e] = p;
    }
    if (lane == 0) {
        float mx = logit[0];
        #pragma unroll
        for (int e = 1; e < NUM_EXPERTS; e++) mx = fmaxf(mx, logit[e]);
        float g[NUM_EXPERTS]; float s = 0.f;
        #pragma unroll
        for (int e = 0; e < NUM_EXPERTS; e++) { g[e] = expf(logit[e]-mx); s += g[e]; }
        #pragma unroll
        for (int e = 0; e < NUM_EXPERTS; e++) g[e] /= s;
        int i0 = 0;
        #pragma unroll
        for (int e = 1; e < NUM_EXPERTS; e++) if (g[e] > g[i0]) i0 = e;
        int i1 = -1;
        #pragma unroll
        for (int e = 0; e < NUM_EXPERTS; e++)
            if (e != i0 && (i1 < 0 || g[e] > g[i1])) i1 = e;
        const float s2 = fmaxf(g[i0] + g[i1], 1e-9f);
        float w[NUM_EXPERTS] = {0.f, 0.f, 0.f, 0.f};
        w[i0] = g[i0]/s2; w[i1] = g[i1]/s2;
        #pragma unroll
        for (int e = 0; e < NUM_EXPERTS; e++) {
            g_gates[t*NUM_EXPERTS + e] = g[e];
            g_w[t*NUM_EXPERTS + e]     = w[e];
        }
    }
}

// ---------------- routing lists (deterministic stable partition) ----------------
__global__ void __launch_bounds__(128) route_kernel()
{
    const int e = threadIdx.x >> 5, lane = threadIdx.x & 31;
    int cnt = 0;
    for (int base = 0; base < TOKENS; base += 32) {
        const int t = base + lane;
        const bool sel = g_w[t*NUM_EXPERTS + e] > 0.f;
        const unsigned m = __ballot_sync(0xffffffffu, sel);
        if (sel) g_elist[e*TOKENS + cnt + __popc(m & ((1u << lane) - 1u))] = t;
        cnt += __popc(m);
    }
    __syncwarp();
    const int padded = (cnt + 127) & ~127;
    if (cnt > 0) {
        const int last = g_elist[e*TOKENS + cnt - 1];
        for (int i = cnt + lane; i < padded; i += 32) g_elist[e*TOKENS + i] = last;
    }
    if (lane == 0) g_ecnt[e] = cnt;
}

// ---------------- aux ----------------
__global__ void __launch_bounds__(256) aux_kernel(float* __restrict__ out, int out_size)
{
    __shared__ float rg[NUM_EXPERTS][256];
    __shared__ float rc[NUM_EXPERTS][256];
    const int tid = threadIdx.x;
    float gs[NUM_EXPERTS] = {0,0,0,0}, cs[NUM_EXPERTS] = {0,0,0,0};
    for (int t = tid; t < TOKENS; t += 256) {
        #pragma unroll
        for (int e = 0; e < NUM_EXPERTS; e++) {
            gs[e] += g_gates[t*NUM_EXPERTS + e];
            cs[e] += (g_w[t*NUM_EXPERTS + e] > 0.f) ? 1.f : 0.f;
        }
    }
    #pragma unroll
    for (int e = 0; e < NUM_EXPERTS; e++) { rg[e][tid] = gs[e]; rc[e][tid] = cs[e]; }
    __syncthreads();
    for (int o = 128; o > 0; o >>= 1) {
        if (tid < o)
            #pragma unroll
            for (int e = 0; e < NUM_EXPERTS; e++) { rg[e][tid] += rg[e][tid+o]; rc[e][tid] += rc[e][tid+o]; }
        __syncthreads();
    }
    if (tid == 0 && out_size > BND) {
        float aux = 0.f;
        #pragma unroll
        for (int e = 0; e < NUM_EXPERTS; e++)
            aux += (rg[e][0]*(1.f/TOKENS)) * (rc[e][0]*(1.f/TOKENS));
        out[out_size - 1] = (float)NUM_EXPERTS * aux;
    }
}

// ---------------- final ----------------
__global__ void __launch_bounds__(256) final_kernel(
    const float* __restrict__ tw, const float* __restrict__ tb, float* __restrict__ out)
{
    const size_t gid = (size_t)blockIdx.x*256 + threadIdx.x;
    if (gid >= (size_t)BND) return;
    const int d = (int)(gid % D_MODEL);
    const int n = (int)((gid / D_MODEL) % SEQ);
    float t = 0.f;
    #pragma unroll
    for (int j = 0; j < 5; j++) {
        const int nn = n - 2 + j;
        if (nn >= 0 && nn < SEQ)
            t = fmaf(g_Tr[gid + (size_t)(j-2)*D_MODEL], tw[d*5 + j], t);
    }
    out[gid] = g_xs[gid] + t + tb[d];
}

// ---------------- launch ----------------
static float* sym_addr(const void* sym) {
    void* p = nullptr;
    cudaGetSymbolAddress(&p, sym);
    return (float*)p;
}

extern "C" void kernel_launch(void* const* d_in, const int* in_sizes, int n_in,
                              void* d_out, int out_size)
{
    const float* x    = (const float*)d_in[0];
    const float* qw   = (const float*)d_in[1];  const float* qb  = (const float*)d_in[2];
    const float* kw   = (const float*)d_in[3];  const float* kb  = (const float*)d_in[4];
    const float* vw   = (const float*)d_in[5];  const float* vb  = (const float*)d_in[6];
    const float* ow   = (const float*)d_in[7];  const float* ob  = (const float*)d_in[8];
    const float* n1g  = (const float*)d_in[9];  const float* n1b = (const float*)d_in[10];
    const float* n2g  = (const float*)d_in[11]; const float* n2b = (const float*)d_in[12];
    const float* alpha= (const float*)d_in[13];
    const float* dw7  = (const float*)d_in[14];
    const float* dw25 = (const float*)d_in[15];
    const float* dw49 = (const float*)d_in[16];
    const float* rw   = (const float*)d_in[17];
    const float* ew1  = (const float*)d_in[18]; const float* eb1 = (const float*)d_in[19];
    const float* ew2  = (const float*)d_in[20]; const float* eb2 = (const float*)d_in[21];
    const float* tw   = (const float*)d_in[22]; const float* tb  = (const float*)d_in[23];
    float* out = (float*)d_out;

    float* pS   = sym_addr(g_S);
    float* pBuf = sym_addr(g_buf);
    float* pQ   = sym_addr(g_q);
    float* pK   = sym_addr(g_k);
    float* pV   = sym_addr(g_v);
    float* pY   = sym_addr(g_y);
    float* pXs  = sym_addr(g_xs);
    float* pH   = sym_addr(g_h);
    float* pW   = sym_addr(g_w);
    int*   pEL  = (int*)sym_addr(g_elist);
    int*   pEC  = (int*)sym_addr(g_ecnt);
    (void)in_sizes; (void)n_in;

    // 1) decomposition -> g_Tr, g_S
    dim3 dgrid(D_MODEL/DC_DT, SEQ/DC_NT, BATCH);
    decomp_kernel<<<dgrid, 256>>>(x, alpha, dw7, dw25, dw49);

    // 2) LN1(S) -> Sn
    ln_kernel<<<TOKENS, 256>>>(pS, n1g, n1b, pBuf);

    // 3) Q,K,V projections (tf32 mma.sync)
    dim3 gqkv(D_MODEL/128, TOKENS/128);
    tc_gemm<0><<<gqkv, 128, TCG_SMEM>>>(pBuf, qw, qb, pQ, D_MODEL, D_MODEL,
                                        nullptr, nullptr, 0, nullptr, nullptr, nullptr);
    tc_gemm<0><<<gqkv, 128, TCG_SMEM>>>(pBuf, kw, kb, pK, D_MODEL, D_MODEL,
                                        nullptr, nullptr, 0, nullptr, nullptr, nullptr);
    tc_gemm<0><<<gqkv, 128, TCG_SMEM>>>(pBuf, vw, vb, pV, D_MODEL, D_MODEL,
                                        nullptr, nullptr, 0, nullptr, nullptr, nullptr);

    // 4) attention
    dim3 agrid(BATCH*NHEAD, SEQ/64);
    attn_kernel<<<agrid, 64>>>();

    // 5) O projection + residual S -> g_xs
    tc_gemm<2><<<gqkv, 128, TCG_SMEM>>>(pY, ow, ob, pXs, D_MODEL, D_MODEL,
                                        pS, nullptr, 0, nullptr, nullptr, nullptr);

    // 6) LN2 -> xf
    ln_kernel<<<TOKENS, 256>>>(pXs, n2g, n2b, pBuf);

    // 7) router + routing lists + aux
    router_kernel<<<TOKENS/8, 256>>>(pBuf, rw);
    route_kernel<<<1, 128>>>();
    aux_kernel<<<1, 256>>>(out, out_size);

    // 8) MoE FFN: routed top-2 (exact-equivalent to dense)
    dim3 gh1(MOE_HIDDEN/128, TOKENS/128);
    dim3 gh2(D_MODEL/128,    TOKENS/128);
    for (int e = 0; e < NUM_EXPERTS; e++) {
        tc_gemm<1><<<gh1, 128, TCG_SMEM>>>(pBuf, ew1 + (size_t)e*MOE_HIDDEN*D_MODEL,
                                           eb1 + (size_t)e*MOE_HIDDEN, pH,
                                           D_MODEL, MOE_HIDDEN,
                                           nullptr, nullptr, 0,
                                           pEL + e*TOKENS, nullptr, pEC + e);
        tc_gemm<3><<<gh2, 128, TCG_SMEM>>>(pH, ew2 + (size_t)e*D_MODEL*MOE_HIDDEN,
                                           eb2 + (size_t)e*D_MODEL, pXs,
                                           MOE_HIDDEN, D_MODEL,
                                           nullptr, pW, e,
                                           nullptr, pEL + e*TOKENS, pEC + e);
    }

    // 9) final
    final_kernel<<<(BND + 255)/256, 256>>>(tw, tb, out);
}

// round 8
// speedup vs baseline: 1.4385x; 1.4385x over previous
#include <cuda_runtime.h>
#include <math.h>
#include <stdint.h>

#define D_MODEL 1024
#define NHEAD 16
#define HEAD_DIM 64
#define MOE_HIDDEN 2048
#define NUM_EXPERTS 4
#define BATCH 8
#define SEQ 1024
#define TOKENS (BATCH*SEQ)          /* 8192  */
#define BND (TOKENS*D_MODEL)        /* 8388608 */
#define LN_EPS 1e-5f

// ---------------- scratch (device globals; no allocation) ----------------
__device__ float g_Tr[BND];
__device__ float g_S[BND];
__device__ float g_buf[BND];
__device__ float g_q[BND];
__device__ float g_k[BND];
__device__ float g_v[BND];
__device__ float g_y[BND];
__device__ float g_xs[BND];
__device__ float g_h[TOKENS*MOE_HIDDEN];
__device__ float g_w[TOKENS*NUM_EXPERTS];
__device__ float g_gates[TOKENS*NUM_EXPERTS];
__device__ int   g_elist[NUM_EXPERTS*TOKENS];   // per-expert token lists (padded)
__device__ int   g_ecnt[NUM_EXPERTS];

// ============================================================
// tf32 helpers (sm_80+ PTX, no 'a'-suffix gating)
// ============================================================
__device__ __forceinline__ uint32_t f2tf32(float f) {
    uint32_t u; asm("cvt.rna.tf32.f32 %0, %1;" : "=r"(u) : "f"(f)); return u;
}
__device__ __forceinline__ void mma_tf32(float* c, const uint32_t* a, const uint32_t* b) {
    asm volatile(
        "mma.sync.aligned.m16n8k8.row.col.f32.tf32.tf32.f32 "
        "{%0,%1,%2,%3}, {%4,%5,%6,%7}, {%8,%9}, {%0,%1,%2,%3};"
        : "+f"(c[0]), "+f"(c[1]), "+f"(c[2]), "+f"(c[3])
        : "r"(a[0]), "r"(a[1]), "r"(a[2]), "r"(a[3]), "r"(b[0]), "r"(b[1]));
}

// ============================================================
// tf32 mma.sync GEMM (R5 config): C[m,n] = sum_k A[m,k]*B[n,k]
// CTA tile 128x128, BK=16, 256 thr (8 warps 2x4, warp tile 64x32),
// double-buffered smem [128][20], register-prefetch, 1 sync/K-iter,
// 2 CTAs/SM (regs capped at 128).
// EPI: 0 plain, 1 GELU, 2 +resid, 3 scatter C[row] += v*w[row,e]
// ============================================================
#define TCG_LDA 20
#define TCG_BUF (128*TCG_LDA)
#define TCG_SMEM (4*TCG_BUF*4)   /* 40960 B */

template<int EPI>
__global__ void __launch_bounds__(256, 2) tc_gemm(
    const float* __restrict__ A, const float* __restrict__ B,
    const float* __restrict__ bias, float* __restrict__ C,
    int K, int Nn,
    const float* __restrict__ resid, const float* __restrict__ wts, int expert,
    const int* __restrict__ aidx, const int* __restrict__ cidx,
    const int* __restrict__ cntp)
{
    extern __shared__ uint32_t smu[];
    const int tid = threadIdx.x;
    const int bm = blockIdx.y * 128, bn = blockIdx.x * 128;
    int cnt = 0x7fffffff;
    if (cntp) { cnt = *cntp; if (bm >= ((cnt + 127) & ~127)) return; }

    uint32_t* As = smu;                 // [2][128*20]
    uint32_t* Bs = smu + 2*TCG_BUF;
    const int warp = tid >> 5, lane = tid & 31;
    const int wm = (warp >> 2) * 64, wn = (warp & 3) * 32;
    const int g = lane >> 2, t = lane & 3;

    const int lr = tid >> 2, lc = tid & 3;   // staging: row(0..63), float4-col(0..3)
    int ra0 = bm + lr, ra1 = bm + lr + 64;
    if (aidx) { ra0 = aidx[ra0]; ra1 = aidx[ra1]; }
    const float* Ag0 = A + (size_t)ra0 * K + lc * 4;
    const float* Ag1 = A + (size_t)ra1 * K + lc * 4;
    const float* Bg0 = B + (size_t)(bn + lr) * K + lc * 4;
    const float* Bg1 = B + (size_t)(bn + lr + 64) * K + lc * 4;

    float acc[4][4][4];
    #pragma unroll
    for (int i = 0; i < 4; i++)
        #pragma unroll
        for (int j = 0; j < 4; j++)
            #pragma unroll
            for (int r = 0; r < 4; r++) acc[i][j][r] = 0.f;

    const int NT = K >> 4;
    float4 pa0 = *(const float4*)Ag0, pa1 = *(const float4*)Ag1;
    float4 pb0 = *(const float4*)Bg0, pb1 = *(const float4*)Bg1;
    {
        uint4 u0 = { f2tf32(pa0.x), f2tf32(pa0.y), f2tf32(pa0.z), f2tf32(pa0.w) };
        uint4 u1 = { f2tf32(pa1.x), f2tf32(pa1.y), f2tf32(pa1.z), f2tf32(pa1.w) };
        uint4 w0 = { f2tf32(pb0.x), f2tf32(pb0.y), f2tf32(pb0.z), f2tf32(pb0.w) };
        uint4 w1 = { f2tf32(pb1.x), f2tf32(pb1.y), f2tf32(pb1.z), f2tf32(pb1.w) };
        *(uint4*)&As[lr*TCG_LDA + lc*4]        = u0;
        *(uint4*)&As[(lr+64)*TCG_LDA + lc*4]   = u1;
        *(uint4*)&Bs[lr*TCG_LDA + lc*4]        = w0;
        *(uint4*)&Bs[(lr+64)*TCG_LDA + lc*4]   = w1;
    }
    __syncthreads();

    for (int kt = 0; kt < NT; kt++) {
        const uint32_t* Ab = As + (kt & 1)*TCG_BUF;
        const uint32_t* Bb = Bs + (kt & 1)*TCG_BUF;
        if (kt + 1 < NT) {
            const int ko = (kt + 1) * 16;
            pa0 = *(const float4*)(Ag0 + ko); pa1 = *(const float4*)(Ag1 + ko);
            pb0 = *(const float4*)(Bg0 + ko); pb1 = *(const float4*)(Bg1 + ko);
        }
        #pragma unroll
        for (int ks = 0; ks < 2; ks++) {
            const int kb = ks * 8;
            uint32_t af[4][4], bf[4][2];
            #pragma unroll
            for (int mf = 0; mf < 4; mf++) {
                const uint32_t* base = Ab + (wm + mf*16 + g)*TCG_LDA + kb + t;
                af[mf][0] = base[0];
                af[mf][1] = base[8*TCG_LDA];
                af[mf][2] = base[4];
                af[mf][3] = base[8*TCG_LDA + 4];
            }
            #pragma unroll
            for (int nf = 0; nf < 4; nf++) {
                const uint32_t* base = Bb + (wn + nf*8 + g)*TCG_LDA + kb + t;
                bf[nf][0] = base[0];
                bf[nf][1] = base[4];
            }
            #pragma unroll
            for (int mf = 0; mf < 4; mf++)
                #pragma unroll
                for (int nf = 0; nf < 4; nf++)
                    mma_tf32(acc[mf][nf], af[mf], bf[nf]);
        }
        if (kt + 1 < NT) {
            uint32_t* Ad = As + ((kt+1) & 1)*TCG_BUF;
            uint32_t* Bd = Bs + ((kt+1) & 1)*TCG_BUF;
            uint4 u0 = { f2tf32(pa0.x), f2tf32(pa0.y), f2tf32(pa0.z), f2tf32(pa0.w) };
            uint4 u1 = { f2tf32(pa1.x), f2tf32(pa1.y), f2tf32(pa1.z), f2tf32(pa1.w) };
            uint4 w0 = { f2tf32(pb0.x), f2tf32(pb0.y), f2tf32(pb0.z), f2tf32(pb0.w) };
            uint4 w1 = { f2tf32(pb1.x), f2tf32(pb1.y), f2tf32(pb1.z), f2tf32(pb1.w) };
            *(uint4*)&Ad[lr*TCG_LDA + lc*4]      = u0;
            *(uint4*)&Ad[(lr+64)*TCG_LDA + lc*4] = u1;
            *(uint4*)&Bd[lr*TCG_LDA + lc*4]      = w0;
            *(uint4*)&Bd[(lr+64)*TCG_LDA + lc*4] = w1;
            __syncthreads();
        }
    }

    // ---- epilogue ----
    #pragma unroll
    for (int mf = 0; mf < 4; mf++) {
        const int mp0 = bm + wm + mf*16 + g;
        const int mp1 = mp0 + 8;
        if (EPI == 3) {
            const int r0 = cidx[mp0], r1 = cidx[mp1];
            const float w0 = wts[r0*NUM_EXPERTS + expert];
            const float w1 = wts[r1*NUM_EXPERTS + expert];
            const bool ok0 = mp0 < cnt, ok1 = mp1 < cnt;
            #pragma unroll
            for (int nf = 0; nf < 4; nf++) {
                const int n0 = bn + wn + nf*8 + 2*t;
                const float b0 = bias[n0], b1 = bias[n0 + 1];
                const float v0 = acc[mf][nf][0] + b0;
                const float v1 = acc[mf][nf][1] + b1;
                const float v2 = acc[mf][nf][2] + b0;
                const float v3 = acc[mf][nf][3] + b1;
                if (ok0) {
                    const size_t i0 = (size_t)r0 * Nn + n0;
                    C[i0]   += v0 * w0;
                    C[i0+1] += v1 * w0;
                }
                if (ok1) {
                    const size_t i1 = (size_t)r1 * Nn + n0;
                    C[i1]   += v2 * w1;
                    C[i1+1] += v3 * w1;
                }
            }
        } else {
            #pragma unroll
            for (int nf = 0; nf < 4; nf++) {
                const int n0 = bn + wn + nf*8 + 2*t;
                const float b0 = bias[n0], b1 = bias[n0 + 1];
                float v0 = acc[mf][nf][0] + b0;
                float v1 = acc[mf][nf][1] + b1;
                float v2 = acc[mf][nf][2] + b0;
                float v3 = acc[mf][nf][3] + b1;
                const size_t i0 = (size_t)mp0 * Nn + n0;
                const size_t i1 = (size_t)mp1 * Nn + n0;
                if (EPI == 0) {
                    C[i0] = v0; C[i0+1] = v1; C[i1] = v2; C[i1+1] = v3;
                } else if (EPI == 1) {
                    C[i0]   = 0.5f*v0*(1.0f + erff(v0*0.70710678118654752f));
                    C[i0+1] = 0.5f*v1*(1.0f + erff(v1*0.70710678118654752f));
                    C[i1]   = 0.5f*v2*(1.0f + erff(v2*0.70710678118654752f));
                    C[i1+1] = 0.5f*v3*(1.0f + erff(v3*0.70710678118654752f));
                } else {
                    C[i0] = v0 + resid[i0]; C[i0+1] = v1 + resid[i0+1];
                    C[i1] = v2 + resid[i1]; C[i1+1] = v3 + resid[i1+1];
                }
            }
        }
    }
}

// ============================================================
// Tensor-core ALiBi flash attention (tf32 mma.sync)
// grid (B*H, SEQ/64), 128 thr (4 warps, warp = 16 q-rows).
// Ks [64][68] (stride==4 mod 32 -> conflict-free frags),
// Vt [64][69] transposed V, Ps [64][68] P round-trip (per-warp rows).
// Unnormalized exp accumulation (logits bounded; validated in fp32 R2).
// ============================================================
#define ATT_LDK 68
#define ATT_LDV 69
#define ATT_SMEM ((64*ATT_LDK + 64*ATT_LDV + 64*ATT_LDK)*4)   /* 52480 B */

__global__ void __launch_bounds__(128, 3) attn_tc_kernel()
{
    extern __shared__ uint32_t smA[];
    uint32_t* Ks = smA;
    uint32_t* Vt = smA + 64*ATT_LDK;
    uint32_t* Ps = smA + 64*ATT_LDK + 64*ATT_LDV;
    const int tid = threadIdx.x;
    const int warp = tid >> 5, lane = tid & 31;
    const int g = lane >> 2, t = lane & 3;
    const int bh = blockIdx.x;
    const int b = bh >> 4, h = bh & 15;
    const int q0 = blockIdx.y * 64;
    const float slope = exp2f(-0.5f*(float)(h + 1));

    // stage Q (scaled by 1/8, tf32) into Ps, then per-warp fragment load
    for (int i = tid; i < 1024; i += 128) {
        const int row = i >> 4, c4 = (i & 15) * 4;
        const float4 qv = *(const float4*)(g_q + ((size_t)(b*SEQ + q0 + row))*D_MODEL + h*64 + c4);
        uint32_t* d = Ps + row*ATT_LDK + c4;
        d[0] = f2tf32(qv.x*0.125f); d[1] = f2tf32(qv.y*0.125f);
        d[2] = f2tf32(qv.z*0.125f); d[3] = f2tf32(qv.w*0.125f);
    }
    __syncthreads();
    uint32_t qf[8][4];
    #pragma unroll
    for (int k = 0; k < 8; k++) {
        const uint32_t* base = Ps + (warp*16 + g)*ATT_LDK + k*8 + t;
        qf[k][0] = base[0]; qf[k][1] = base[8*ATT_LDK];
        qf[k][2] = base[4]; qf[k][3] = base[8*ATT_LDK + 4];
    }

    float o[8][4];
    #pragma unroll
    for (int nf = 0; nf < 8; nf++)
        #pragma unroll
        for (int r = 0; r < 4; r++) o[nf][r] = 0.f;
    float l0 = 0.f, l1 = 0.f;
    const int qg0 = q0 + warp*16 + g, qg1 = qg0 + 8;

    for (int kt = 0; kt < 16; kt++) {
        __syncthreads();   // prev PV done before Ks/Vt overwrite (also covers Q-frag loads at kt=0)
        for (int i = tid; i < 1024; i += 128) {
            const int row = i >> 4, c4 = (i & 15) * 4;
            const size_t gofs = ((size_t)(b*SEQ + kt*64 + row))*D_MODEL + h*64 + c4;
            const float4 kv = *(const float4*)(g_k + gofs);
            uint32_t* dk = Ks + row*ATT_LDK + c4;
            dk[0] = f2tf32(kv.x); dk[1] = f2tf32(kv.y);
            dk[2] = f2tf32(kv.z); dk[3] = f2tf32(kv.w);
            const float4 vv = *(const float4*)(g_v + gofs);
            Vt[(c4+0)*ATT_LDV + row] = f2tf32(vv.x);
            Vt[(c4+1)*ATT_LDV + row] = f2tf32(vv.y);
            Vt[(c4+2)*ATT_LDV + row] = f2tf32(vv.z);
            Vt[(c4+3)*ATT_LDV + row] = f2tf32(vv.w);
        }
        __syncthreads();

        // S = Q K^T  (warp's 16 q-rows x 64 j)
        float s[8][4];
        #pragma unroll
        for (int nf = 0; nf < 8; nf++)
            #pragma unroll
            for (int r = 0; r < 4; r++) s[nf][r] = 0.f;
        #pragma unroll
        for (int k = 0; k < 8; k++) {
            uint32_t bf[8][2];
            #pragma unroll
            for (int nf = 0; nf < 8; nf++) {
                const uint32_t* base = Ks + (nf*8 + g)*ATT_LDK + k*8 + t;
                bf[nf][0] = base[0]; bf[nf][1] = base[4];
            }
            #pragma unroll
            for (int nf = 0; nf < 8; nf++) mma_tf32(s[nf], qf[k], bf[nf]);
        }

        // ALiBi + exp + row-sum + P -> smem (own warp rows only)
        #pragma unroll
        for (int nf = 0; nf < 8; nf++) {
            const int jg = kt*64 + nf*8 + 2*t;
            const int d00 = jg - qg0, d10 = jg - qg1;
            const float p00 = __expf(s[nf][0] - slope*(float)(d00   > 0 ? d00   : 0));
            const float p01 = __expf(s[nf][1] - slope*(float)(d00+1 > 0 ? d00+1 : 0));
            const float p10 = __expf(s[nf][2] - slope*(float)(d10   > 0 ? d10   : 0));
            const float p11 = __expf(s[nf][3] - slope*(float)(d10+1 > 0 ? d10+1 : 0));
            l0 += p00 + p01; l1 += p10 + p11;
            uint32_t* pr0 = Ps + (warp*16 + g)*ATT_LDK + nf*8 + 2*t;
            pr0[0] = f2tf32(p00); pr0[1] = f2tf32(p01);
            pr0[8*ATT_LDK] = f2tf32(p10); pr0[8*ATT_LDK + 1] = f2tf32(p11);
        }
        __syncwarp();

        // O += P V   (contract over j)
        #pragma unroll
        for (int k = 0; k < 8; k++) {
            uint32_t pf[4];
            const uint32_t* pb = Ps + (warp*16 + g)*ATT_LDK + k*8 + t;
            pf[0] = pb[0]; pf[1] = pb[8*ATT_LDK];
            pf[2] = pb[4]; pf[3] = pb[8*ATT_LDK + 4];
            #pragma unroll
            for (int nf = 0; nf < 8; nf++) {
                const uint32_t* vb = Vt + (nf*8 + g)*ATT_LDV + k*8 + t;
                uint32_t bf[2] = { vb[0], vb[4] };
                mma_tf32(o[nf], pf, bf);
            }
        }
    }

    l0 += __shfl_xor_sync(0xffffffffu, l0, 1);
    l0 += __shfl_xor_sync(0xffffffffu, l0, 2);
    l1 += __shfl_xor_sync(0xffffffffu, l1, 1);
    l1 += __shfl_xor_sync(0xffffffffu, l1, 2);
    const float inv0 = 1.f/l0, inv1 = 1.f/l1;
    float* y0 = g_y + ((size_t)(b*SEQ + qg0))*D_MODEL + h*64;
    float* y1 = g_y + ((size_t)(b*SEQ + qg1))*D_MODEL + h*64;
    #pragma unroll
    for (int nf = 0; nf < 8; nf++) {
        const int c = nf*8 + 2*t;
        y0[c]   = o[nf][0]*inv0;
        y0[c+1] = o[nf][1]*inv0;
        y1[c]   = o[nf][2]*inv1;
        y1[c+1] = o[nf][3]*inv1;
    }
}

// ---------------- Decomp1D ----------------
#define DC_NT 128
#define DC_DT 32
#define DC_HALO 24
__global__ void __launch_bounds__(256) decomp_kernel(
    const float* __restrict__ x, const float* __restrict__ alpha,
    const float* __restrict__ dw7, const float* __restrict__ dw25,
    const float* __restrict__ dw49)
{
    __shared__ float sx[DC_NT + 2*DC_HALO][DC_DT];
    __shared__ float sw7[DC_DT][7];
    __shared__ float sw25[DC_DT][25];
    __shared__ float sw49[DC_DT][49];
    const int b  = blockIdx.z;
    const int n0 = blockIdx.y * DC_NT;
    const int d0 = blockIdx.x * DC_DT;
    const int tid = threadIdx.x;

    for (int i = tid; i < DC_DT*7;  i += 256) sw7 [i/7 ][i%7 ] = dw7 [(d0 + i/7 )*7  + i%7 ];
    for (int i = tid; i < DC_DT*25; i += 256) sw25[i/25][i%25] = dw25[(d0 + i/25)*25 + i%25];
    for (int i = tid; i < DC_DT*49; i += 256) sw49[i/49][i%49] = dw49[(d0 + i/49)*49 + i%49];

    for (int i = tid; i < (DC_NT + 2*DC_HALO)*DC_DT; i += 256) {
        int r = i / DC_DT, c = i % DC_DT;
        int n = n0 + r - DC_HALO;
        if (n < 0)    n = -n;
        if (n >= SEQ) n = 2*SEQ - 2 - n;
        sx[r][c] = x[((size_t)b*SEQ + n)*D_MODEL + d0 + c];
    }
    __syncthreads();

    const float a0 = alpha[0], a1 = alpha[1], a2 = alpha[2];
    const float mx = fmaxf(a0, fmaxf(a1, a2));
    const float e0 = __expf(a0-mx), e1 = __expf(a1-mx), e2 = __expf(a2-mx);
    const float inv = 1.f/(e0+e1+e2);
    const float w0 = e0*inv, w1 = e1*inv, w2 = e2*inv;

    for (int i = tid; i < DC_NT*DC_DT; i += 256) {
        const int p = i / DC_DT, c = i % DC_DT;
        float t7 = 0.f, t25 = 0.f, t49 = 0.f;
        #pragma unroll
        for (int j = 0; j < 7;  j++) t7  = fmaf(sx[p + DC_HALO - 3  + j][c], sw7 [c][j], t7 );
        #pragma unroll
        for (int j = 0; j < 25; j++) t25 = fmaf(sx[p + DC_HALO - 12 + j][c], sw25[c][j], t25);
        #pragma unroll
        for (int j = 0; j < 49; j++) t49 = fmaf(sx[p + j][c],                sw49[c][j], t49);
        const float tr = w0*t7 + w1*t25 + w2*t49;
        const size_t idx = ((size_t)b*SEQ + n0 + p)*D_MODEL + d0 + c;
        g_Tr[idx] = tr;
        g_S[idx]  = sx[p + DC_HALO][c] - tr;
    }
}

// ---------------- LayerNorm ----------------
__global__ void __launch_bounds__(256) ln_kernel(
    const float* __restrict__ in, const float* __restrict__ gam,
    const float* __restrict__ bet, float* __restrict__ out)
{
    __shared__ float row[D_MODEL];
    __shared__ float red[256];
    const int t = blockIdx.x, tid = threadIdx.x;
    const float* ip = in + (size_t)t*D_MODEL;
    float s = 0.f;
    for (int d = tid; d < D_MODEL; d += 256) { float v = ip[d]; row[d] = v; s += v; }
    red[tid] = s; __syncthreads();
    for (int o = 128; o > 0; o >>= 1) { if (tid < o) red[tid] += red[tid+o]; __syncthreads(); }
    const float mean = red[0] * (1.f/D_MODEL);
    __syncthreads();
    float vs = 0.f;
    for (int d = tid; d < D_MODEL; d += 256) { float dv = row[d]-mean; vs += dv*dv; }
    red[tid] = vs; __syncthreads();
    for (int o = 128; o > 0; o >>= 1) { if (tid < o) red[tid] += red[tid+o]; __syncthreads(); }
    const float rstd = rsqrtf(red[0] * (1.f/D_MODEL) + LN_EPS);
    for (int d = tid; d < D_MODEL; d += 256)
        out[(size_t)t*D_MODEL + d] = (row[d]-mean)*rstd*gam[d] + bet[d];
}

// ---------------- Router ----------------
__global__ void __launch_bounds__(256) router_kernel(
    const float* __restrict__ xf, const float* __restrict__ rw)
{
    const int warp = threadIdx.x / 32, lane = threadIdx.x % 32;
    const int t = blockIdx.x*8 + warp;
    const float* xp = xf + (size_t)t*D_MODEL;
    float logit[NUM_EXPERTS];
    #pragma unroll
    for (int e = 0; e < NUM_EXPERTS; e++) {
        float p = 0.f;
        for (int d = lane; d < D_MODEL; d += 32) p = fmaf(xp[d], rw[e*D_MODEL + d], p);
        #pragma unroll
        for (int o = 16; o > 0; o >>= 1) p += __shfl_xor_sync(0xffffffffu, p, o);
        logit[e] = p;
    }
    if (lane == 0) {
        float mx = logit[0];
        #pragma unroll
        for (int e = 1; e < NUM_EXPERTS; e++) mx = fmaxf(mx, logit[e]);
        float g[NUM_EXPERTS]; float s = 0.f;
        #pragma unroll
        for (int e = 0; e < NUM_EXPERTS; e++) { g[e] = expf(logit[e]-mx); s += g[e]; }
        #pragma unroll
        for (int e = 0; e < NUM_EXPERTS; e++) g[e] /= s;
        int i0 = 0;
        #pragma unroll
        for (int e = 1; e < NUM_EXPERTS; e++) if (g[e] > g[i0]) i0 = e;
        int i1 = -1;
        #pragma unroll
        for (int e = 0; e < NUM_EXPERTS; e++)
            if (e != i0 && (i1 < 0 || g[e] > g[i1])) i1 = e;
        const float s2 = fmaxf(g[i0] + g[i1], 1e-9f);
        float w[NUM_EXPERTS] = {0.f, 0.f, 0.f, 0.f};
        w[i0] = g[i0]/s2; w[i1] = g[i1]/s2;
        #pragma unroll
        for (int e = 0; e < NUM_EXPERTS; e++) {
            g_gates[t*NUM_EXPERTS + e] = g[e];
            g_w[t*NUM_EXPERTS + e]     = w[e];
        }
    }
}

// ---------------- routing lists (deterministic stable partition) ----------------
__global__ void __launch_bounds__(128) route_kernel()
{
    const int e = threadIdx.x >> 5, lane = threadIdx.x & 31;
    int cnt = 0;
    for (int base = 0; base < TOKENS; base += 32) {
        const int t = base + lane;
        const bool sel = g_w[t*NUM_EXPERTS + e] > 0.f;
        const unsigned m = __ballot_sync(0xffffffffu, sel);
        if (sel) g_elist[e*TOKENS + cnt + __popc(m & ((1u << lane) - 1u))] = t;
        cnt += __popc(m);
    }
    __syncwarp();
    const int padded = (cnt + 127) & ~127;
    if (cnt > 0) {
        const int last = g_elist[e*TOKENS + cnt - 1];
        for (int i = cnt + lane; i < padded; i += 32) g_elist[e*TOKENS + i] = last;
    }
    if (lane == 0) g_ecnt[e] = cnt;
}

// ---------------- aux ----------------
__global__ void __launch_bounds__(256) aux_kernel(float* __restrict__ out, int out_size)
{
    __shared__ float rg[NUM_EXPERTS][256];
    __shared__ float rc[NUM_EXPERTS][256];
    const int tid = threadIdx.x;
    float gs[NUM_EXPERTS] = {0,0,0,0}, cs[NUM_EXPERTS] = {0,0,0,0};
    for (int t = tid; t < TOKENS; t += 256) {
        #pragma unroll
        for (int e = 0; e < NUM_EXPERTS; e++) {
            gs[e] += g_gates[t*NUM_EXPERTS + e];
            cs[e] += (g_w[t*NUM_EXPERTS + e] > 0.f) ? 1.f : 0.f;
        }
    }
    #pragma unroll
    for (int e = 0; e < NUM_EXPERTS; e++) { rg[e][tid] = gs[e]; rc[e][tid] = cs[e]; }
    __syncthreads();
    for (int o = 128; o > 0; o >>= 1) {
        if (tid < o)
            #pragma unroll
            for (int e = 0; e < NUM_EXPERTS; e++) { rg[e][tid] += rg[e][tid+o]; rc[e][tid] += rc[e][tid+o]; }
        __syncthreads();
    }
    if (tid == 0 && out_size > BND) {
        float aux = 0.f;
        #pragma unroll
        for (int e = 0; e < NUM_EXPERTS; e++)
            aux += (rg[e][0]*(1.f/TOKENS)) * (rc[e][0]*(1.f/TOKENS));
        out[out_size - 1] = (float)NUM_EXPERTS * aux;
    }
}

// ---------------- final ----------------
__global__ void __launch_bounds__(256) final_kernel(
    const float* __restrict__ tw, const float* __restrict__ tb, float* __restrict__ out)
{
    const size_t gid = (size_t)blockIdx.x*256 + threadIdx.x;
    if (gid >= (size_t)BND) return;
    const int d = (int)(gid % D_MODEL);
    const int n = (int)((gid / D_MODEL) % SEQ);
    float t = 0.f;
    #pragma unroll
    for (int j = 0; j < 5; j++) {
        const int nn = n - 2 + j;
        if (nn >= 0 && nn < SEQ)
            t = fmaf(g_Tr[gid + (size_t)(j-2)*D_MODEL], tw[d*5 + j], t);
    }
    out[gid] = g_xs[gid] + t + tb[d];
}

// ---------------- launch ----------------
static float* sym_addr(const void* sym) {
    void* p = nullptr;
    cudaGetSymbolAddress(&p, sym);
    return (float*)p;
}

extern "C" void kernel_launch(void* const* d_in, const int* in_sizes, int n_in,
                              void* d_out, int out_size)
{
    const float* x    = (const float*)d_in[0];
    const float* qw   = (const float*)d_in[1];  const float* qb  = (const float*)d_in[2];
    const float* kw   = (const float*)d_in[3];  const float* kb  = (const float*)d_in[4];
    const float* vw   = (const float*)d_in[5];  const float* vb  = (const float*)d_in[6];
    const float* ow   = (const float*)d_in[7];  const float* ob  = (const float*)d_in[8];
    const float* n1g  = (const float*)d_in[9];  const float* n1b = (const float*)d_in[10];
    const float* n2g  = (const float*)d_in[11]; const float* n2b = (const float*)d_in[12];
    const float* alpha= (const float*)d_in[13];
    const float* dw7  = (const float*)d_in[14];
    const float* dw25 = (const float*)d_in[15];
    const float* dw49 = (const float*)d_in[16];
    const float* rw   = (const float*)d_in[17];
    const float* ew1  = (const float*)d_in[18]; const float* eb1 = (const float*)d_in[19];
    const float* ew2  = (const float*)d_in[20]; const float* eb2 = (const float*)d_in[21];
    const float* tw   = (const float*)d_in[22]; const float* tb  = (const float*)d_in[23];
    float* out = (float*)d_out;

    float* pS   = sym_addr(g_S);
    float* pBuf = sym_addr(g_buf);
    float* pQ   = sym_addr(g_q);
    float* pK   = sym_addr(g_k);
    float* pV   = sym_addr(g_v);
    float* pY   = sym_addr(g_y);
    float* pXs  = sym_addr(g_xs);
    float* pH   = sym_addr(g_h);
    float* pW   = sym_addr(g_w);
    int*   pEL  = (int*)sym_addr(g_elist);
    int*   pEC  = (int*)sym_addr(g_ecnt);
    (void)in_sizes; (void)n_in;

    cudaFuncSetAttribute(attn_tc_kernel, cudaFuncAttributeMaxDynamicSharedMemorySize, ATT_SMEM);

    // 1) decomposition -> g_Tr, g_S
    dim3 dgrid(D_MODEL/DC_DT, SEQ/DC_NT, BATCH);
    decomp_kernel<<<dgrid, 256>>>(x, alpha, dw7, dw25, dw49);

    // 2) LN1(S) -> Sn
    ln_kernel<<<TOKENS, 256>>>(pS, n1g, n1b, pBuf);

    // 3) Q,K,V projections (tf32 mma.sync)
    dim3 gqkv(D_MODEL/128, TOKENS/128);
    tc_gemm<0><<<gqkv, 256, TCG_SMEM>>>(pBuf, qw, qb, pQ, D_MODEL, D_MODEL,
                                        nullptr, nullptr, 0, nullptr, nullptr, nullptr);
    tc_gemm<0><<<gqkv, 256, TCG_SMEM>>>(pBuf, kw, kb, pK, D_MODEL, D_MODEL,
                                        nullptr, nullptr, 0, nullptr, nullptr, nullptr);
    tc_gemm<0><<<gqkv, 256, TCG_SMEM>>>(pBuf, vw, vb, pV, D_MODEL, D_MODEL,
                                        nullptr, nullptr, 0, nullptr, nullptr, nullptr);

    // 4) attention (tensor-core)
    dim3 agrid(BATCH*NHEAD, SEQ/64);
    attn_tc_kernel<<<agrid, 128, ATT_SMEM>>>();

    // 5) O projection + residual S -> g_xs
    tc_gemm<2><<<gqkv, 256, TCG_SMEM>>>(pY, ow, ob, pXs, D_MODEL, D_MODEL,
                                        pS, nullptr, 0, nullptr, nullptr, nullptr);

    // 6) LN2 -> xf
    ln_kernel<<<TOKENS, 256>>>(pXs, n2g, n2b, pBuf);

    // 7) router + routing lists + aux
    router_kernel<<<TOKENS/8, 256>>>(pBuf, rw);
    route_kernel<<<1, 128>>>();
    aux_kernel<<<1, 256>>>(out, out_size);

    // 8) MoE FFN: routed top-2 (exact-equivalent to dense)
    dim3 gh1(MOE_HIDDEN/128, TOKENS/128);
    dim3 gh2(D_MODEL/128,    TOKENS/128);
    for (int e = 0; e < NUM_EXPERTS; e++) {
        tc_gemm<1><<<gh1, 256, TCG_SMEM>>>(pBuf, ew1 + (size_t)e*MOE_HIDDEN*D_MODEL,
                                           eb1 + (size_t)e*MOE_HIDDEN, pH,
                                           D_MODEL, MOE_HIDDEN,
                                           nullptr, nullptr, 0,
                                           pEL + e*TOKENS, nullptr, pEC + e);
        tc_gemm<3><<<gh2, 256, TCG_SMEM>>>(pH, ew2 + (size_t)e*D_MODEL*MOE_HIDDEN,
                                           eb2 + (size_t)e*D_MODEL, pXs,
                                           MOE_HIDDEN, D_MODEL,
                                           nullptr, pW, e,
                                           nullptr, pEL + e*TOKENS, pEC + e);
    }

    // 9) final
    final_kernel<<<(BND + 255)/256, 256>>>(tw, tb, out);
}

// round 9
// speedup vs baseline: 1.6250x; 1.1297x over previous
#include <cuda_runtime.h>
#include <math.h>
#include <stdint.h>

#define D_MODEL 1024
#define NHEAD 16
#define HEAD_DIM 64
#define MOE_HIDDEN 2048
#define NUM_EXPERTS 4
#define BATCH 8
#define SEQ 1024
#define TOKENS (BATCH*SEQ)          /* 8192  */
#define BND (TOKENS*D_MODEL)        /* 8388608 */
#define LN_EPS 1e-5f

// ---------------- scratch (device globals; no allocation) ----------------
__device__ float g_Tr[BND];
__device__ float g_S[BND];
__device__ float g_buf[BND];
__device__ float g_q[BND];
__device__ float g_k[BND];
__device__ float g_v[BND];
__device__ float g_y[BND];
__device__ float g_xs[BND];
__device__ float g_h[TOKENS*MOE_HIDDEN];
__device__ float g_w[TOKENS*NUM_EXPERTS];
__device__ float g_gates[TOKENS*NUM_EXPERTS];
__device__ int   g_elist[NUM_EXPERTS*TOKENS];
__device__ int   g_ecnt[NUM_EXPERTS];
// tf32-pre-rounded weights
__device__ float g_rw4[4*D_MODEL*D_MODEL];                    // qw,kw,vw,ow
__device__ float g_rew1[NUM_EXPERTS*MOE_HIDDEN*D_MODEL];
__device__ float g_rew2[NUM_EXPERTS*D_MODEL*MOE_HIDDEN];

// ============================================================
// tf32 helpers (sm_80+ PTX, no 'a'-suffix gating)
// ============================================================
__device__ __forceinline__ uint32_t f2tf32(float f) {
    uint32_t u; asm("cvt.rna.tf32.f32 %0, %1;" : "=r"(u) : "f"(f)); return u;
}
__device__ __forceinline__ float f2tf32f(float f) {
    uint32_t u; asm("cvt.rna.tf32.f32 %0, %1;" : "=r"(u) : "f"(f));
    return __uint_as_float(u);
}
__device__ __forceinline__ void mma_tf32(float* c, const uint32_t* a, const uint32_t* b) {
    asm volatile(
        "mma.sync.aligned.m16n8k8.row.col.f32.tf32.tf32.f32 "
        "{%0,%1,%2,%3}, {%4,%5,%6,%7}, {%8,%9}, {%0,%1,%2,%3};"
        : "+f"(c[0]), "+f"(c[1]), "+f"(c[2]), "+f"(c[3])
        : "r"(a[0]), "r"(a[1]), "r"(a[2]), "r"(a[3]), "r"(b[0]), "r"(b[1]));
}
__device__ __forceinline__ uint32_t smem_u32(const void* p) {
    uint32_t a;
    asm("{ .reg .u64 t; cvta.to.shared.u64 t, %1; cvt.u32.u64 %0, t; }" : "=r"(a) : "l"(p));
    return a;
}
__device__ __forceinline__ void cp16(uint32_t dst, const void* src) {
    asm volatile("cp.async.cg.shared.global [%0], [%1], 16;" :: "r"(dst), "l"(src));
}

// ---------------- weight tf32 pre-round ----------------
__global__ void __launch_bounds__(256) round_tf32_kernel(
    const float* __restrict__ src, float* __restrict__ dst, int n4)
{
    const int i = blockIdx.x*256 + threadIdx.x;
    if (i < n4) {
        const float4 v = ((const float4*)src)[i];
        uint4 u = { f2tf32(v.x), f2tf32(v.y), f2tf32(v.z), f2tf32(v.w) };
        ((uint4*)dst)[i] = u;
    }
}

// ============================================================
// tf32 mma.sync GEMM v3: cp.async 3-stage pipeline, no cvt in loop.
// Operands MUST be tf32-pre-rounded. CTA tile 128x128, BK=16,
// 256 thr (8 warps 2x4, warp tile 64x32), smem [128][20] per matrix
// per stage, 1 sync/K-iter, 2 CTAs/SM.
// EPI: 0 plain, 1 GELU(tf32-rounded out), 2 +resid, 3 scatter +=
// ============================================================
#define TCG_LDA 20
#define ST_WORDS (128*TCG_LDA)            /* 2560 words per matrix per stage */
#define TCG_SMEM (3*2*ST_WORDS*4)         /* 61440 B */

template<int EPI>
__global__ void __launch_bounds__(256, 2) tc_gemm(
    const float* __restrict__ A, const float* __restrict__ B,
    const float* __restrict__ bias, float* __restrict__ C,
    int K, int Nn,
    const float* __restrict__ resid, const float* __restrict__ wts, int expert,
    const int* __restrict__ aidx, const int* __restrict__ cidx,
    const int* __restrict__ cntp)
{
    extern __shared__ uint32_t smu[];
    const int tid = threadIdx.x;
    const int bm = blockIdx.y * 128, bn = blockIdx.x * 128;
    int cnt = 0x7fffffff;
    if (cntp) { cnt = *cntp; if (bm >= ((cnt + 127) & ~127)) return; }

    const int warp = tid >> 5, lane = tid & 31;
    const int wm = (warp >> 2) * 64, wn = (warp & 3) * 32;
    const int g = lane >> 2, t = lane & 3;

    const int lr = tid >> 2, lc = tid & 3;
    int ra0 = bm + lr, ra1 = bm + lr + 64;
    if (aidx) { ra0 = aidx[ra0]; ra1 = aidx[ra1]; }
    const float* Ag0 = A + (size_t)ra0 * K + lc * 4;
    const float* Ag1 = A + (size_t)ra1 * K + lc * 4;
    const float* Bg0 = B + (size_t)(bn + lr) * K + lc * 4;
    const float* Bg1 = B + (size_t)(bn + lr + 64) * K + lc * 4;

    const uint32_t sbase = smem_u32(smu);
    const uint32_t oa0 = (lr*TCG_LDA + lc*4)*4;
    const uint32_t oa1 = ((lr+64)*TCG_LDA + lc*4)*4;
    const uint32_t obB = ST_WORDS*4;

    float acc[4][4][4];
    #pragma unroll
    for (int i = 0; i < 4; i++)
        #pragma unroll
        for (int j = 0; j < 4; j++)
            #pragma unroll
            for (int r = 0; r < 4; r++) acc[i][j][r] = 0.f;

    const int NT = K >> 4;
    // prologue: stages 0,1
    #pragma unroll
    for (int s = 0; s < 2; s++) {
        const uint32_t sb = sbase + s*2*ST_WORDS*4;
        const int ko = s*16;
        cp16(sb + oa0, Ag0 + ko); cp16(sb + oa1, Ag1 + ko);
        cp16(sb + obB + oa0, Bg0 + ko); cp16(sb + obB + oa1, Bg1 + ko);
        asm volatile("cp.async.commit_group;");
    }

    int stage = 0;
    for (int kt = 0; kt < NT; kt++) {
        asm volatile("cp.async.wait_group 1;" ::: "memory");
        __syncthreads();
        const uint32_t* Ab = smu + stage*2*ST_WORDS;
        const uint32_t* Bb = Ab + ST_WORDS;

        #pragma unroll
        for (int ks = 0; ks < 2; ks++) {
            const int kb = ks * 8;
            uint32_t af[4][4], bf[4][2];
            #pragma unroll
            for (int mf = 0; mf < 4; mf++) {
                const uint32_t* base = Ab + (wm + mf*16 + g)*TCG_LDA + kb + t;
                af[mf][0] = base[0];
                af[mf][1] = base[8*TCG_LDA];
                af[mf][2] = base[4];
                af[mf][3] = base[8*TCG_LDA + 4];
            }
            #pragma unroll
            for (int nf = 0; nf < 4; nf++) {
                const uint32_t* base = Bb + (wn + nf*8 + g)*TCG_LDA + kb + t;
                bf[nf][0] = base[0];
                bf[nf][1] = base[4];
            }
            #pragma unroll
            for (int mf = 0; mf < 4; mf++)
                #pragma unroll
                for (int nf = 0; nf < 4; nf++)
                    mma_tf32(acc[mf][nf], af[mf], bf[nf]);
        }

        if (kt + 2 < NT) {
            const int ns = (stage + 2 >= 3) ? stage - 1 : stage + 2;
            const int ko = (kt + 2) * 16;
            const uint32_t sb = sbase + ns*2*ST_WORDS*4;
            cp16(sb + oa0, Ag0 + ko); cp16(sb + oa1, Ag1 + ko);
            cp16(sb + obB + oa0, Bg0 + ko); cp16(sb + obB + oa1, Bg1 + ko);
            asm volatile("cp.async.commit_group;");
        } else {
            asm volatile("cp.async.commit_group;");   // empty group: keeps wait_group 1 correct at tail
        }
        stage = (stage + 1 == 3) ? 0 : stage + 1;
    }

    // ---- epilogue ----
    #pragma unroll
    for (int mf = 0; mf < 4; mf++) {
        const int mp0 = bm + wm + mf*16 + g;
        const int mp1 = mp0 + 8;
        if (EPI == 3) {
            const int r0 = cidx[mp0], r1 = cidx[mp1];
            const float w0 = wts[r0*NUM_EXPERTS + expert];
            const float w1 = wts[r1*NUM_EXPERTS + expert];
            const bool ok0 = mp0 < cnt, ok1 = mp1 < cnt;
            #pragma unroll
            for (int nf = 0; nf < 4; nf++) {
                const int n0 = bn + wn + nf*8 + 2*t;
                const float b0 = bias[n0], b1 = bias[n0 + 1];
                const float v0 = acc[mf][nf][0] + b0;
                const float v1 = acc[mf][nf][1] + b1;
                const float v2 = acc[mf][nf][2] + b0;
                const float v3 = acc[mf][nf][3] + b1;
                if (ok0) {
                    const size_t i0 = (size_t)r0 * Nn + n0;
                    C[i0]   += v0 * w0;
                    C[i0+1] += v1 * w0;
                }
                if (ok1) {
                    const size_t i1 = (size_t)r1 * Nn + n0;
                    C[i1]   += v2 * w1;
                    C[i1+1] += v3 * w1;
                }
            }
        } else {
            #pragma unroll
            for (int nf = 0; nf < 4; nf++) {
                const int n0 = bn + wn + nf*8 + 2*t;
                const float b0 = bias[n0], b1 = bias[n0 + 1];
                float v0 = acc[mf][nf][0] + b0;
                float v1 = acc[mf][nf][1] + b1;
                float v2 = acc[mf][nf][2] + b0;
                float v3 = acc[mf][nf][3] + b1;
                const size_t i0 = (size_t)mp0 * Nn + n0;
                const size_t i1 = (size_t)mp1 * Nn + n0;
                if (EPI == 0) {
                    C[i0] = v0; C[i0+1] = v1; C[i1] = v2; C[i1+1] = v3;
                } else if (EPI == 1) {
                    // GELU then tf32-round (feeds GEMM2 as A)
                    C[i0]   = f2tf32f(0.5f*v0*(1.0f + erff(v0*0.70710678118654752f)));
                    C[i0+1] = f2tf32f(0.5f*v1*(1.0f + erff(v1*0.70710678118654752f)));
                    C[i1]   = f2tf32f(0.5f*v2*(1.0f + erff(v2*0.70710678118654752f)));
                    C[i1+1] = f2tf32f(0.5f*v3*(1.0f + erff(v3*0.70710678118654752f)));
                } else {
                    C[i0] = v0 + resid[i0]; C[i0+1] = v1 + resid[i0+1];
                    C[i1] = v2 + resid[i1]; C[i1+1] = v3 + resid[i1+1];
                }
            }
        }
    }
}

// ============================================================
// Tensor-core ALiBi flash attention (tf32 mma.sync) — unchanged from R8
// except y stores are tf32-rounded (y feeds O-proj GEMM as A).
// ============================================================
#define ATT_LDK 68
#define ATT_LDV 69
#define ATT_SMEM ((64*ATT_LDK + 64*ATT_LDV + 64*ATT_LDK)*4)   /* 52480 B */

__global__ void __launch_bounds__(128, 3) attn_tc_kernel()
{
    extern __shared__ uint32_t smA[];
    uint32_t* Ks = smA;
    uint32_t* Vt = smA + 64*ATT_LDK;
    uint32_t* Ps = smA + 64*ATT_LDK + 64*ATT_LDV;
    const int tid = threadIdx.x;
    const int warp = tid >> 5, lane = tid & 31;
    const int g = lane >> 2, t = lane & 3;
    const int bh = blockIdx.x;
    const int b = bh >> 4, h = bh & 15;
    const int q0 = blockIdx.y * 64;
    const float slope = exp2f(-0.5f*(float)(h + 1));

    for (int i = tid; i < 1024; i += 128) {
        const int row = i >> 4, c4 = (i & 15) * 4;
        const float4 qv = *(const float4*)(g_q + ((size_t)(b*SEQ + q0 + row))*D_MODEL + h*64 + c4);
        uint32_t* d = Ps + row*ATT_LDK + c4;
        d[0] = f2tf32(qv.x*0.125f); d[1] = f2tf32(qv.y*0.125f);
        d[2] = f2tf32(qv.z*0.125f); d[3] = f2tf32(qv.w*0.125f);
    }
    __syncthreads();
    uint32_t qf[8][4];
    #pragma unroll
    for (int k = 0; k < 8; k++) {
        const uint32_t* base = Ps + (warp*16 + g)*ATT_LDK + k*8 + t;
        qf[k][0] = base[0]; qf[k][1] = base[8*ATT_LDK];
        qf[k][2] = base[4]; qf[k][3] = base[8*ATT_LDK + 4];
    }

    float o[8][4];
    #pragma unroll
    for (int nf = 0; nf < 8; nf++)
        #pragma unroll
        for (int r = 0; r < 4; r++) o[nf][r] = 0.f;
    float l0 = 0.f, l1 = 0.f;
    const int qg0 = q0 + warp*16 + g, qg1 = qg0 + 8;

    for (int kt = 0; kt < 16; kt++) {
        __syncthreads();
        for (int i = tid; i < 1024; i += 128) {
            const int row = i >> 4, c4 = (i & 15) * 4;
            const size_t gofs = ((size_t)(b*SEQ + kt*64 + row))*D_MODEL + h*64 + c4;
            const float4 kv = *(const float4*)(g_k + gofs);
            uint32_t* dk = Ks + row*ATT_LDK + c4;
            dk[0] = f2tf32(kv.x); dk[1] = f2tf32(kv.y);
            dk[2] = f2tf32(kv.z); dk[3] = f2tf32(kv.w);
            const float4 vv = *(const float4*)(g_v + gofs);
            Vt[(c4+0)*ATT_LDV + row] = f2tf32(vv.x);
            Vt[(c4+1)*ATT_LDV + row] = f2tf32(vv.y);
            Vt[(c4+2)*ATT_LDV + row] = f2tf32(vv.z);
            Vt[(c4+3)*ATT_LDV + row] = f2tf32(vv.w);
        }
        __syncthreads();

        float s[8][4];
        #pragma unroll
        for (int nf = 0; nf < 8; nf++)
            #pragma unroll
            for (int r = 0; r < 4; r++) s[nf][r] = 0.f;
        #pragma unroll
        for (int k = 0; k < 8; k++) {
            uint32_t bf[8][2];
            #pragma unroll
            for (int nf = 0; nf < 8; nf++) {
                const uint32_t* base = Ks + (nf*8 + g)*ATT_LDK + k*8 + t;
                bf[nf][0] = base[0]; bf[nf][1] = base[4];
            }
            #pragma unroll
            for (int nf = 0; nf < 8; nf++) mma_tf32(s[nf], qf[k], bf[nf]);
        }

        #pragma unroll
        for (int nf = 0; nf < 8; nf++) {
            const int jg = kt*64 + nf*8 + 2*t;
            const int d00 = jg - qg0, d10 = jg - qg1;
            const float p00 = __expf(s[nf][0] - slope*(float)(d00   > 0 ? d00   : 0));
            const float p01 = __expf(s[nf][1] - slope*(float)(d00+1 > 0 ? d00+1 : 0));
            const float p10 = __expf(s[nf][2] - slope*(float)(d10   > 0 ? d10   : 0));
            const float p11 = __expf(s[nf][3] - slope*(float)(d10+1 > 0 ? d10+1 : 0));
            l0 += p00 + p01; l1 += p10 + p11;
            uint32_t* pr0 = Ps + (warp*16 + g)*ATT_LDK + nf*8 + 2*t;
            pr0[0] = f2tf32(p00); pr0[1] = f2tf32(p01);
            pr0[8*ATT_LDK] = f2tf32(p10); pr0[8*ATT_LDK + 1] = f2tf32(p11);
        }
        __syncwarp();

        #pragma unroll
        for (int k = 0; k < 8; k++) {
            uint32_t pf[4];
            const uint32_t* pb = Ps + (warp*16 + g)*ATT_LDK + k*8 + t;
            pf[0] = pb[0]; pf[1] = pb[8*ATT_LDK];
            pf[2] = pb[4]; pf[3] = pb[8*ATT_LDK + 4];
            #pragma unroll
            for (int nf = 0; nf < 8; nf++) {
                const uint32_t* vb = Vt + (nf*8 + g)*ATT_LDV + k*8 + t;
                uint32_t bf[2] = { vb[0], vb[4] };
                mma_tf32(o[nf], pf, bf);
            }
        }
    }

    l0 += __shfl_xor_sync(0xffffffffu, l0, 1);
    l0 += __shfl_xor_sync(0xffffffffu, l0, 2);
    l1 += __shfl_xor_sync(0xffffffffu, l1, 1);
    l1 += __shfl_xor_sync(0xffffffffu, l1, 2);
    const float inv0 = 1.f/l0, inv1 = 1.f/l1;
    float* y0 = g_y + ((size_t)(b*SEQ + qg0))*D_MODEL + h*64;
    float* y1 = g_y + ((size_t)(b*SEQ + qg1))*D_MODEL + h*64;
    #pragma unroll
    for (int nf = 0; nf < 8; nf++) {
        const int c = nf*8 + 2*t;
        y0[c]   = f2tf32f(o[nf][0]*inv0);
        y0[c+1] = f2tf32f(o[nf][1]*inv0);
        y1[c]   = f2tf32f(o[nf][2]*inv1);
        y1[c+1] = f2tf32f(o[nf][3]*inv1);
    }
}

// ---------------- Decomp1D ----------------
#define DC_NT 128
#define DC_DT 32
#define DC_HALO 24
__global__ void __launch_bounds__(256) decomp_kernel(
    const float* __restrict__ x, const float* __restrict__ alpha,
    const float* __restrict__ dw7, const float* __restrict__ dw25,
    const float* __restrict__ dw49)
{
    __shared__ float sx[DC_NT + 2*DC_HALO][DC_DT];
    __shared__ float sw7[DC_DT][7];
    __shared__ float sw25[DC_DT][25];
    __shared__ float sw49[DC_DT][49];
    const int b  = blockIdx.z;
    const int n0 = blockIdx.y * DC_NT;
    const int d0 = blockIdx.x * DC_DT;
    const int tid = threadIdx.x;

    for (int i = tid; i < DC_DT*7;  i += 256) sw7 [i/7 ][i%7 ] = dw7 [(d0 + i/7 )*7  + i%7 ];
    for (int i = tid; i < DC_DT*25; i += 256) sw25[i/25][i%25] = dw25[(d0 + i/25)*25 + i%25];
    for (int i = tid; i < DC_DT*49; i += 256) sw49[i/49][i%49] = dw49[(d0 + i/49)*49 + i%49];

    for (int i = tid; i < (DC_NT + 2*DC_HALO)*DC_DT; i += 256) {
        int r = i / DC_DT, c = i % DC_DT;
        int n = n0 + r - DC_HALO;
        if (n < 0)    n = -n;
        if (n >= SEQ) n = 2*SEQ - 2 - n;
        sx[r][c] = x[((size_t)b*SEQ + n)*D_MODEL + d0 + c];
    }
    __syncthreads();

    const float a0 = alpha[0], a1 = alpha[1], a2 = alpha[2];
    const float mx = fmaxf(a0, fmaxf(a1, a2));
    const float e0 = __expf(a0-mx), e1 = __expf(a1-mx), e2 = __expf(a2-mx);
    const float inv = 1.f/(e0+e1+e2);
    const float w0 = e0*inv, w1 = e1*inv, w2 = e2*inv;

    for (int i = tid; i < DC_NT*DC_DT; i += 256) {
        const int p = i / DC_DT, c = i % DC_DT;
        float t7 = 0.f, t25 = 0.f, t49 = 0.f;
        #pragma unroll
        for (int j = 0; j < 7;  j++) t7  = fmaf(sx[p + DC_HALO - 3  + j][c], sw7 [c][j], t7 );
        #pragma unroll
        for (int j = 0; j < 25; j++) t25 = fmaf(sx[p + DC_HALO - 12 + j][c], sw25[c][j], t25);
        #pragma unroll
        for (int j = 0; j < 49; j++) t49 = fmaf(sx[p + j][c],                sw49[c][j], t49);
        const float tr = w0*t7 + w1*t25 + w2*t49;
        const size_t idx = ((size_t)b*SEQ + n0 + p)*D_MODEL + d0 + c;
        g_Tr[idx] = tr;
        g_S[idx]  = sx[p + DC_HALO][c] - tr;
    }
}

// ---------------- LayerNorm (tf32-rounded output: feeds GEMMs as A) ----------------
__global__ void __launch_bounds__(256) ln_kernel(
    const float* __restrict__ in, const float* __restrict__ gam,
    const float* __restrict__ bet, float* __restrict__ out)
{
    __shared__ float row[D_MODEL];
    __shared__ float red[256];
    const int t = blockIdx.x, tid = threadIdx.x;
    const float* ip = in + (size_t)t*D_MODEL;
    float s = 0.f;
    for (int d = tid; d < D_MODEL; d += 256) { float v = ip[d]; row[d] = v; s += v; }
    red[tid] = s; __syncthreads();
    for (int o = 128; o > 0; o >>= 1) { if (tid < o) red[tid] += red[tid+o]; __syncthreads(); }
    const float mean = red[0] * (1.f/D_MODEL);
    __syncthreads();
    float vs = 0.f;
    for (int d = tid; d < D_MODEL; d += 256) { float dv = row[d]-mean; vs += dv*dv; }
    red[tid] = vs; __syncthreads();
    for (int o = 128; o > 0; o >>= 1) { if (tid < o) red[tid] += red[tid+o]; __syncthreads(); }
    const float rstd = rsqrtf(red[0] * (1.f/D_MODEL) + LN_EPS);
    for (int d = tid; d < D_MODEL; d += 256)
        out[(size_t)t*D_MODEL + d] = f2tf32f((row[d]-mean)*rstd*gam[d] + bet[d]);
}

// ---------------- Router ----------------
__global__ void __launch_bounds__(256) router_kernel(
    const float* __restrict__ xf, const float* __restrict__ rw)
{
    const int warp = threadIdx.x / 32, lane = threadIdx.x % 32;
    const int t = blockIdx.x*8 + warp;
    const float* xp = xf + (size_t)t*D_MODEL;
    float logit[NUM_EXPERTS];
    #pragma unroll
    for (int e = 0; e < NUM_EXPERTS; e++) {
        float p = 0.f;
        for (int d = lane; d < D_MODEL; d += 32) p = fmaf(xp[d], rw[e*D_MODEL + d], p);
        #pragma unroll
        for (int o = 16; o > 0; o >>= 1) p += __shfl_xor_sync(0xffffffffu, p, o);
        logit[e] = p;
    }
    if (lane == 0) {
        float mx = logit[0];
        #pragma unroll
        for (int e = 1; e < NUM_EXPERTS; e++) mx = fmaxf(mx, logit[e]);
        float g[NUM_EXPERTS]; float s = 0.f;
        #pragma unroll
        for (int e = 0; e < NUM_EXPERTS; e++) { g[e] = expf(logit[e]-mx); s += g[e]; }
        #pragma unroll
        for (int e = 0; e < NUM_EXPERTS; e++) g[e] /= s;
        int i0 = 0;
        #pragma unroll
        for (int e = 1; e < NUM_EXPERTS; e++) if (g[e] > g[i0]) i0 = e;
        int i1 = -1;
        #pragma unroll
        for (int e = 0; e < NUM_EXPERTS; e++)
            if (e != i0 && (i1 < 0 || g[e] > g[i1])) i1 = e;
        const float s2 = fmaxf(g[i0] + g[i1], 1e-9f);
        float w[NUM_EXPERTS] = {0.f, 0.f, 0.f, 0.f};
        w[i0] = g[i0]/s2; w[i1] = g[i1]/s2;
        #pragma unroll
        for (int e = 0; e < NUM_EXPERTS; e++) {
            g_gates[t*NUM_EXPERTS + e] = g[e];
            g_w[t*NUM_EXPERTS + e]     = w[e];
        }
    }
}

// ---------------- routing lists ----------------
__global__ void __launch_bounds__(128) route_kernel()
{
    const int e = threadIdx.x >> 5, lane = threadIdx.x & 31;
    int cnt = 0;
    for (int base = 0; base < TOKENS; base += 32) {
        const int t = base + lane;
        const bool sel = g_w[t*NUM_EXPERTS + e] > 0.f;
        const unsigned m = __ballot_sync(0xffffffffu, sel);
        if (sel) g_elist[e*TOKENS + cnt + __popc(m & ((1u << lane) - 1u))] = t;
        cnt += __popc(m);
    }
    __syncwarp();
    const int padded = (cnt + 127) & ~127;
    if (cnt > 0) {
        const int last = g_elist[e*TOKENS + cnt - 1];
        for (int i = cnt + lane; i < padded; i += 32) g_elist[e*TOKENS + i] = last;
    }
    if (lane == 0) g_ecnt[e] = cnt;
}

// ---------------- aux ----------------
__global__ void __launch_bounds__(256) aux_kernel(float* __restrict__ out, int out_size)
{
    __shared__ float rg[NUM_EXPERTS][256];
    __shared__ float rc[NUM_EXPERTS][256];
    const int tid = threadIdx.x;
    float gs[NUM_EXPERTS] = {0,0,0,0}, cs[NUM_EXPERTS] = {0,0,0,0};
    for (int t = tid; t < TOKENS; t += 256) {
        #pragma unroll
        for (int e = 0; e < NUM_EXPERTS; e++) {
            gs[e] += g_gates[t*NUM_EXPERTS + e];
            cs[e] += (g_w[t*NUM_EXPERTS + e] > 0.f) ? 1.f : 0.f;
        }
    }
    #pragma unroll
    for (int e = 0; e < NUM_EXPERTS; e++) { rg[e][tid] = gs[e]; rc[e][tid] = cs[e]; }
    __syncthreads();
    for (int o = 128; o > 0; o >>= 1) {
        if (tid < o)
            #pragma unroll
            for (int e = 0; e < NUM_EXPERTS; e++) { rg[e][tid] += rg[e][tid+o]; rc[e][tid] += rc[e][tid+o]; }
        __syncthreads();
    }
    if (tid == 0 && out_size > BND) {
        float aux = 0.f;
        #pragma unroll
        for (int e = 0; e < NUM_EXPERTS; e++)
            aux += (rg[e][0]*(1.f/TOKENS)) * (rc[e][0]*(1.f/TOKENS));
        out[out_size - 1] = (float)NUM_EXPERTS * aux;
    }
}

// ---------------- final ----------------
__global__ void __launch_bounds__(256) final_kernel(
    const float* __restrict__ tw, const float* __restrict__ tb, float* __restrict__ out)
{
    const size_t gid = (size_t)blockIdx.x*256 + threadIdx.x;
    if (gid >= (size_t)BND) return;
    const int d = (int)(gid % D_MODEL);
    const int n = (int)((gid / D_MODEL) % SEQ);
    float t = 0.f;
    #pragma unroll
    for (int j = 0; j < 5; j++) {
        const int nn = n - 2 + j;
        if (nn >= 0 && nn < SEQ)
            t = fmaf(g_Tr[gid + (size_t)(j-2)*D_MODEL], tw[d*5 + j], t);
    }
    out[gid] = g_xs[gid] + t + tb[d];
}

// ---------------- launch ----------------
static float* sym_addr(const void* sym) {
    void* p = nullptr;
    cudaGetSymbolAddress(&p, sym);
    return (float*)p;
}

extern "C" void kernel_launch(void* const* d_in, const int* in_sizes, int n_in,
                              void* d_out, int out_size)
{
    const float* x    = (const float*)d_in[0];
    const float* qw   = (const float*)d_in[1];  const float* qb  = (const float*)d_in[2];
    const float* kw   = (const float*)d_in[3];  const float* kb  = (const float*)d_in[4];
    const float* vw   = (const float*)d_in[5];  const float* vb  = (const float*)d_in[6];
    const float* ow   = (const float*)d_in[7];  const float* ob  = (const float*)d_in[8];
    const float* n1g  = (const float*)d_in[9];  const float* n1b = (const float*)d_in[10];
    const float* n2g  = (const float*)d_in[11]; const float* n2b = (const float*)d_in[12];
    const float* alpha= (const float*)d_in[13];
    const float* dw7  = (const float*)d_in[14];
    const float* dw25 = (const float*)d_in[15];
    const float* dw49 = (const float*)d_in[16];
    const float* rw   = (const float*)d_in[17];
    const float* ew1  = (const float*)d_in[18]; const float* eb1 = (const float*)d_in[19];
    const float* ew2  = (const float*)d_in[20]; const float* eb2 = (const float*)d_in[21];
    const float* tw   = (const float*)d_in[22]; const float* tb  = (const float*)d_in[23];
    float* out = (float*)d_out;

    float* pS   = sym_addr(g_S);
    float* pBuf = sym_addr(g_buf);
    float* pQ   = sym_addr(g_q);
    float* pK   = sym_addr(g_k);
    float* pV   = sym_addr(g_v);
    float* pY   = sym_addr(g_y);
    float* pXs  = sym_addr(g_xs);
    float* pH   = sym_addr(g_h);
    float* pW   = sym_addr(g_w);
    int*   pEL  = (int*)sym_addr(g_elist);
    int*   pEC  = (int*)sym_addr(g_ecnt);
    float* pRW4 = sym_addr(g_rw4);
    float* pRE1 = sym_addr(g_rew1);
    float* pRE2 = sym_addr(g_rew2);
    (void)in_sizes; (void)n_in;

    cudaFuncSetAttribute(attn_tc_kernel, cudaFuncAttributeMaxDynamicSharedMemorySize, ATT_SMEM);
    cudaFuncSetAttribute(tc_gemm<0>, cudaFuncAttributeMaxDynamicSharedMemorySize, TCG_SMEM);
    cudaFuncSetAttribute(tc_gemm<1>, cudaFuncAttributeMaxDynamicSharedMemorySize, TCG_SMEM);
    cudaFuncSetAttribute(tc_gemm<2>, cudaFuncAttributeMaxDynamicSharedMemorySize, TCG_SMEM);
    cudaFuncSetAttribute(tc_gemm<3>, cudaFuncAttributeMaxDynamicSharedMemorySize, TCG_SMEM);

    // 0) pre-round weights to tf32
    const int DD4 = D_MODEL*D_MODEL/4;          // 262144 float4
    const int E14 = NUM_EXPERTS*MOE_HIDDEN*D_MODEL/4;
    const int E24 = NUM_EXPERTS*D_MODEL*MOE_HIDDEN/4;
    round_tf32_kernel<<<(DD4+255)/256, 256>>>(qw, pRW4 + 0*D_MODEL*D_MODEL, DD4);
    round_tf32_kernel<<<(DD4+255)/256, 256>>>(kw, pRW4 + 1*D_MODEL*D_MODEL, DD4);
    round_tf32_kernel<<<(DD4+255)/256, 256>>>(vw, pRW4 + 2*D_MODEL*D_MODEL, DD4);
    round_tf32_kernel<<<(DD4+255)/256, 256>>>(ow, pRW4 + 3*D_MODEL*D_MODEL, DD4);
    round_tf32_kernel<<<(E14+255)/256, 256>>>(ew1, pRE1, E14);
    round_tf32_kernel<<<(E24+255)/256, 256>>>(ew2, pRE2, E24);

    // 1) decomposition -> g_Tr, g_S
    dim3 dgrid(D_MODEL/DC_DT, SEQ/DC_NT, BATCH);
    decomp_kernel<<<dgrid, 256>>>(x, alpha, dw7, dw25, dw49);

    // 2) LN1(S) -> Sn (tf32-rounded)
    ln_kernel<<<TOKENS, 256>>>(pS, n1g, n1b, pBuf);

    // 3) Q,K,V projections
    dim3 gqkv(D_MODEL/128, TOKENS/128);
    tc_gemm<0><<<gqkv, 256, TCG_SMEM>>>(pBuf, pRW4 + 0*D_MODEL*D_MODEL, qb, pQ, D_MODEL, D_MODEL,
                                        nullptr, nullptr, 0, nullptr, nullptr, nullptr);
    tc_gemm<0><<<gqkv, 256, TCG_SMEM>>>(pBuf, pRW4 + 1*D_MODEL*D_MODEL, kb, pK, D_MODEL, D_MODEL,
                                        nullptr, nullptr, 0, nullptr, nullptr, nullptr);
    tc_gemm<0><<<gqkv, 256, TCG_SMEM>>>(pBuf, pRW4 + 2*D_MODEL*D_MODEL, vb, pV, D_MODEL, D_MODEL,
                                        nullptr, nullptr, 0, nullptr, nullptr, nullptr);

    // 4) attention (tensor-core), y tf32-rounded
    dim3 agrid(BATCH*NHEAD, SEQ/64);
    attn_tc_kernel<<<agrid, 128, ATT_SMEM>>>();

    // 5) O projection + residual S -> g_xs
    tc_gemm<2><<<gqkv, 256, TCG_SMEM>>>(pY, pRW4 + 3*D_MODEL*D_MODEL, ob, pXs, D_MODEL, D_MODEL,
                                        pS, nullptr, 0, nullptr, nullptr, nullptr);

    // 6) LN2 -> xf (tf32-rounded)
    ln_kernel<<<TOKENS, 256>>>(pXs, n2g, n2b, pBuf);

    // 7) router + routing lists + aux
    router_kernel<<<TOKENS/8, 256>>>(pBuf, rw);
    route_kernel<<<1, 128>>>();
    aux_kernel<<<1, 256>>>(out, out_size);

    // 8) MoE FFN: routed top-2
    dim3 gh1(MOE_HIDDEN/128, TOKENS/128);
    dim3 gh2(D_MODEL/128,    TOKENS/128);
    for (int e = 0; e < NUM_EXPERTS; e++) {
        tc_gemm<1><<<gh1, 256, TCG_SMEM>>>(pBuf, pRE1 + (size_t)e*MOE_HIDDEN*D_MODEL,
                                           eb1 + (size_t)e*MOE_HIDDEN, pH,
                                           D_MODEL, MOE_HIDDEN,
                                           nullptr, nullptr, 0,
                                           pEL + e*TOKENS, nullptr, pEC + e);
        tc_gemm<3><<<gh2, 256, TCG_SMEM>>>(pH, pRE2 + (size_t)e*D_MODEL*MOE_HIDDEN,
                                           eb2 + (size_t)e*D_MODEL, pXs,
                                           MOE_HIDDEN, D_MODEL,
                                           nullptr, pW, e,
                                           nullptr, pEL + e*TOKENS, pEC + e);
    }

    // 9) final
    final_kernel<<<(BND + 255)/256, 256>>>(tw, tb, out);
}

// round 10
// speedup vs baseline: 1.7161x; 1.0560x over previous
#include <cuda_runtime.h>
#include <math.h>
#include <stdint.h>

#define D_MODEL 1024
#define NHEAD 16
#define HEAD_DIM 64
#define MOE_HIDDEN 2048
#define NUM_EXPERTS 4
#define BATCH 8
#define SEQ 1024
#define TOKENS (BATCH*SEQ)          /* 8192  */
#define BND (TOKENS*D_MODEL)        /* 8388608 */
#define QKV_LD (3*D_MODEL)
#define LN_EPS 1e-5f

// ---------------- scratch (device globals; no allocation) ----------------
__device__ float g_Tr[BND];
__device__ float g_S[BND];
__device__ float g_buf[BND];
__device__ float g_qkv[TOKENS*QKV_LD];          // packed q|k|v per token
__device__ float g_y[BND];
__device__ float g_xs[BND];
__device__ float g_h[NUM_EXPERTS*TOKENS*MOE_HIDDEN];   // per-expert hidden
__device__ float g_w[TOKENS*NUM_EXPERTS];
__device__ float g_gates[TOKENS*NUM_EXPERTS];
__device__ int   g_elist[NUM_EXPERTS*TOKENS];
__device__ int   g_ecnt[NUM_EXPERTS];
__device__ float g_qkvb[QKV_LD];                // concat qb|kb|vb
// tf32-pre-rounded weights
__device__ float g_rw4[4*D_MODEL*D_MODEL];      // qw,kw,vw,ow (contiguous!)
__device__ float g_rew1[NUM_EXPERTS*MOE_HIDDEN*D_MODEL];
__device__ float g_rew2[NUM_EXPERTS*D_MODEL*MOE_HIDDEN];

// ============================================================
// tf32 helpers
// ============================================================
__device__ __forceinline__ uint32_t f2tf32(float f) {
    uint32_t u; asm("cvt.rna.tf32.f32 %0, %1;" : "=r"(u) : "f"(f)); return u;
}
__device__ __forceinline__ float f2tf32f(float f) {
    uint32_t u; asm("cvt.rna.tf32.f32 %0, %1;" : "=r"(u) : "f"(f));
    return __uint_as_float(u);
}
__device__ __forceinline__ void mma_tf32(float* c, const uint32_t* a, const uint32_t* b) {
    asm volatile(
        "mma.sync.aligned.m16n8k8.row.col.f32.tf32.tf32.f32 "
        "{%0,%1,%2,%3}, {%4,%5,%6,%7}, {%8,%9}, {%0,%1,%2,%3};"
        : "+f"(c[0]), "+f"(c[1]), "+f"(c[2]), "+f"(c[3])
        : "r"(a[0]), "r"(a[1]), "r"(a[2]), "r"(a[3]), "r"(b[0]), "r"(b[1]));
}
__device__ __forceinline__ uint32_t smem_u32(const void* p) {
    uint32_t a;
    asm("{ .reg .u64 t; cvta.to.shared.u64 t, %1; cvt.u32.u64 %0, t; }" : "=r"(a) : "l"(p));
    return a;
}
__device__ __forceinline__ void cp16(uint32_t dst, const void* src) {
    asm volatile("cp.async.cg.shared.global [%0], [%1], 16;" :: "r"(dst), "l"(src));
}

// ---------------- weight tf32 pre-round ----------------
__global__ void __launch_bounds__(256) round_tf32_kernel(
    const float* __restrict__ src, float* __restrict__ dst, int n4)
{
    const int i = blockIdx.x*256 + threadIdx.x;
    if (i < n4) {
        const float4 v = ((const float4*)src)[i];
        uint4 u = { f2tf32(v.x), f2tf32(v.y), f2tf32(v.z), f2tf32(v.w) };
        ((uint4*)dst)[i] = u;
    }
}

// ============================================================
// tf32 mma.sync GEMM (R9 core + per-blockIdx.z expert strides):
// cp.async 3-stage pipeline, operands tf32-pre-rounded, CTA 128x128,
// BK=16, 256 thr (8 warps 2x4, warp tile 64x32), 2 CTAs/SM.
// EPI: 0 plain, 1 GELU(tf32 out), 2 +resid, 3 scatter +=
// ============================================================
#define TCG_LDA 20
#define ST_WORDS (128*TCG_LDA)
#define TCG_SMEM (3*2*ST_WORDS*4)         /* 61440 B */

template<int EPI>
__global__ void __launch_bounds__(256, 2) tc_gemm(
    const float* __restrict__ A, const float* __restrict__ B,
    const float* __restrict__ bias, float* __restrict__ C,
    int K, int Nn,
    const float* __restrict__ resid, const float* __restrict__ wts, int expert,
    const int* __restrict__ aidx, const int* __restrict__ cidx,
    const int* __restrict__ cntp,
    size_t bstride, int bias_stride, size_t cstride)
{
    extern __shared__ uint32_t smu[];
    const int tid = threadIdx.x;
    const int ez = blockIdx.z;
    const int bm = blockIdx.y * 128, bn = blockIdx.x * 128;
    int cnt = 0x7fffffff;
    if (cntp) { cnt = cntp[ez]; if (bm >= ((cnt + 127) & ~127)) return; }
    B    += (size_t)ez * bstride;
    bias += (size_t)ez * bias_stride;
    C    += (size_t)ez * cstride;
    if (aidx) aidx += ez * TOKENS;

    const int warp = tid >> 5, lane = tid & 31;
    const int wm = (warp >> 2) * 64, wn = (warp & 3) * 32;
    const int g = lane >> 2, t = lane & 3;

    const int lr = tid >> 2, lc = tid & 3;
    int ra0 = bm + lr, ra1 = bm + lr + 64;
    if (aidx) { ra0 = aidx[ra0]; ra1 = aidx[ra1]; }
    const float* Ag0 = A + (size_t)ra0 * K + lc * 4;
    const float* Ag1 = A + (size_t)ra1 * K + lc * 4;
    const float* Bg0 = B + (size_t)(bn + lr) * K + lc * 4;
    const float* Bg1 = B + (size_t)(bn + lr + 64) * K + lc * 4;

    const uint32_t sbase = smem_u32(smu);
    const uint32_t oa0 = (lr*TCG_LDA + lc*4)*4;
    const uint32_t oa1 = ((lr+64)*TCG_LDA + lc*4)*4;
    const uint32_t obB = ST_WORDS*4;

    float acc[4][4][4];
    #pragma unroll
    for (int i = 0; i < 4; i++)
        #pragma unroll
        for (int j = 0; j < 4; j++)
            #pragma unroll
            for (int r = 0; r < 4; r++) acc[i][j][r] = 0.f;

    const int NT = K >> 4;
    #pragma unroll
    for (int s = 0; s < 2; s++) {
        const uint32_t sb = sbase + s*2*ST_WORDS*4;
        const int ko = s*16;
        cp16(sb + oa0, Ag0 + ko); cp16(sb + oa1, Ag1 + ko);
        cp16(sb + obB + oa0, Bg0 + ko); cp16(sb + obB + oa1, Bg1 + ko);
        asm volatile("cp.async.commit_group;");
    }

    int stage = 0;
    for (int kt = 0; kt < NT; kt++) {
        asm volatile("cp.async.wait_group 1;" ::: "memory");
        __syncthreads();
        const uint32_t* Ab = smu + stage*2*ST_WORDS;
        const uint32_t* Bb = Ab + ST_WORDS;

        #pragma unroll
        for (int ks = 0; ks < 2; ks++) {
            const int kb = ks * 8;
            uint32_t af[4][4], bf[4][2];
            #pragma unroll
            for (int mf = 0; mf < 4; mf++) {
                const uint32_t* base = Ab + (wm + mf*16 + g)*TCG_LDA + kb + t;
                af[mf][0] = base[0];
                af[mf][1] = base[8*TCG_LDA];
                af[mf][2] = base[4];
                af[mf][3] = base[8*TCG_LDA + 4];
            }
            #pragma unroll
            for (int nf = 0; nf < 4; nf++) {
                const uint32_t* base = Bb + (wn + nf*8 + g)*TCG_LDA + kb + t;
                bf[nf][0] = base[0];
                bf[nf][1] = base[4];
            }
            #pragma unroll
            for (int mf = 0; mf < 4; mf++)
                #pragma unroll
                for (int nf = 0; nf < 4; nf++)
                    mma_tf32(acc[mf][nf], af[mf], bf[nf]);
        }

        if (kt + 2 < NT) {
            const int ns = (stage + 2 >= 3) ? stage - 1 : stage + 2;
            const int ko = (kt + 2) * 16;
            const uint32_t sb = sbase + ns*2*ST_WORDS*4;
            cp16(sb + oa0, Ag0 + ko); cp16(sb + oa1, Ag1 + ko);
            cp16(sb + obB + oa0, Bg0 + ko); cp16(sb + obB + oa1, Bg1 + ko);
            asm volatile("cp.async.commit_group;");
        } else {
            asm volatile("cp.async.commit_group;");
        }
        stage = (stage + 1 == 3) ? 0 : stage + 1;
    }

    // ---- epilogue ----
    #pragma unroll
    for (int mf = 0; mf < 4; mf++) {
        const int mp0 = bm + wm + mf*16 + g;
        const int mp1 = mp0 + 8;
        if (EPI == 3) {
            const int r0 = cidx[mp0], r1 = cidx[mp1];
            const float w0 = wts[r0*NUM_EXPERTS + expert];
            const float w1 = wts[r1*NUM_EXPERTS + expert];
            const bool ok0 = mp0 < cnt, ok1 = mp1 < cnt;
            #pragma unroll
            for (int nf = 0; nf < 4; nf++) {
                const int n0 = bn + wn + nf*8 + 2*t;
                const float b0 = bias[n0], b1 = bias[n0 + 1];
                const float v0 = acc[mf][nf][0] + b0;
                const float v1 = acc[mf][nf][1] + b1;
                const float v2 = acc[mf][nf][2] + b0;
                const float v3 = acc[mf][nf][3] + b1;
                if (ok0) {
                    const size_t i0 = (size_t)r0 * Nn + n0;
                    C[i0]   += v0 * w0;
                    C[i0+1] += v1 * w0;
                }
                if (ok1) {
                    const size_t i1 = (size_t)r1 * Nn + n0;
                    C[i1]   += v2 * w1;
                    C[i1+1] += v3 * w1;
                }
            }
        } else {
            #pragma unroll
            for (int nf = 0; nf < 4; nf++) {
                const int n0 = bn + wn + nf*8 + 2*t;
                const float b0 = bias[n0], b1 = bias[n0 + 1];
                float v0 = acc[mf][nf][0] + b0;
                float v1 = acc[mf][nf][1] + b1;
                float v2 = acc[mf][nf][2] + b0;
                float v3 = acc[mf][nf][3] + b1;
                const size_t i0 = (size_t)mp0 * Nn + n0;
                const size_t i1 = (size_t)mp1 * Nn + n0;
                if (EPI == 0) {
                    C[i0] = v0; C[i0+1] = v1; C[i1] = v2; C[i1+1] = v3;
                } else if (EPI == 1) {
                    C[i0]   = f2tf32f(0.5f*v0*(1.0f + erff(v0*0.70710678118654752f)));
                    C[i0+1] = f2tf32f(0.5f*v1*(1.0f + erff(v1*0.70710678118654752f)));
                    C[i1]   = f2tf32f(0.5f*v2*(1.0f + erff(v2*0.70710678118654752f)));
                    C[i1+1] = f2tf32f(0.5f*v3*(1.0f + erff(v3*0.70710678118654752f)));
                } else {
                    C[i0] = v0 + resid[i0]; C[i0+1] = v1 + resid[i0+1];
                    C[i1] = v2 + resid[i1]; C[i1+1] = v3 + resid[i1+1];
                }
            }
        }
    }
}

// ============================================================
// Tensor-core ALiBi flash attention — reads packed g_qkv (stride 3072)
// ============================================================
#define ATT_LDK 68
#define ATT_LDV 69
#define ATT_SMEM ((64*ATT_LDK + 64*ATT_LDV + 64*ATT_LDK)*4)   /* 52480 B */

__global__ void __launch_bounds__(128, 3) attn_tc_kernel()
{
    extern __shared__ uint32_t smA[];
    uint32_t* Ks = smA;
    uint32_t* Vt = smA + 64*ATT_LDK;
    uint32_t* Ps = smA + 64*ATT_LDK + 64*ATT_LDV;
    const int tid = threadIdx.x;
    const int warp = tid >> 5, lane = tid & 31;
    const int g = lane >> 2, t = lane & 3;
    const int bh = blockIdx.x;
    const int b = bh >> 4, h = bh & 15;
    const int q0 = blockIdx.y * 64;
    const float slope = exp2f(-0.5f*(float)(h + 1));

    for (int i = tid; i < 1024; i += 128) {
        const int row = i >> 4, c4 = (i & 15) * 4;
        const float4 qv = *(const float4*)(g_qkv + ((size_t)(b*SEQ + q0 + row))*QKV_LD + h*64 + c4);
        uint32_t* d = Ps + row*ATT_LDK + c4;
        d[0] = f2tf32(qv.x*0.125f); d[1] = f2tf32(qv.y*0.125f);
        d[2] = f2tf32(qv.z*0.125f); d[3] = f2tf32(qv.w*0.125f);
    }
    __syncthreads();
    uint32_t qf[8][4];
    #pragma unroll
    for (int k = 0; k < 8; k++) {
        const uint32_t* base = Ps + (warp*16 + g)*ATT_LDK + k*8 + t;
        qf[k][0] = base[0]; qf[k][1] = base[8*ATT_LDK];
        qf[k][2] = base[4]; qf[k][3] = base[8*ATT_LDK + 4];
    }

    float o[8][4];
    #pragma unroll
    for (int nf = 0; nf < 8; nf++)
        #pragma unroll
        for (int r = 0; r < 4; r++) o[nf][r] = 0.f;
    float l0 = 0.f, l1 = 0.f;
    const int qg0 = q0 + warp*16 + g, qg1 = qg0 + 8;

    for (int kt = 0; kt < 16; kt++) {
        __syncthreads();
        for (int i = tid; i < 1024; i += 128) {
            const int row = i >> 4, c4 = (i & 15) * 4;
            const size_t gofs = ((size_t)(b*SEQ + kt*64 + row))*QKV_LD + h*64 + c4;
            const float4 kv = *(const float4*)(g_qkv + gofs + D_MODEL);
            uint32_t* dk = Ks + row*ATT_LDK + c4;
            dk[0] = f2tf32(kv.x); dk[1] = f2tf32(kv.y);
            dk[2] = f2tf32(kv.z); dk[3] = f2tf32(kv.w);
            const float4 vv = *(const float4*)(g_qkv + gofs + 2*D_MODEL);
            Vt[(c4+0)*ATT_LDV + row] = f2tf32(vv.x);
            Vt[(c4+1)*ATT_LDV + row] = f2tf32(vv.y);
            Vt[(c4+2)*ATT_LDV + row] = f2tf32(vv.z);
            Vt[(c4+3)*ATT_LDV + row] = f2tf32(vv.w);
        }
        __syncthreads();

        float s[8][4];
        #pragma unroll
        for (int nf = 0; nf < 8; nf++)
            #pragma unroll
            for (int r = 0; r < 4; r++) s[nf][r] = 0.f;
        #pragma unroll
        for (int k = 0; k < 8; k++) {
            uint32_t bf[8][2];
            #pragma unroll
            for (int nf = 0; nf < 8; nf++) {
                const uint32_t* base = Ks + (nf*8 + g)*ATT_LDK + k*8 + t;
                bf[nf][0] = base[0]; bf[nf][1] = base[4];
            }
            #pragma unroll
            for (int nf = 0; nf < 8; nf++) mma_tf32(s[nf], qf[k], bf[nf]);
        }

        #pragma unroll
        for (int nf = 0; nf < 8; nf++) {
            const int jg = kt*64 + nf*8 + 2*t;
            const int d00 = jg - qg0, d10 = jg - qg1;
            const float p00 = __expf(s[nf][0] - slope*(float)(d00   > 0 ? d00   : 0));
            const float p01 = __expf(s[nf][1] - slope*(float)(d00+1 > 0 ? d00+1 : 0));
            const float p10 = __expf(s[nf][2] - slope*(float)(d10   > 0 ? d10   : 0));
            const float p11 = __expf(s[nf][3] - slope*(float)(d10+1 > 0 ? d10+1 : 0));
            l0 += p00 + p01; l1 += p10 + p11;
            uint32_t* pr0 = Ps + (warp*16 + g)*ATT_LDK + nf*8 + 2*t;
            pr0[0] = f2tf32(p00); pr0[1] = f2tf32(p01);
            pr0[8*ATT_LDK] = f2tf32(p10); pr0[8*ATT_LDK + 1] = f2tf32(p11);
        }
        __syncwarp();

        #pragma unroll
        for (int k = 0; k < 8; k++) {
            uint32_t pf[4];
            const uint32_t* pb = Ps + (warp*16 + g)*ATT_LDK + k*8 + t;
            pf[0] = pb[0]; pf[1] = pb[8*ATT_LDK];
            pf[2] = pb[4]; pf[3] = pb[8*ATT_LDK + 4];
            #pragma unroll
            for (int nf = 0; nf < 8; nf++) {
                const uint32_t* vb = Vt + (nf*8 + g)*ATT_LDV + k*8 + t;
                uint32_t bf[2] = { vb[0], vb[4] };
                mma_tf32(o[nf], pf, bf);
            }
        }
    }

    l0 += __shfl_xor_sync(0xffffffffu, l0, 1);
    l0 += __shfl_xor_sync(0xffffffffu, l0, 2);
    l1 += __shfl_xor_sync(0xffffffffu, l1, 1);
    l1 += __shfl_xor_sync(0xffffffffu, l1, 2);
    const float inv0 = 1.f/l0, inv1 = 1.f/l1;
    float* y0 = g_y + ((size_t)(b*SEQ + qg0))*D_MODEL + h*64;
    float* y1 = g_y + ((size_t)(b*SEQ + qg1))*D_MODEL + h*64;
    #pragma unroll
    for (int nf = 0; nf < 8; nf++) {
        const int c = nf*8 + 2*t;
        y0[c]   = f2tf32f(o[nf][0]*inv0);
        y0[c+1] = f2tf32f(o[nf][1]*inv0);
        y1[c]   = f2tf32f(o[nf][2]*inv1);
        y1[c+1] = f2tf32f(o[nf][3]*inv1);
    }
}

// ---------------- Decomp1D ----------------
#define DC_NT 128
#define DC_DT 32
#define DC_HALO 24
__global__ void __launch_bounds__(256) decomp_kernel(
    const float* __restrict__ x, const float* __restrict__ alpha,
    const float* __restrict__ dw7, const float* __restrict__ dw25,
    const float* __restrict__ dw49)
{
    __shared__ float sx[DC_NT + 2*DC_HALO][DC_DT];
    __shared__ float sw7[DC_DT][7];
    __shared__ float sw25[DC_DT][25];
    __shared__ float sw49[DC_DT][49];
    const int b  = blockIdx.z;
    const int n0 = blockIdx.y * DC_NT;
    const int d0 = blockIdx.x * DC_DT;
    const int tid = threadIdx.x;

    for (int i = tid; i < DC_DT*7;  i += 256) sw7 [i/7 ][i%7 ] = dw7 [(d0 + i/7 )*7  + i%7 ];
    for (int i = tid; i < DC_DT*25; i += 256) sw25[i/25][i%25] = dw25[(d0 + i/25)*25 + i%25];
    for (int i = tid; i < DC_DT*49; i += 256) sw49[i/49][i%49] = dw49[(d0 + i/49)*49 + i%49];

    for (int i = tid; i < (DC_NT + 2*DC_HALO)*DC_DT; i += 256) {
        int r = i / DC_DT, c = i % DC_DT;
        int n = n0 + r - DC_HALO;
        if (n < 0)    n = -n;
        if (n >= SEQ) n = 2*SEQ - 2 - n;
        sx[r][c] = x[((size_t)b*SEQ + n)*D_MODEL + d0 + c];
    }
    __syncthreads();

    const float a0 = alpha[0], a1 = alpha[1], a2 = alpha[2];
    const float mx = fmaxf(a0, fmaxf(a1, a2));
    const float e0 = __expf(a0-mx), e1 = __expf(a1-mx), e2 = __expf(a2-mx);
    const float inv = 1.f/(e0+e1+e2);
    const float w0 = e0*inv, w1 = e1*inv, w2 = e2*inv;

    for (int i = tid; i < DC_NT*DC_DT; i += 256) {
        const int p = i / DC_DT, c = i % DC_DT;
        float t7 = 0.f, t25 = 0.f, t49 = 0.f;
        #pragma unroll
        for (int j = 0; j < 7;  j++) t7  = fmaf(sx[p + DC_HALO - 3  + j][c], sw7 [c][j], t7 );
        #pragma unroll
        for (int j = 0; j < 25; j++) t25 = fmaf(sx[p + DC_HALO - 12 + j][c], sw25[c][j], t25);
        #pragma unroll
        for (int j = 0; j < 49; j++) t49 = fmaf(sx[p + j][c],                sw49[c][j], t49);
        const float tr = w0*t7 + w1*t25 + w2*t49;
        const size_t idx = ((size_t)b*SEQ + n0 + p)*D_MODEL + d0 + c;
        g_Tr[idx] = tr;
        g_S[idx]  = sx[p + DC_HALO][c] - tr;
    }
}

// ---------------- LayerNorm (tf32-rounded output) ----------------
__global__ void __launch_bounds__(256) ln_kernel(
    const float* __restrict__ in, const float* __restrict__ gam,
    const float* __restrict__ bet, float* __restrict__ out)
{
    __shared__ float row[D_MODEL];
    __shared__ float red[256];
    const int t = blockIdx.x, tid = threadIdx.x;
    const float* ip = in + (size_t)t*D_MODEL;
    float s = 0.f;
    for (int d = tid; d < D_MODEL; d += 256) { float v = ip[d]; row[d] = v; s += v; }
    red[tid] = s; __syncthreads();
    for (int o = 128; o > 0; o >>= 1) { if (tid < o) red[tid] += red[tid+o]; __syncthreads(); }
    const float mean = red[0] * (1.f/D_MODEL);
    __syncthreads();
    float vs = 0.f;
    for (int d = tid; d < D_MODEL; d += 256) { float dv = row[d]-mean; vs += dv*dv; }
    red[tid] = vs; __syncthreads();
    for (int o = 128; o > 0; o >>= 1) { if (tid < o) red[tid] += red[tid+o]; __syncthreads(); }
    const float rstd = rsqrtf(red[0] * (1.f/D_MODEL) + LN_EPS);
    for (int d = tid; d < D_MODEL; d += 256)
        out[(size_t)t*D_MODEL + d] = f2tf32f((row[d]-mean)*rstd*gam[d] + bet[d]);
}

// ---------------- Router ----------------
__global__ void __launch_bounds__(256) router_kernel(
    const float* __restrict__ xf, const float* __restrict__ rw)
{
    const int warp = threadIdx.x / 32, lane = threadIdx.x % 32;
    const int t = blockIdx.x*8 + warp;
    const float* xp = xf + (size_t)t*D_MODEL;
    float logit[NUM_EXPERTS];
    #pragma unroll
    for (int e = 0; e < NUM_EXPERTS; e++) {
        float p = 0.f;
        for (int d = lane; d < D_MODEL; d += 32) p = fmaf(xp[d], rw[e*D_MODEL + d], p);
        #pragma unroll
        for (int o = 16; o > 0; o >>= 1) p += __shfl_xor_sync(0xffffffffu, p, o);
        logit[e] = p;
    }
    if (lane == 0) {
        float mx = logit[0];
        #pragma unroll
        for (int e = 1; e < NUM_EXPERTS; e++) mx = fmaxf(mx, logit[e]);
        float g[NUM_EXPERTS]; float s = 0.f;
        #pragma unroll
        for (int e = 0; e < NUM_EXPERTS; e++) { g[e] = expf(logit[e]-mx); s += g[e]; }
        #pragma unroll
        for (int e = 0; e < NUM_EXPERTS; e++) g[e] /= s;
        int i0 = 0;
        #pragma unroll
        for (int e = 1; e < NUM_EXPERTS; e++) if (g[e] > g[i0]) i0 = e;
        int i1 = -1;
        #pragma unroll
        for (int e = 0; e < NUM_EXPERTS; e++)
            if (e != i0 && (i1 < 0 || g[e] > g[i1])) i1 = e;
        const float s2 = fmaxf(g[i0] + g[i1], 1e-9f);
        float w[NUM_EXPERTS] = {0.f, 0.f, 0.f, 0.f};
        w[i0] = g[i0]/s2; w[i1] = g[i1]/s2;
        #pragma unroll
        for (int e = 0; e < NUM_EXPERTS; e++) {
            g_gates[t*NUM_EXPERTS + e] = g[e];
            g_w[t*NUM_EXPERTS + e]     = w[e];
        }
    }
}

// ---------------- routing lists ----------------
__global__ void __launch_bounds__(128) route_kernel()
{
    const int e = threadIdx.x >> 5, lane = threadIdx.x & 31;
    int cnt = 0;
    for (int base = 0; base < TOKENS; base += 32) {
        const int t = base + lane;
        const bool sel = g_w[t*NUM_EXPERTS + e] > 0.f;
        const unsigned m = __ballot_sync(0xffffffffu, sel);
        if (sel) g_elist[e*TOKENS + cnt + __popc(m & ((1u << lane) - 1u))] = t;
        cnt += __popc(m);
    }
    __syncwarp();
    const int padded = (cnt + 127) & ~127;
    if (cnt > 0) {
        const int last = g_elist[e*TOKENS + cnt - 1];
        for (int i = cnt + lane; i < padded; i += 32) g_elist[e*TOKENS + i] = last;
    }
    if (lane == 0) g_ecnt[e] = cnt;
}

// ---------------- aux ----------------
__global__ void __launch_bounds__(256) aux_kernel(float* __restrict__ out, int out_size)
{
    __shared__ float rg[NUM_EXPERTS][256];
    __shared__ float rc[NUM_EXPERTS][256];
    const int tid = threadIdx.x;
    float gs[NUM_EXPERTS] = {0,0,0,0}, cs[NUM_EXPERTS] = {0,0,0,0};
    for (int t = tid; t < TOKENS; t += 256) {
        #pragma unroll
        for (int e = 0; e < NUM_EXPERTS; e++) {
            gs[e] += g_gates[t*NUM_EXPERTS + e];
            cs[e] += (g_w[t*NUM_EXPERTS + e] > 0.f) ? 1.f : 0.f;
        }
    }
    #pragma unroll
    for (int e = 0; e < NUM_EXPERTS; e++) { rg[e][tid] = gs[e]; rc[e][tid] = cs[e]; }
    __syncthreads();
    for (int o = 128; o > 0; o >>= 1) {
        if (tid < o)
            #pragma unroll
            for (int e = 0; e < NUM_EXPERTS; e++) { rg[e][tid] += rg[e][tid+o]; rc[e][tid] += rc[e][tid+o]; }
        __syncthreads();
    }
    if (tid == 0 && out_size > BND) {
        float aux = 0.f;
        #pragma unroll
        for (int e = 0; e < NUM_EXPERTS; e++)
            aux += (rg[e][0]*(1.f/TOKENS)) * (rc[e][0]*(1.f/TOKENS));
        out[out_size - 1] = (float)NUM_EXPERTS * aux;
    }
}

// ---------------- final ----------------
__global__ void __launch_bounds__(256) final_kernel(
    const float* __restrict__ tw, const float* __restrict__ tb, float* __restrict__ out)
{
    const size_t gid = (size_t)blockIdx.x*256 + threadIdx.x;
    if (gid >= (size_t)BND) return;
    const int d = (int)(gid % D_MODEL);
    const int n = (int)((gid / D_MODEL) % SEQ);
    float t = 0.f;
    #pragma unroll
    for (int j = 0; j < 5; j++) {
        const int nn = n - 2 + j;
        if (nn >= 0 && nn < SEQ)
            t = fmaf(g_Tr[gid + (size_t)(j-2)*D_MODEL], tw[d*5 + j], t);
    }
    out[gid] = g_xs[gid] + t + tb[d];
}

// ---------------- launch ----------------
static float* sym_addr(const void* sym) {
    void* p = nullptr;
    cudaGetSymbolAddress(&p, sym);
    return (float*)p;
}

extern "C" void kernel_launch(void* const* d_in, const int* in_sizes, int n_in,
                              void* d_out, int out_size)
{
    const float* x    = (const float*)d_in[0];
    const float* qw   = (const float*)d_in[1];  const float* qb  = (const float*)d_in[2];
    const float* kw   = (const float*)d_in[3];  const float* kb  = (const float*)d_in[4];
    const float* vw   = (const float*)d_in[5];  const float* vb  = (const float*)d_in[6];
    const float* ow   = (const float*)d_in[7];  const float* ob  = (const float*)d_in[8];
    const float* n1g  = (const float*)d_in[9];  const float* n1b = (const float*)d_in[10];
    const float* n2g  = (const float*)d_in[11]; const float* n2b = (const float*)d_in[12];
    const float* alpha= (const float*)d_in[13];
    const float* dw7  = (const float*)d_in[14];
    const float* dw25 = (const float*)d_in[15];
    const float* dw49 = (const float*)d_in[16];
    const float* rw   = (const float*)d_in[17];
    const float* ew1  = (const float*)d_in[18]; const float* eb1 = (const float*)d_in[19];
    const float* ew2  = (const float*)d_in[20]; const float* eb2 = (const float*)d_in[21];
    const float* tw   = (const float*)d_in[22]; const float* tb  = (const float*)d_in[23];
    float* out = (float*)d_out;

    float* pS   = sym_addr(g_S);
    float* pBuf = sym_addr(g_buf);
    float* pQKV = sym_addr(g_qkv);
    float* pY   = sym_addr(g_y);
    float* pXs  = sym_addr(g_xs);
    float* pH   = sym_addr(g_h);
    float* pW   = sym_addr(g_w);
    int*   pEL  = (int*)sym_addr(g_elist);
    int*   pEC  = (int*)sym_addr(g_ecnt);
    float* pRW4 = sym_addr(g_rw4);
    float* pRE1 = sym_addr(g_rew1);
    float* pRE2 = sym_addr(g_rew2);
    float* pQKVB= sym_addr(g_qkvb);
    (void)in_sizes; (void)n_in;

    cudaFuncSetAttribute(attn_tc_kernel, cudaFuncAttributeMaxDynamicSharedMemorySize, ATT_SMEM);
    cudaFuncSetAttribute(tc_gemm<0>, cudaFuncAttributeMaxDynamicSharedMemorySize, TCG_SMEM);
    cudaFuncSetAttribute(tc_gemm<1>, cudaFuncAttributeMaxDynamicSharedMemorySize, TCG_SMEM);
    cudaFuncSetAttribute(tc_gemm<2>, cudaFuncAttributeMaxDynamicSharedMemorySize, TCG_SMEM);
    cudaFuncSetAttribute(tc_gemm<3>, cudaFuncAttributeMaxDynamicSharedMemorySize, TCG_SMEM);

    // 0) pre-round weights to tf32 + concat qkv bias
    const int DD4 = D_MODEL*D_MODEL/4;
    const int E14 = NUM_EXPERTS*MOE_HIDDEN*D_MODEL/4;
    const int E24 = NUM_EXPERTS*D_MODEL*MOE_HIDDEN/4;
    round_tf32_kernel<<<(DD4+255)/256, 256>>>(qw, pRW4 + 0*D_MODEL*D_MODEL, DD4);
    round_tf32_kernel<<<(DD4+255)/256, 256>>>(kw, pRW4 + 1*D_MODEL*D_MODEL, DD4);
    round_tf32_kernel<<<(DD4+255)/256, 256>>>(vw, pRW4 + 2*D_MODEL*D_MODEL, DD4);
    round_tf32_kernel<<<(DD4+255)/256, 256>>>(ow, pRW4 + 3*D_MODEL*D_MODEL, DD4);
    round_tf32_kernel<<<(E14+255)/256, 256>>>(ew1, pRE1, E14);
    round_tf32_kernel<<<(E24+255)/256, 256>>>(ew2, pRE2, E24);
    cudaMemcpyAsync(pQKVB,            qb, D_MODEL*4, cudaMemcpyDeviceToDevice);
    cudaMemcpyAsync(pQKVB + D_MODEL,  kb, D_MODEL*4, cudaMemcpyDeviceToDevice);
    cudaMemcpyAsync(pQKVB + 2*D_MODEL,vb, D_MODEL*4, cudaMemcpyDeviceToDevice);

    // 1) decomposition -> g_Tr, g_S
    dim3 dgrid(D_MODEL/DC_DT, SEQ/DC_NT, BATCH);
    decomp_kernel<<<dgrid, 256>>>(x, alpha, dw7, dw25, dw49);

    // 2) LN1(S) -> Sn (tf32-rounded)
    ln_kernel<<<TOKENS, 256>>>(pS, n1g, n1b, pBuf);

    // 3) fused QKV projection: one GEMM, N=3072
    dim3 gq(QKV_LD/128, TOKENS/128, 1);
    tc_gemm<0><<<gq, 256, TCG_SMEM>>>(pBuf, pRW4, pQKVB, pQKV, D_MODEL, QKV_LD,
                                      nullptr, nullptr, 0, nullptr, nullptr, nullptr,
                                      0, 0, 0);

    // 4) attention (tensor-core), y tf32-rounded
    dim3 agrid(BATCH*NHEAD, SEQ/64);
    attn_tc_kernel<<<agrid, 128, ATT_SMEM>>>();

    // 5) O projection + residual S -> g_xs
    dim3 go(D_MODEL/128, TOKENS/128, 1);
    tc_gemm<2><<<go, 256, TCG_SMEM>>>(pY, pRW4 + 3*D_MODEL*D_MODEL, ob, pXs, D_MODEL, D_MODEL,
                                      pS, nullptr, 0, nullptr, nullptr, nullptr,
                                      0, 0, 0);

    // 6) LN2 -> xf (tf32-rounded)
    ln_kernel<<<TOKENS, 256>>>(pXs, n2g, n2b, pBuf);

    // 7) router + routing lists + aux
    router_kernel<<<TOKENS/8, 256>>>(pBuf, rw);
    route_kernel<<<1, 128>>>();
    aux_kernel<<<1, 256>>>(out, out_size);

    // 8) MoE FFN: fused GEMM1 over all experts (blockIdx.z = expert)
    dim3 gh1(MOE_HIDDEN/128, TOKENS/128, NUM_EXPERTS);
    tc_gemm<1><<<gh1, 256, TCG_SMEM>>>(pBuf, pRE1, eb1, pH,
                                       D_MODEL, MOE_HIDDEN,
                                       nullptr, nullptr, 0,
                                       pEL, nullptr, pEC,
                                       (size_t)MOE_HIDDEN*D_MODEL, MOE_HIDDEN,
                                       (size_t)TOKENS*MOE_HIDDEN);
    // GEMM2: per-expert (scatter-accumulate into shared rows -> keep serialized)
    dim3 gh2(D_MODEL/128, TOKENS/128, 1);
    for (int e = 0; e < NUM_EXPERTS; e++) {
        tc_gemm<3><<<gh2, 256, TCG_SMEM>>>(pH + (size_t)e*TOKENS*MOE_HIDDEN,
                                           pRE2 + (size_t)e*D_MODEL*MOE_HIDDEN,
                                           eb2 + (size_t)e*D_MODEL, pXs,
                                           MOE_HIDDEN, D_MODEL,
                                           nullptr, pW, e,
                                           nullptr, pEL + e*TOKENS, pEC + e,
                                           0, 0, 0);
    }

    // 9) final
    final_kernel<<<(BND + 255)/256, 256>>>(tw, tb, out);
}

// round 11
// speedup vs baseline: 2.4351x; 1.4190x over previous
#include <cuda_runtime.h>
#include <cuda_bf16.h>
#include <math.h>
#include <stdint.h>

#define D_MODEL 1024
#define NHEAD 16
#define HEAD_DIM 64
#define MOE_HIDDEN 2048
#define NUM_EXPERTS 4
#define BATCH 8
#define SEQ 1024
#define TOKENS (BATCH*SEQ)          /* 8192  */
#define BND (TOKENS*D_MODEL)        /* 8388608 */
#define QKV_LD (3*D_MODEL)
#define LN_EPS 1e-5f

// ---------------- scratch (device globals; no allocation) ----------------
__device__ float g_Tr[BND];
__device__ float g_S[BND];
__device__ float g_buf[BND];                    // LN2 fp32 (router)
__device__ __nv_bfloat16 g_bufh[BND];           // LN bf16 (GEMM A)
__device__ float g_qkv[TOKENS*QKV_LD];          // packed q|k|v per token (fp32)
__device__ __nv_bfloat16 g_yh[BND];             // attention out, bf16 (O-proj A)
__device__ float g_xs[BND];
__device__ __nv_bfloat16 g_hh[NUM_EXPERTS*TOKENS*MOE_HIDDEN];  // per-expert hidden (bf16)
__device__ float g_w[TOKENS*NUM_EXPERTS];
__device__ float g_gates[TOKENS*NUM_EXPERTS];
__device__ int   g_elist[NUM_EXPERTS*TOKENS];
__device__ int   g_ecnt[NUM_EXPERTS];
__device__ float g_qkvb[QKV_LD];                // concat qb|kb|vb (fp32)
// bf16-pre-rounded weights
__device__ __nv_bfloat16 g_rw4h[4*D_MODEL*D_MODEL];       // qw,kw,vw,ow (contiguous)
__device__ __nv_bfloat16 g_rew1h[NUM_EXPERTS*MOE_HIDDEN*D_MODEL];
__device__ __nv_bfloat16 g_rew2h[NUM_EXPERTS*D_MODEL*MOE_HIDDEN];

// ============================================================
// helpers
// ============================================================
__device__ __forceinline__ uint32_t f2tf32(float f) {
    uint32_t u; asm("cvt.rna.tf32.f32 %0, %1;" : "=r"(u) : "f"(f)); return u;
}
__device__ __forceinline__ void mma_tf32(float* c, const uint32_t* a, const uint32_t* b) {
    asm volatile(
        "mma.sync.aligned.m16n8k8.row.col.f32.tf32.tf32.f32 "
        "{%0,%1,%2,%3}, {%4,%5,%6,%7}, {%8,%9}, {%0,%1,%2,%3};"
        : "+f"(c[0]), "+f"(c[1]), "+f"(c[2]), "+f"(c[3])
        : "r"(a[0]), "r"(a[1]), "r"(a[2]), "r"(a[3]), "r"(b[0]), "r"(b[1]));
}
__device__ __forceinline__ void mma_bf16(float* c, const uint32_t* a, const uint32_t* b) {
    asm volatile(
        "mma.sync.aligned.m16n8k16.row.col.f32.bf16.bf16.f32 "
        "{%0,%1,%2,%3}, {%4,%5,%6,%7}, {%8,%9}, {%0,%1,%2,%3};"
        : "+f"(c[0]), "+f"(c[1]), "+f"(c[2]), "+f"(c[3])
        : "r"(a[0]), "r"(a[1]), "r"(a[2]), "r"(a[3]), "r"(b[0]), "r"(b[1]));
}
__device__ __forceinline__ uint32_t smem_u32(const void* p) {
    uint32_t a;
    asm("{ .reg .u64 t; cvta.to.shared.u64 t, %1; cvt.u32.u64 %0, t; }" : "=r"(a) : "l"(p));
    return a;
}
__device__ __forceinline__ void cp16(uint32_t dst, const void* src) {
    asm volatile("cp.async.cg.shared.global [%0], [%1], 16;" :: "r"(dst), "l"(src));
}

// ---------------- weight bf16 pre-round (4 floats -> 4 bf16 per thread-iter) ----------------
__global__ void __launch_bounds__(256) round_bf16_kernel(
    const float* __restrict__ src, __nv_bfloat16* __restrict__ dst, int n4)
{
    const int i = blockIdx.x*256 + threadIdx.x;
    if (i < n4) {
        const float4 v = ((const float4*)src)[i];
        __nv_bfloat162 lo = { __float2bfloat16(v.x), __float2bfloat16(v.y) };
        __nv_bfloat162 hi = { __float2bfloat16(v.z), __float2bfloat16(v.w) };
        ((__nv_bfloat162*)dst)[2*i]   = lo;
        ((__nv_bfloat162*)dst)[2*i+1] = hi;
    }
}

// ============================================================
// bf16 mma.sync GEMM: C[m,n] = sum_k A[m,k]*B[n,k]  (A,B bf16; acc fp32)
// cp.async 3-stage pipeline, CTA 128x128, BK=32 elems (16 words),
// 256 thr (8 warps 2x4, warp tile 64x32), smem rows LDA=20 words
// (proven conflict-free), 1 sync/K-iter, 2 CTAs/SM.
// EPI: 0 plain fp32, 1 GELU->bf16, 2 +resid fp32, 3 scatter += fp32
// ============================================================
#define TCG_LDA 20
#define ST_WORDS (128*TCG_LDA)
#define TCG_SMEM (3*2*ST_WORDS*4)         /* 61440 B */

template<int EPI>
__global__ void __launch_bounds__(256, 2) tc_gemm(
    const __nv_bfloat16* __restrict__ A, const __nv_bfloat16* __restrict__ B,
    const float* __restrict__ bias, float* __restrict__ C,
    int K, int Nn,
    const float* __restrict__ resid, const float* __restrict__ wts, int expert,
    const int* __restrict__ aidx, const int* __restrict__ cidx,
    const int* __restrict__ cntp,
    size_t bstride, int bias_stride, size_t cstride)
{
    extern __shared__ uint32_t smu[];
    const int tid = threadIdx.x;
    const int ez = blockIdx.z;
    const int bm = blockIdx.y * 128, bn = blockIdx.x * 128;
    int cnt = 0x7fffffff;
    if (cntp) { cnt = cntp[ez]; if (bm >= ((cnt + 127) & ~127)) return; }
    B    += (size_t)ez * bstride;
    bias += (size_t)ez * bias_stride;
    float* Cf = C + (EPI == 1 ? (size_t)0 : (size_t)ez * cstride);
    __nv_bfloat16* Cb = (__nv_bfloat16*)C + (EPI == 1 ? (size_t)ez * cstride : (size_t)0);
    if (aidx) aidx += ez * TOKENS;

    const int warp = tid >> 5, lane = tid & 31;
    const int wm = (warp >> 2) * 64, wn = (warp & 3) * 32;
    const int g = lane >> 2, t = lane & 3;

    const int lr = tid >> 2, lc = tid & 3;   // staging: row(0..63), 16B-chunk(0..3)
    int ra0 = bm + lr, ra1 = bm + lr + 64;
    if (aidx) { ra0 = aidx[ra0]; ra1 = aidx[ra1]; }
    const __nv_bfloat16* Ag0 = A + (size_t)ra0 * K + lc * 8;
    const __nv_bfloat16* Ag1 = A + (size_t)ra1 * K + lc * 8;
    const __nv_bfloat16* Bg0 = B + (size_t)(bn + lr) * K + lc * 8;
    const __nv_bfloat16* Bg1 = B + (size_t)(bn + lr + 64) * K + lc * 8;

    const uint32_t sbase = smem_u32(smu);
    const uint32_t oa0 = (lr*TCG_LDA + lc*4)*4;
    const uint32_t oa1 = ((lr+64)*TCG_LDA + lc*4)*4;
    const uint32_t obB = ST_WORDS*4;

    float acc[4][4][4];
    #pragma unroll
    for (int i = 0; i < 4; i++)
        #pragma unroll
        for (int j = 0; j < 4; j++)
            #pragma unroll
            for (int r = 0; r < 4; r++) acc[i][j][r] = 0.f;

    const int NT = K >> 5;                   // BK = 32 bf16 per iter
    #pragma unroll
    for (int s = 0; s < 2; s++) {
        const uint32_t sb = sbase + s*2*ST_WORDS*4;
        const int ko = s*32;
        cp16(sb + oa0, Ag0 + ko); cp16(sb + oa1, Ag1 + ko);
        cp16(sb + obB + oa0, Bg0 + ko); cp16(sb + obB + oa1, Bg1 + ko);
        asm volatile("cp.async.commit_group;");
    }

    int stage = 0;
    for (int kt = 0; kt < NT; kt++) {
        asm volatile("cp.async.wait_group 1;" ::: "memory");
        __syncthreads();
        const uint32_t* Ab = smu + stage*2*ST_WORDS;
        const uint32_t* Bb = Ab + ST_WORDS;

        #pragma unroll
        for (int ks = 0; ks < 2; ks++) {       // each ks = K16 via m16n8k16
            const int kb = ks * 8;             // word offset
            uint32_t af[4][4], bf[4][2];
            #pragma unroll
            for (int mf = 0; mf < 4; mf++) {
                const uint32_t* base = Ab + (wm + mf*16 + g)*TCG_LDA + kb + t;
                af[mf][0] = base[0];
                af[mf][1] = base[8*TCG_LDA];
                af[mf][2] = base[4];
                af[mf][3] = base[8*TCG_LDA + 4];
            }
            #pragma unroll
            for (int nf = 0; nf < 4; nf++) {
                const uint32_t* base = Bb + (wn + nf*8 + g)*TCG_LDA + kb + t;
                bf[nf][0] = base[0];
                bf[nf][1] = base[4];
            }
            #pragma unroll
            for (int mf = 0; mf < 4; mf++)
                #pragma unroll
                for (int nf = 0; nf < 4; nf++)
                    mma_bf16(acc[mf][nf], af[mf], bf[nf]);
        }

        if (kt + 2 < NT) {
            const int ns = (stage + 2 >= 3) ? stage - 1 : stage + 2;
            const int ko = (kt + 2) * 32;
            const uint32_t sb = sbase + ns*2*ST_WORDS*4;
            cp16(sb + oa0, Ag0 + ko); cp16(sb + oa1, Ag1 + ko);
            cp16(sb + obB + oa0, Bg0 + ko); cp16(sb + obB + oa1, Bg1 + ko);
            asm volatile("cp.async.commit_group;");
        } else {
            asm volatile("cp.async.commit_group;");
        }
        stage = (stage + 1 == 3) ? 0 : stage + 1;
    }

    // ---- epilogue ----
    #pragma unroll
    for (int mf = 0; mf < 4; mf++) {
        const int mp0 = bm + wm + mf*16 + g;
        const int mp1 = mp0 + 8;
        if (EPI == 3) {
            const int r0 = cidx[mp0], r1 = cidx[mp1];
            const float w0 = wts[r0*NUM_EXPERTS + expert];
            const float w1 = wts[r1*NUM_EXPERTS + expert];
            const bool ok0 = mp0 < cnt, ok1 = mp1 < cnt;
            #pragma unroll
            for (int nf = 0; nf < 4; nf++) {
                const int n0 = bn + wn + nf*8 + 2*t;
                const float b0 = bias[n0], b1 = bias[n0 + 1];
                const float v0 = acc[mf][nf][0] + b0;
                const float v1 = acc[mf][nf][1] + b1;
                const float v2 = acc[mf][nf][2] + b0;
                const float v3 = acc[mf][nf][3] + b1;
                if (ok0) {
                    const size_t i0 = (size_t)r0 * Nn + n0;
                    Cf[i0]   += v0 * w0;
                    Cf[i0+1] += v1 * w0;
                }
                if (ok1) {
                    const size_t i1 = (size_t)r1 * Nn + n0;
                    Cf[i1]   += v2 * w1;
                    Cf[i1+1] += v3 * w1;
                }
            }
        } else {
            #pragma unroll
            for (int nf = 0; nf < 4; nf++) {
                const int n0 = bn + wn + nf*8 + 2*t;
                const float b0 = bias[n0], b1 = bias[n0 + 1];
                float v0 = acc[mf][nf][0] + b0;
                float v1 = acc[mf][nf][1] + b1;
                float v2 = acc[mf][nf][2] + b0;
                float v3 = acc[mf][nf][3] + b1;
                const size_t i0 = (size_t)mp0 * Nn + n0;
                const size_t i1 = (size_t)mp1 * Nn + n0;
                if (EPI == 0) {
                    Cf[i0] = v0; Cf[i0+1] = v1; Cf[i1] = v2; Cf[i1+1] = v3;
                } else if (EPI == 1) {
                    Cb[i0]   = __float2bfloat16(0.5f*v0*(1.0f + erff(v0*0.70710678118654752f)));
                    Cb[i0+1] = __float2bfloat16(0.5f*v1*(1.0f + erff(v1*0.70710678118654752f)));
                    Cb[i1]   = __float2bfloat16(0.5f*v2*(1.0f + erff(v2*0.70710678118654752f)));
                    Cb[i1+1] = __float2bfloat16(0.5f*v3*(1.0f + erff(v3*0.70710678118654752f)));
                } else {
                    Cf[i0] = v0 + resid[i0]; Cf[i0+1] = v1 + resid[i0+1];
                    Cf[i1] = v2 + resid[i1]; Cf[i1+1] = v3 + resid[i1+1];
                }
            }
        }
    }
}

// ============================================================
// Tensor-core ALiBi flash attention (tf32) — reads packed g_qkv fp32,
// writes y as bf16 (feeds O-proj GEMM as A).
// ============================================================
#define ATT_LDK 68
#define ATT_LDV 69
#define ATT_SMEM ((64*ATT_LDK + 64*ATT_LDV + 64*ATT_LDK)*4)   /* 52480 B */

__global__ void __launch_bounds__(128, 3) attn_tc_kernel()
{
    extern __shared__ uint32_t smA[];
    uint32_t* Ks = smA;
    uint32_t* Vt = smA + 64*ATT_LDK;
    uint32_t* Ps = smA + 64*ATT_LDK + 64*ATT_LDV;
    const int tid = threadIdx.x;
    const int warp = tid >> 5, lane = tid & 31;
    const int g = lane >> 2, t = lane & 3;
    const int bh = blockIdx.x;
    const int b = bh >> 4, h = bh & 15;
    const int q0 = blockIdx.y * 64;
    const float slope = exp2f(-0.5f*(float)(h + 1));

    for (int i = tid; i < 1024; i += 128) {
        const int row = i >> 4, c4 = (i & 15) * 4;
        const float4 qv = *(const float4*)(g_qkv + ((size_t)(b*SEQ + q0 + row))*QKV_LD + h*64 + c4);
        uint32_t* d = Ps + row*ATT_LDK + c4;
        d[0] = f2tf32(qv.x*0.125f); d[1] = f2tf32(qv.y*0.125f);
        d[2] = f2tf32(qv.z*0.125f); d[3] = f2tf32(qv.w*0.125f);
    }
    __syncthreads();
    uint32_t qf[8][4];
    #pragma unroll
    for (int k = 0; k < 8; k++) {
        const uint32_t* base = Ps + (warp*16 + g)*ATT_LDK + k*8 + t;
        qf[k][0] = base[0]; qf[k][1] = base[8*ATT_LDK];
        qf[k][2] = base[4]; qf[k][3] = base[8*ATT_LDK + 4];
    }

    float o[8][4];
    #pragma unroll
    for (int nf = 0; nf < 8; nf++)
        #pragma unroll
        for (int r = 0; r < 4; r++) o[nf][r] = 0.f;
    float l0 = 0.f, l1 = 0.f;
    const int qg0 = q0 + warp*16 + g, qg1 = qg0 + 8;

    for (int kt = 0; kt < 16; kt++) {
        __syncthreads();
        for (int i = tid; i < 1024; i += 128) {
            const int row = i >> 4, c4 = (i & 15) * 4;
            const size_t gofs = ((size_t)(b*SEQ + kt*64 + row))*QKV_LD + h*64 + c4;
            const float4 kv = *(const float4*)(g_qkv + gofs + D_MODEL);
            uint32_t* dk = Ks + row*ATT_LDK + c4;
            dk[0] = f2tf32(kv.x); dk[1] = f2tf32(kv.y);
            dk[2] = f2tf32(kv.z); dk[3] = f2tf32(kv.w);
            const float4 vv = *(const float4*)(g_qkv + gofs + 2*D_MODEL);
            Vt[(c4+0)*ATT_LDV + row] = f2tf32(vv.x);
            Vt[(c4+1)*ATT_LDV + row] = f2tf32(vv.y);
            Vt[(c4+2)*ATT_LDV + row] = f2tf32(vv.z);
            Vt[(c4+3)*ATT_LDV + row] = f2tf32(vv.w);
        }
        __syncthreads();

        float s[8][4];
        #pragma unroll
        for (int nf = 0; nf < 8; nf++)
            #pragma unroll
            for (int r = 0; r < 4; r++) s[nf][r] = 0.f;
        #pragma unroll
        for (int k = 0; k < 8; k++) {
            uint32_t bf[8][2];
            #pragma unroll
            for (int nf = 0; nf < 8; nf++) {
                const uint32_t* base = Ks + (nf*8 + g)*ATT_LDK + k*8 + t;
                bf[nf][0] = base[0]; bf[nf][1] = base[4];
            }
            #pragma unroll
            for (int nf = 0; nf < 8; nf++) mma_tf32(s[nf], qf[k], bf[nf]);
        }

        #pragma unroll
        for (int nf = 0; nf < 8; nf++) {
            const int jg = kt*64 + nf*8 + 2*t;
            const int d00 = jg - qg0, d10 = jg - qg1;
            const float p00 = __expf(s[nf][0] - slope*(float)(d00   > 0 ? d00   : 0));
            const float p01 = __expf(s[nf][1] - slope*(float)(d00+1 > 0 ? d00+1 : 0));
            const float p10 = __expf(s[nf][2] - slope*(float)(d10   > 0 ? d10   : 0));
            const float p11 = __expf(s[nf][3] - slope*(float)(d10+1 > 0 ? d10+1 : 0));
            l0 += p00 + p01; l1 += p10 + p11;
            uint32_t* pr0 = Ps + (warp*16 + g)*ATT_LDK + nf*8 + 2*t;
            pr0[0] = f2tf32(p00); pr0[1] = f2tf32(p01);
            pr0[8*ATT_LDK] = f2tf32(p10); pr0[8*ATT_LDK + 1] = f2tf32(p11);
        }
        __syncwarp();

        #pragma unroll
        for (int k = 0; k < 8; k++) {
            uint32_t pf[4];
            const uint32_t* pb = Ps + (warp*16 + g)*ATT_LDK + k*8 + t;
            pf[0] = pb[0]; pf[1] = pb[8*ATT_LDK];
            pf[2] = pb[4]; pf[3] = pb[8*ATT_LDK + 4];
            #pragma unroll
            for (int nf = 0; nf < 8; nf++) {
                const uint32_t* vb = Vt + (nf*8 + g)*ATT_LDV + k*8 + t;
                uint32_t bf[2] = { vb[0], vb[4] };
                mma_tf32(o[nf], pf, bf);
            }
        }
    }

    l0 += __shfl_xor_sync(0xffffffffu, l0, 1);
    l0 += __shfl_xor_sync(0xffffffffu, l0, 2);
    l1 += __shfl_xor_sync(0xffffffffu, l1, 1);
    l1 += __shfl_xor_sync(0xffffffffu, l1, 2);
    const float inv0 = 1.f/l0, inv1 = 1.f/l1;
    __nv_bfloat16* y0 = g_yh + ((size_t)(b*SEQ + qg0))*D_MODEL + h*64;
    __nv_bfloat16* y1 = g_yh + ((size_t)(b*SEQ + qg1))*D_MODEL + h*64;
    #pragma unroll
    for (int nf = 0; nf < 8; nf++) {
        const int c = nf*8 + 2*t;
        y0[c]   = __float2bfloat16(o[nf][0]*inv0);
        y0[c+1] = __float2bfloat16(o[nf][1]*inv0);
        y1[c]   = __float2bfloat16(o[nf][2]*inv1);
        y1[c+1] = __float2bfloat16(o[nf][3]*inv1);
    }
}

// ---------------- Decomp1D ----------------
#define DC_NT 128
#define DC_DT 32
#define DC_HALO 24
__global__ void __launch_bounds__(256) decomp_kernel(
    const float* __restrict__ x, const float* __restrict__ alpha,
    const float* __restrict__ dw7, const float* __restrict__ dw25,
    const float* __restrict__ dw49)
{
    __shared__ float sx[DC_NT + 2*DC_HALO][DC_DT];
    __shared__ float sw7[DC_DT][7];
    __shared__ float sw25[DC_DT][25];
    __shared__ float sw49[DC_DT][49];
    const int b  = blockIdx.z;
    const int n0 = blockIdx.y * DC_NT;
    const int d0 = blockIdx.x * DC_DT;
    const int tid = threadIdx.x;

    for (int i = tid; i < DC_DT*7;  i += 256) sw7 [i/7 ][i%7 ] = dw7 [(d0 + i/7 )*7  + i%7 ];
    for (int i = tid; i < DC_DT*25; i += 256) sw25[i/25][i%25] = dw25[(d0 + i/25)*25 + i%25];
    for (int i = tid; i < DC_DT*49; i += 256) sw49[i/49][i%49] = dw49[(d0 + i/49)*49 + i%49];

    for (int i = tid; i < (DC_NT + 2*DC_HALO)*DC_DT; i += 256) {
        int r = i / DC_DT, c = i % DC_DT;
        int n = n0 + r - DC_HALO;
        if (n < 0)    n = -n;
        if (n >= SEQ) n = 2*SEQ - 2 - n;
        sx[r][c] = x[((size_t)b*SEQ + n)*D_MODEL + d0 + c];
    }
    __syncthreads();

    const float a0 = alpha[0], a1 = alpha[1], a2 = alpha[2];
    const float mx = fmaxf(a0, fmaxf(a1, a2));
    const float e0 = __expf(a0-mx), e1 = __expf(a1-mx), e2 = __expf(a2-mx);
    const float inv = 1.f/(e0+e1+e2);
    const float w0 = e0*inv, w1 = e1*inv, w2 = e2*inv;

    for (int i = tid; i < DC_NT*DC_DT; i += 256) {
        const int p = i / DC_DT, c = i % DC_DT;
        float t7 = 0.f, t25 = 0.f, t49 = 0.f;
        #pragma unroll
        for (int j = 0; j < 7;  j++) t7  = fmaf(sx[p + DC_HALO - 3  + j][c], sw7 [c][j], t7 );
        #pragma unroll
        for (int j = 0; j < 25; j++) t25 = fmaf(sx[p + DC_HALO - 12 + j][c], sw25[c][j], t25);
        #pragma unroll
        for (int j = 0; j < 49; j++) t49 = fmaf(sx[p + j][c],                sw49[c][j], t49);
        const float tr = w0*t7 + w1*t25 + w2*t49;
        const size_t idx = ((size_t)b*SEQ + n0 + p)*D_MODEL + d0 + c;
        g_Tr[idx] = tr;
        g_S[idx]  = sx[p + DC_HALO][c] - tr;
    }
}

// ---------------- LayerNorm: bf16 out (GEMM A) + optional fp32 out (router) ----------------
__global__ void __launch_bounds__(256) ln_kernel(
    const float* __restrict__ in, const float* __restrict__ gam,
    const float* __restrict__ bet, __nv_bfloat16* __restrict__ outh,
    float* __restrict__ outf)
{
    __shared__ float row[D_MODEL];
    __shared__ float red[256];
    const int t = blockIdx.x, tid = threadIdx.x;
    const float* ip = in + (size_t)t*D_MODEL;
    float s = 0.f;
    for (int d = tid; d < D_MODEL; d += 256) { float v = ip[d]; row[d] = v; s += v; }
    red[tid] = s; __syncthreads();
    for (int o = 128; o > 0; o >>= 1) { if (tid < o) red[tid] += red[tid+o]; __syncthreads(); }
    const float mean = red[0] * (1.f/D_MODEL);
    __syncthreads();
    float vs = 0.f;
    for (int d = tid; d < D_MODEL; d += 256) { float dv = row[d]-mean; vs += dv*dv; }
    red[tid] = vs; __syncthreads();
    for (int o = 128; o > 0; o >>= 1) { if (tid < o) red[tid] += red[tid+o]; __syncthreads(); }
    const float rstd = rsqrtf(red[0] * (1.f/D_MODEL) + LN_EPS);
    for (int d = tid; d < D_MODEL; d += 256) {
        const float v = (row[d]-mean)*rstd*gam[d] + bet[d];
        outh[(size_t)t*D_MODEL + d] = __float2bfloat16(v);
        if (outf) outf[(size_t)t*D_MODEL + d] = v;
    }
}

// ---------------- Router (fp32 xf) ----------------
__global__ void __launch_bounds__(256) router_kernel(
    const float* __restrict__ xf, const float* __restrict__ rw)
{
    const int warp = threadIdx.x / 32, lane = threadIdx.x % 32;
    const int t = blockIdx.x*8 + warp;
    const float* xp = xf + (size_t)t*D_MODEL;
    float logit[NUM_EXPERTS];
    #pragma unroll
    for (int e = 0; e < NUM_EXPERTS; e++) {
        float p = 0.f;
        for (int d = lane; d < D_MODEL; d += 32) p = fmaf(xp[d], rw[e*D_MODEL + d], p);
        #pragma unroll
        for (int o = 16; o > 0; o >>= 1) p += __shfl_xor_sync(0xffffffffu, p, o);
        logit[e] = p;
    }
    if (lane == 0) {
        float mx = logit[0];
        #pragma unroll
        for (int e = 1; e < NUM_EXPERTS; e++) mx = fmaxf(mx, logit[e]);
        float g[NUM_EXPERTS]; float s = 0.f;
        #pragma unroll
        for (int e = 0; e < NUM_EXPERTS; e++) { g[e] = expf(logit[e]-mx); s += g[e]; }
        #pragma unroll
        for (int e = 0; e < NUM_EXPERTS; e++) g[e] /= s;
        int i0 = 0;
        #pragma unroll
        for (int e = 1; e < NUM_EXPERTS; e++) if (g[e] > g[i0]) i0 = e;
        int i1 = -1;
        #pragma unroll
        for (int e = 0; e < NUM_EXPERTS; e++)
            if (e != i0 && (i1 < 0 || g[e] > g[i1])) i1 = e;
        const float s2 = fmaxf(g[i0] + g[i1], 1e-9f);
        float w[NUM_EXPERTS] = {0.f, 0.f, 0.f, 0.f};
        w[i0] = g[i0]/s2; w[i1] = g[i1]/s2;
        #pragma unroll
        for (int e = 0; e < NUM_EXPERTS; e++) {
            g_gates[t*NUM_EXPERTS + e] = g[e];
            g_w[t*NUM_EXPERTS + e]     = w[e];
        }
    }
}

// ---------------- routing lists ----------------
__global__ void __launch_bounds__(128) route_kernel()
{
    const int e = threadIdx.x >> 5, lane = threadIdx.x & 31;
    int cnt = 0;
    for (int base = 0; base < TOKENS; base += 32) {
        const int t = base + lane;
        const bool sel = g_w[t*NUM_EXPERTS + e] > 0.f;
        const unsigned m = __ballot_sync(0xffffffffu, sel);
        if (sel) g_elist[e*TOKENS + cnt + __popc(m & ((1u << lane) - 1u))] = t;
        cnt += __popc(m);
    }
    __syncwarp();
    const int padded = (cnt + 127) & ~127;
    if (cnt > 0) {
        const int last = g_elist[e*TOKENS + cnt - 1];
        for (int i = cnt + lane; i < padded; i += 32) g_elist[e*TOKENS + i] = last;
    }
    if (lane == 0) g_ecnt[e] = cnt;
}

// ---------------- aux ----------------
__global__ void __launch_bounds__(256) aux_kernel(float* __restrict__ out, int out_size)
{
    __shared__ float rg[NUM_EXPERTS][256];
    __shared__ float rc[NUM_EXPERTS][256];
    const int tid = threadIdx.x;
    float gs[NUM_EXPERTS] = {0,0,0,0}, cs[NUM_EXPERTS] = {0,0,0,0};
    for (int t = tid; t < TOKENS; t += 256) {
        #pragma unroll
        for (int e = 0; e < NUM_EXPERTS; e++) {
            gs[e] += g_gates[t*NUM_EXPERTS + e];
            cs[e] += (g_w[t*NUM_EXPERTS + e] > 0.f) ? 1.f : 0.f;
        }
    }
    #pragma unroll
    for (int e = 0; e < NUM_EXPERTS; e++) { rg[e][tid] = gs[e]; rc[e][tid] = cs[e]; }
    __syncthreads();
    for (int o = 128; o > 0; o >>= 1) {
        if (tid < o)
            #pragma unroll
            for (int e = 0; e < NUM_EXPERTS; e++) { rg[e][tid] += rg[e][tid+o]; rc[e][tid] += rc[e][tid+o]; }
        __syncthreads();
    }
    if (tid == 0 && out_size > BND) {
        float aux = 0.f;
        #pragma unroll
        for (int e = 0; e < NUM_EXPERTS; e++)
            aux += (rg[e][0]*(1.f/TOKENS)) * (rc[e][0]*(1.f/TOKENS));
        out[out_size - 1] = (float)NUM_EXPERTS * aux;
    }
}

// ---------------- final ----------------
__global__ void __launch_bounds__(256) final_kernel(
    const float* __restrict__ tw, const float* __restrict__ tb, float* __restrict__ out)
{
    const size_t gid = (size_t)blockIdx.x*256 + threadIdx.x;
    if (gid >= (size_t)BND) return;
    const int d = (int)(gid % D_MODEL);
    const int n = (int)((gid / D_MODEL) % SEQ);
    float t = 0.f;
    #pragma unroll
    for (int j = 0; j < 5; j++) {
        const int nn = n - 2 + j;
        if (nn >= 0 && nn < SEQ)
            t = fmaf(g_Tr[gid + (size_t)(j-2)*D_MODEL], tw[d*5 + j], t);
    }
    out[gid] = g_xs[gid] + t + tb[d];
}

// ---------------- launch ----------------
static void* sym_addr(const void* sym) {
    void* p = nullptr;
    cudaGetSymbolAddress(&p, sym);
    return p;
}

extern "C" void kernel_launch(void* const* d_in, const int* in_sizes, int n_in,
                              void* d_out, int out_size)
{
    const float* x    = (const float*)d_in[0];
    const float* qw   = (const float*)d_in[1];  const float* qb  = (const float*)d_in[2];
    const float* kw   = (const float*)d_in[3];  const float* kb  = (const float*)d_in[4];
    const float* vw   = (const float*)d_in[5];  const float* vb  = (const float*)d_in[6];
    const float* ow   = (const float*)d_in[7];  const float* ob  = (const float*)d_in[8];
    const float* n1g  = (const float*)d_in[9];  const float* n1b = (const float*)d_in[10];
    const float* n2g  = (const float*)d_in[11]; const float* n2b = (const float*)d_in[12];
    const float* alpha= (const float*)d_in[13];
    const float* dw7  = (const float*)d_in[14];
    const float* dw25 = (const float*)d_in[15];
    const float* dw49 = (const float*)d_in[16];
    const float* rw   = (const float*)d_in[17];
    const float* ew1  = (const float*)d_in[18]; const float* eb1 = (const float*)d_in[19];
    const float* ew2  = (const float*)d_in[20]; const float* eb2 = (const float*)d_in[21];
    const float* tw   = (const float*)d_in[22]; const float* tb  = (const float*)d_in[23];
    float* out = (float*)d_out;

    float* pS   = (float*)sym_addr(g_S);
    float* pBuf = (float*)sym_addr(g_buf);
    __nv_bfloat16* pBufH = (__nv_bfloat16*)sym_addr(g_bufh);
    float* pQKV = (float*)sym_addr(g_qkv);
    __nv_bfloat16* pYH = (__nv_bfloat16*)sym_addr(g_yh);
    float* pXs  = (float*)sym_addr(g_xs);
    __nv_bfloat16* pHH = (__nv_bfloat16*)sym_addr(g_hh);
    float* pW   = (float*)sym_addr(g_w);
    int*   pEL  = (int*)sym_addr(g_elist);
    int*   pEC  = (int*)sym_addr(g_ecnt);
    __nv_bfloat16* pRW4 = (__nv_bfloat16*)sym_addr(g_rw4h);
    __nv_bfloat16* pRE1 = (__nv_bfloat16*)sym_addr(g_rew1h);
    __nv_bfloat16* pRE2 = (__nv_bfloat16*)sym_addr(g_rew2h);
    float* pQKVB= (float*)sym_addr(g_qkvb);
    (void)in_sizes; (void)n_in;

    cudaFuncSetAttribute(attn_tc_kernel, cudaFuncAttributeMaxDynamicSharedMemorySize, ATT_SMEM);
    cudaFuncSetAttribute(tc_gemm<0>, cudaFuncAttributeMaxDynamicSharedMemorySize, TCG_SMEM);
    cudaFuncSetAttribute(tc_gemm<1>, cudaFuncAttributeMaxDynamicSharedMemorySize, TCG_SMEM);
    cudaFuncSetAttribute(tc_gemm<2>, cudaFuncAttributeMaxDynamicSharedMemorySize, TCG_SMEM);
    cudaFuncSetAttribute(tc_gemm<3>, cudaFuncAttributeMaxDynamicSharedMemorySize, TCG_SMEM);

    // 0) pre-round weights to bf16 + concat qkv bias
    const int DD4 = D_MODEL*D_MODEL/4;
    const int E14 = NUM_EXPERTS*MOE_HIDDEN*D_MODEL/4;
    const int E24 = NUM_EXPERTS*D_MODEL*MOE_HIDDEN/4;
    round_bf16_kernel<<<(DD4+255)/256, 256>>>(qw, pRW4 + 0*D_MODEL*D_MODEL, DD4);
    round_bf16_kernel<<<(DD4+255)/256, 256>>>(kw, pRW4 + 1*D_MODEL*D_MODEL, DD4);
    round_bf16_kernel<<<(DD4+255)/256, 256>>>(vw, pRW4 + 2*D_MODEL*D_MODEL, DD4);
    round_bf16_kernel<<<(DD4+255)/256, 256>>>(ow, pRW4 + 3*D_MODEL*D_MODEL, DD4);
    round_bf16_kernel<<<(E14+255)/256, 256>>>(ew1, pRE1, E14);
    round_bf16_kernel<<<(E24+255)/256, 256>>>(ew2, pRE2, E24);
    cudaMemcpyAsync(pQKVB,            qb, D_MODEL*4, cudaMemcpyDeviceToDevice);
    cudaMemcpyAsync(pQKVB + D_MODEL,  kb, D_MODEL*4, cudaMemcpyDeviceToDevice);
    cudaMemcpyAsync(pQKVB + 2*D_MODEL,vb, D_MODEL*4, cudaMemcpyDeviceToDevice);

    // 1) decomposition -> g_Tr, g_S
    dim3 dgrid(D_MODEL/DC_DT, SEQ/DC_NT, BATCH);
    decomp_kernel<<<dgrid, 256>>>(x, alpha, dw7, dw25, dw49);

    // 2) LN1(S) -> bf16 Sn
    ln_kernel<<<TOKENS, 256>>>(pS, n1g, n1b, pBufH, nullptr);

    // 3) fused QKV projection: one bf16 GEMM, N=3072
    dim3 gq(QKV_LD/128, TOKENS/128, 1);
    tc_gemm<0><<<gq, 256, TCG_SMEM>>>(pBufH, pRW4, pQKVB, pQKV, D_MODEL, QKV_LD,
                                      nullptr, nullptr, 0, nullptr, nullptr, nullptr,
                                      0, 0, 0);

    // 4) attention (tf32), y -> bf16
    dim3 agrid(BATCH*NHEAD, SEQ/64);
    attn_tc_kernel<<<agrid, 128, ATT_SMEM>>>();

    // 5) O projection + residual S -> g_xs
    dim3 go(D_MODEL/128, TOKENS/128, 1);
    tc_gemm<2><<<go, 256, TCG_SMEM>>>(pYH, pRW4 + (size_t)3*D_MODEL*D_MODEL, ob, pXs,
                                      D_MODEL, D_MODEL,
                                      pS, nullptr, 0, nullptr, nullptr, nullptr,
                                      0, 0, 0);

    // 6) LN2 -> bf16 xf (GEMM) + fp32 xf (router)
    ln_kernel<<<TOKENS, 256>>>(pXs, n2g, n2b, pBufH, pBuf);

    // 7) router (fp32 xf) + routing lists + aux
    router_kernel<<<TOKENS/8, 256>>>(pBuf, rw);
    route_kernel<<<1, 128>>>();
    aux_kernel<<<1, 256>>>(out, out_size);

    // 8) MoE FFN: fused bf16 GEMM1 over all experts (blockIdx.z = expert)
    dim3 gh1(MOE_HIDDEN/128, TOKENS/128, NUM_EXPERTS);
    tc_gemm<1><<<gh1, 256, TCG_SMEM>>>(pBufH, pRE1, eb1, (float*)pHH,
                                       D_MODEL, MOE_HIDDEN,
                                       nullptr, nullptr, 0,
                                       pEL, nullptr, pEC,
                                       (size_t)MOE_HIDDEN*D_MODEL, MOE_HIDDEN,
                                       (size_t)TOKENS*MOE_HIDDEN);
    // GEMM2: per-expert scatter-accumulate (serialized for determinism)
    dim3 gh2(D_MODEL/128, TOKENS/128, 1);
    for (int e = 0; e < NUM_EXPERTS; e++) {
        tc_gemm<3><<<gh2, 256, TCG_SMEM>>>(pHH + (size_t)e*TOKENS*MOE_HIDDEN,
                                           pRE2 + (size_t)e*D_MODEL*MOE_HIDDEN,
                                           eb2 + (size_t)e*D_MODEL, pXs,
                                           MOE_HIDDEN, D_MODEL,
                                           nullptr, pW, e,
                                           nullptr, pEL + e*TOKENS, pEC + e,
                                           0, 0, 0);
    }

    // 9) final
    final_kernel<<<(BND + 255)/256, 256>>>(tw, tb, out);
}

// round 12
// speedup vs baseline: 2.6051x; 1.0698x over previous
#include <cuda_runtime.h>
#include <cuda_bf16.h>
#include <math.h>
#include <stdint.h>

#define D_MODEL 1024
#define NHEAD 16
#define HEAD_DIM 64
#define MOE_HIDDEN 2048
#define NUM_EXPERTS 4
#define BATCH 8
#define SEQ 1024
#define TOKENS (BATCH*SEQ)          /* 8192  */
#define BND (TOKENS*D_MODEL)        /* 8388608 */
#define QKV_LD (3*D_MODEL)
#define LN_EPS 1e-5f

// ---------------- scratch (device globals; no allocation) ----------------
__device__ float g_Tr[BND];
__device__ float g_S[BND];
__device__ float g_buf[BND];                    // LN2 fp32 (router)
__device__ __nv_bfloat16 g_bufh[BND];           // LN bf16 (GEMM A)
__device__ float g_qkv[TOKENS*QKV_LD];          // packed q|k|v per token (fp32)
__device__ __nv_bfloat16 g_yh[BND];             // attention out, bf16 (O-proj A)
__device__ float g_xs[BND];
__device__ __nv_bfloat16 g_hh[NUM_EXPERTS*TOKENS*MOE_HIDDEN];  // per-expert hidden (bf16)
__device__ float g_w[TOKENS*NUM_EXPERTS];
__device__ float g_gates[TOKENS*NUM_EXPERTS];
__device__ int   g_elist[NUM_EXPERTS*TOKENS];
__device__ int   g_ecnt[NUM_EXPERTS];
__device__ float g_qkvb[QKV_LD];                // concat qb|kb|vb (fp32)
// bf16-pre-rounded weights
__device__ __nv_bfloat16 g_rw4h[4*D_MODEL*D_MODEL];       // qw,kw,vw,ow (contiguous)
__device__ __nv_bfloat16 g_rew1h[NUM_EXPERTS*MOE_HIDDEN*D_MODEL];
__device__ __nv_bfloat16 g_rew2h[NUM_EXPERTS*D_MODEL*MOE_HIDDEN];

// ============================================================
// helpers
// ============================================================
__device__ __forceinline__ uint32_t f2tf32(float f) {
    uint32_t u; asm("cvt.rna.tf32.f32 %0, %1;" : "=r"(u) : "f"(f)); return u;
}
__device__ __forceinline__ void mma_tf32(float* c, const uint32_t* a, const uint32_t* b) {
    asm volatile(
        "mma.sync.aligned.m16n8k8.row.col.f32.tf32.tf32.f32 "
        "{%0,%1,%2,%3}, {%4,%5,%6,%7}, {%8,%9}, {%0,%1,%2,%3};"
        : "+f"(c[0]), "+f"(c[1]), "+f"(c[2]), "+f"(c[3])
        : "r"(a[0]), "r"(a[1]), "r"(a[2]), "r"(a[3]), "r"(b[0]), "r"(b[1]));
}
__device__ __forceinline__ void mma_bf16(float* c, const uint32_t* a, const uint32_t* b) {
    asm volatile(
        "mma.sync.aligned.m16n8k16.row.col.f32.bf16.bf16.f32 "
        "{%0,%1,%2,%3}, {%4,%5,%6,%7}, {%8,%9}, {%0,%1,%2,%3};"
        : "+f"(c[0]), "+f"(c[1]), "+f"(c[2]), "+f"(c[3])
        : "r"(a[0]), "r"(a[1]), "r"(a[2]), "r"(a[3]), "r"(b[0]), "r"(b[1]));
}
__device__ __forceinline__ void ldsm_x4(uint32_t* r, uint32_t addr) {
    asm volatile("ldmatrix.sync.aligned.m8n8.x4.shared.b16 {%0,%1,%2,%3}, [%4];"
        : "=r"(r[0]), "=r"(r[1]), "=r"(r[2]), "=r"(r[3]) : "r"(addr));
}
__device__ __forceinline__ void ldsm_x2(uint32_t* r, uint32_t addr) {
    asm volatile("ldmatrix.sync.aligned.m8n8.x2.shared.b16 {%0,%1}, [%2];"
        : "=r"(r[0]), "=r"(r[1]) : "r"(addr));
}
__device__ __forceinline__ uint32_t smem_u32(const void* p) {
    uint32_t a;
    asm("{ .reg .u64 t; cvta.to.shared.u64 t, %1; cvt.u32.u64 %0, t; }" : "=r"(a) : "l"(p));
    return a;
}
__device__ __forceinline__ void cp16(uint32_t dst, const void* src) {
    asm volatile("cp.async.cg.shared.global [%0], [%1], 16;" :: "r"(dst), "l"(src));
}

// ---------------- weight bf16 pre-round ----------------
__global__ void __launch_bounds__(256) round_bf16_kernel(
    const float* __restrict__ src, __nv_bfloat16* __restrict__ dst, int n4)
{
    const int i = blockIdx.x*256 + threadIdx.x;
    if (i < n4) {
        const float4 v = ((const float4*)src)[i];
        __nv_bfloat162 lo = { __float2bfloat16(v.x), __float2bfloat16(v.y) };
        __nv_bfloat162 hi = { __float2bfloat16(v.z), __float2bfloat16(v.w) };
        ((__nv_bfloat162*)dst)[2*i]   = lo;
        ((__nv_bfloat162*)dst)[2*i+1] = hi;
    }
}

// ============================================================
// bf16 mma.sync GEMM: C[m,n] = sum_k A[m,k]*B[n,k]  (A,B bf16; acc fp32)
// cp.async 3-stage pipeline, CTA 128x128, BK=32 elems (16 words),
// 256 thr (8 warps 2x4, warp tile 64x32), LDA=20 words (conflict-free,
// incl. ldmatrix row pattern 80B stride), ldmatrix fragment loads,
// 1 sync/K-iter, 2 CTAs/SM.
// EPI: 0 plain fp32, 1 GELU->bf16, 2 +resid fp32, 3 scatter += fp32
// ============================================================
#define TCG_LDA 20
#define ST_WORDS (128*TCG_LDA)
#define TCG_SMEM (3*2*ST_WORDS*4)         /* 61440 B */

template<int EPI>
__global__ void __launch_bounds__(256, 2) tc_gemm(
    const __nv_bfloat16* __restrict__ A, const __nv_bfloat16* __restrict__ B,
    const float* __restrict__ bias, float* __restrict__ C,
    int K, int Nn,
    const float* __restrict__ resid, const float* __restrict__ wts, int expert,
    const int* __restrict__ aidx, const int* __restrict__ cidx,
    const int* __restrict__ cntp,
    size_t bstride, int bias_stride, size_t cstride)
{
    extern __shared__ uint32_t smu[];
    const int tid = threadIdx.x;
    const int ez = blockIdx.z;
    const int bm = blockIdx.y * 128, bn = blockIdx.x * 128;
    int cnt = 0x7fffffff;
    if (cntp) { cnt = cntp[ez]; if (bm >= ((cnt + 127) & ~127)) return; }
    B    += (size_t)ez * bstride;
    bias += (size_t)ez * bias_stride;
    float* Cf = C + (EPI == 1 ? (size_t)0 : (size_t)ez * cstride);
    __nv_bfloat16* Cb = (__nv_bfloat16*)C + (EPI == 1 ? (size_t)ez * cstride : (size_t)0);
    if (aidx) aidx += ez * TOKENS;

    const int warp = tid >> 5, lane = tid & 31;
    const int wm = (warp >> 2) * 64, wn = (warp & 3) * 32;
    const int g = lane >> 2, t = lane & 3;

    const int lr = tid >> 2, lc = tid & 3;   // staging: row(0..63), 16B-chunk(0..3)
    int ra0 = bm + lr, ra1 = bm + lr + 64;
    if (aidx) { ra0 = aidx[ra0]; ra1 = aidx[ra1]; }
    const __nv_bfloat16* Ag0 = A + (size_t)ra0 * K + lc * 8;
    const __nv_bfloat16* Ag1 = A + (size_t)ra1 * K + lc * 8;
    const __nv_bfloat16* Bg0 = B + (size_t)(bn + lr) * K + lc * 8;
    const __nv_bfloat16* Bg1 = B + (size_t)(bn + lr + 64) * K + lc * 8;

    const uint32_t sbase = smem_u32(smu);
    const uint32_t oa0 = (lr*TCG_LDA + lc*4)*4;
    const uint32_t oa1 = ((lr+64)*TCG_LDA + lc*4)*4;
    const uint32_t obB = ST_WORDS*4;
    // ldmatrix per-lane offsets (bytes).
    // A (.x4): lanes 0-7 rows m0-7 @k-word 0; 8-15 rows m8-15 @0; 16-23 m0-7 @+4; 24-31 m8-15 @+4
    const uint32_t lma = ((wm + (lane & 15))*TCG_LDA + ((lane >> 4) << 2)) * 4;
    // B (.x2): lanes 0-7 rows n0-7 @0; lanes 8-15 rows n0-7 @+4
    const uint32_t lmb = obB + ((wn + (lane & 7))*TCG_LDA + ((lane & 8) ? 4 : 0)) * 4;

    float acc[4][4][4];
    #pragma unroll
    for (int i = 0; i < 4; i++)
        #pragma unroll
        for (int j = 0; j < 4; j++)
            #pragma unroll
            for (int r = 0; r < 4; r++) acc[i][j][r] = 0.f;

    const int NT = K >> 5;                   // BK = 32 bf16 per iter
    #pragma unroll
    for (int s = 0; s < 2; s++) {
        const uint32_t sb = sbase + s*2*ST_WORDS*4;
        const int ko = s*32;
        cp16(sb + oa0, Ag0 + ko); cp16(sb + oa1, Ag1 + ko);
        cp16(sb + obB + oa0, Bg0 + ko); cp16(sb + obB + oa1, Bg1 + ko);
        asm volatile("cp.async.commit_group;");
    }

    int stage = 0;
    for (int kt = 0; kt < NT; kt++) {
        asm volatile("cp.async.wait_group 1;" ::: "memory");
        __syncthreads();
        const uint32_t stb = sbase + stage*2*ST_WORDS*4;

        #pragma unroll
        for (int ks = 0; ks < 2; ks++) {       // each ks = K16 via m16n8k16
            const uint32_t kb4 = (uint32_t)(ks * 8) * 4;   // k-word offset in bytes
            uint32_t af[4][4], bf[4][2];
            #pragma unroll
            for (int mf = 0; mf < 4; mf++)
                ldsm_x4(af[mf], stb + lma + (uint32_t)(mf*16*TCG_LDA)*4 + kb4);
            #pragma unroll
            for (int nf = 0; nf < 4; nf++)
                ldsm_x2(bf[nf], stb + lmb + (uint32_t)(nf*8*TCG_LDA)*4 + kb4);
            #pragma unroll
            for (int mf = 0; mf < 4; mf++)
                #pragma unroll
                for (int nf = 0; nf < 4; nf++)
                    mma_bf16(acc[mf][nf], af[mf], bf[nf]);
        }

        if (kt + 2 < NT) {
            const int ns = (stage + 2 >= 3) ? stage - 1 : stage + 2;
            const int ko = (kt + 2) * 32;
            const uint32_t sb = sbase + ns*2*ST_WORDS*4;
            cp16(sb + oa0, Ag0 + ko); cp16(sb + oa1, Ag1 + ko);
            cp16(sb + obB + oa0, Bg0 + ko); cp16(sb + obB + oa1, Bg1 + ko);
            asm volatile("cp.async.commit_group;");
        } else {
            asm volatile("cp.async.commit_group;");
        }
        stage = (stage + 1 == 3) ? 0 : stage + 1;
    }

    // ---- epilogue ----
    #pragma unroll
    for (int mf = 0; mf < 4; mf++) {
        const int mp0 = bm + wm + mf*16 + g;
        const int mp1 = mp0 + 8;
        if (EPI == 3) {
            const int r0 = cidx[mp0], r1 = cidx[mp1];
            const float w0 = wts[r0*NUM_EXPERTS + expert];
            const float w1 = wts[r1*NUM_EXPERTS + expert];
            const bool ok0 = mp0 < cnt, ok1 = mp1 < cnt;
            #pragma unroll
            for (int nf = 0; nf < 4; nf++) {
                const int n0 = bn + wn + nf*8 + 2*t;
                const float b0 = bias[n0], b1 = bias[n0 + 1];
                const float v0 = acc[mf][nf][0] + b0;
                const float v1 = acc[mf][nf][1] + b1;
                const float v2 = acc[mf][nf][2] + b0;
                const float v3 = acc[mf][nf][3] + b1;
                if (ok0) {
                    const size_t i0 = (size_t)r0 * Nn + n0;
                    Cf[i0]   += v0 * w0;
                    Cf[i0+1] += v1 * w0;
                }
                if (ok1) {
                    const size_t i1 = (size_t)r1 * Nn + n0;
                    Cf[i1]   += v2 * w1;
                    Cf[i1+1] += v3 * w1;
                }
            }
        } else {
            #pragma unroll
            for (int nf = 0; nf < 4; nf++) {
                const int n0 = bn + wn + nf*8 + 2*t;
                const float b0 = bias[n0], b1 = bias[n0 + 1];
                float v0 = acc[mf][nf][0] + b0;
                float v1 = acc[mf][nf][1] + b1;
                float v2 = acc[mf][nf][2] + b0;
                float v3 = acc[mf][nf][3] + b1;
                const size_t i0 = (size_t)mp0 * Nn + n0;
                const size_t i1 = (size_t)mp1 * Nn + n0;
                if (EPI == 0) {
                    Cf[i0] = v0; Cf[i0+1] = v1; Cf[i1] = v2; Cf[i1+1] = v3;
                } else if (EPI == 1) {
                    Cb[i0]   = __float2bfloat16(0.5f*v0*(1.0f + erff(v0*0.70710678118654752f)));
                    Cb[i0+1] = __float2bfloat16(0.5f*v1*(1.0f + erff(v1*0.70710678118654752f)));
                    Cb[i1]   = __float2bfloat16(0.5f*v2*(1.0f + erff(v2*0.70710678118654752f)));
                    Cb[i1+1] = __float2bfloat16(0.5f*v3*(1.0f + erff(v3*0.70710678118654752f)));
                } else {
                    Cf[i0] = v0 + resid[i0]; Cf[i0+1] = v1 + resid[i0+1];
                    Cf[i1] = v2 + resid[i1]; Cf[i1+1] = v3 + resid[i1+1];
                }
            }
        }
    }
}

// ============================================================
// Tensor-core ALiBi flash attention (tf32) — unchanged (R11)
// ============================================================
#define ATT_LDK 68
#define ATT_LDV 69
#define ATT_SMEM ((64*ATT_LDK + 64*ATT_LDV + 64*ATT_LDK)*4)   /* 52480 B */

__global__ void __launch_bounds__(128, 3) attn_tc_kernel()
{
    extern __shared__ uint32_t smA[];
    uint32_t* Ks = smA;
    uint32_t* Vt = smA + 64*ATT_LDK;
    uint32_t* Ps = smA + 64*ATT_LDK + 64*ATT_LDV;
    const int tid = threadIdx.x;
    const int warp = tid >> 5, lane = tid & 31;
    const int g = lane >> 2, t = lane & 3;
    const int bh = blockIdx.x;
    const int b = bh >> 4, h = bh & 15;
    const int q0 = blockIdx.y * 64;
    const float slope = exp2f(-0.5f*(float)(h + 1));

    for (int i = tid; i < 1024; i += 128) {
        const int row = i >> 4, c4 = (i & 15) * 4;
        const float4 qv = *(const float4*)(g_qkv + ((size_t)(b*SEQ + q0 + row))*QKV_LD + h*64 + c4);
        uint32_t* d = Ps + row*ATT_LDK + c4;
        d[0] = f2tf32(qv.x*0.125f); d[1] = f2tf32(qv.y*0.125f);
        d[2] = f2tf32(qv.z*0.125f); d[3] = f2tf32(qv.w*0.125f);
    }
    __syncthreads();
    uint32_t qf[8][4];
    #pragma unroll
    for (int k = 0; k < 8; k++) {
        const uint32_t* base = Ps + (warp*16 + g)*ATT_LDK + k*8 + t;
        qf[k][0] = base[0]; qf[k][1] = base[8*ATT_LDK];
        qf[k][2] = base[4]; qf[k][3] = base[8*ATT_LDK + 4];
    }

    float o[8][4];
    #pragma unroll
    for (int nf = 0; nf < 8; nf++)
        #pragma unroll
        for (int r = 0; r < 4; r++) o[nf][r] = 0.f;
    float l0 = 0.f, l1 = 0.f;
    const int qg0 = q0 + warp*16 + g, qg1 = qg0 + 8;

    for (int kt = 0; kt < 16; kt++) {
        __syncthreads();
        for (int i = tid; i < 1024; i += 128) {
            const int row = i >> 4, c4 = (i & 15) * 4;
            const size_t gofs = ((size_t)(b*SEQ + kt*64 + row))*QKV_LD + h*64 + c4;
            const float4 kv = *(const float4*)(g_qkv + gofs + D_MODEL);
            uint32_t* dk = Ks + row*ATT_LDK + c4;
            dk[0] = f2tf32(kv.x); dk[1] = f2tf32(kv.y);
            dk[2] = f2tf32(kv.z); dk[3] = f2tf32(kv.w);
            const float4 vv = *(const float4*)(g_qkv + gofs + 2*D_MODEL);
            Vt[(c4+0)*ATT_LDV + row] = f2tf32(vv.x);
            Vt[(c4+1)*ATT_LDV + row] = f2tf32(vv.y);
            Vt[(c4+2)*ATT_LDV + row] = f2tf32(vv.z);
            Vt[(c4+3)*ATT_LDV + row] = f2tf32(vv.w);
        }
        __syncthreads();

        float s[8][4];
        #pragma unroll
        for (int nf = 0; nf < 8; nf++)
            #pragma unroll
            for (int r = 0; r < 4; r++) s[nf][r] = 0.f;
        #pragma unroll
        for (int k = 0; k < 8; k++) {
            uint32_t bf[8][2];
            #pragma unroll
            for (int nf = 0; nf < 8; nf++) {
                const uint32_t* base = Ks + (nf*8 + g)*ATT_LDK + k*8 + t;
                bf[nf][0] = base[0]; bf[nf][1] = base[4];
            }
            #pragma unroll
            for (int nf = 0; nf < 8; nf++) mma_tf32(s[nf], qf[k], bf[nf]);
        }

        #pragma unroll
        for (int nf = 0; nf < 8; nf++) {
            const int jg = kt*64 + nf*8 + 2*t;
            const int d00 = jg - qg0, d10 = jg - qg1;
            const float p00 = __expf(s[nf][0] - slope*(float)(d00   > 0 ? d00   : 0));
            const float p01 = __expf(s[nf][1] - slope*(float)(d00+1 > 0 ? d00+1 : 0));
            const float p10 = __expf(s[nf][2] - slope*(float)(d10   > 0 ? d10   : 0));
            const float p11 = __expf(s[nf][3] - slope*(float)(d10+1 > 0 ? d10+1 : 0));
            l0 += p00 + p01; l1 += p10 + p11;
            uint32_t* pr0 = Ps + (warp*16 + g)*ATT_LDK + nf*8 + 2*t;
            pr0[0] = f2tf32(p00); pr0[1] = f2tf32(p01);
            pr0[8*ATT_LDK] = f2tf32(p10); pr0[8*ATT_LDK + 1] = f2tf32(p11);
        }
        __syncwarp();

        #pragma unroll
        for (int k = 0; k < 8; k++) {
            uint32_t pf[4];
            const uint32_t* pb = Ps + (warp*16 + g)*ATT_LDK + k*8 + t;
            pf[0] = pb[0]; pf[1] = pb[8*ATT_LDK];
            pf[2] = pb[4]; pf[3] = pb[8*ATT_LDK + 4];
            #pragma unroll
            for (int nf = 0; nf < 8; nf++) {
                const uint32_t* vb = Vt + (nf*8 + g)*ATT_LDV + k*8 + t;
                uint32_t bf[2] = { vb[0], vb[4] };
                mma_tf32(o[nf], pf, bf);
            }
        }
    }

    l0 += __shfl_xor_sync(0xffffffffu, l0, 1);
    l0 += __shfl_xor_sync(0xffffffffu, l0, 2);
    l1 += __shfl_xor_sync(0xffffffffu, l1, 1);
    l1 += __shfl_xor_sync(0xffffffffu, l1, 2);
    const float inv0 = 1.f/l0, inv1 = 1.f/l1;
    __nv_bfloat16* y0 = g_yh + ((size_t)(b*SEQ + qg0))*D_MODEL + h*64;
    __nv_bfloat16* y1 = g_yh + ((size_t)(b*SEQ + qg1))*D_MODEL + h*64;
    #pragma unroll
    for (int nf = 0; nf < 8; nf++) {
        const int c = nf*8 + 2*t;
        y0[c]   = __float2bfloat16(o[nf][0]*inv0);
        y0[c+1] = __float2bfloat16(o[nf][1]*inv0);
        y1[c]   = __float2bfloat16(o[nf][2]*inv1);
        y1[c+1] = __float2bfloat16(o[nf][3]*inv1);
    }
}

// ---------------- Decomp1D ----------------
#define DC_NT 128
#define DC_DT 32
#define DC_HALO 24
__global__ void __launch_bounds__(256) decomp_kernel(
    const float* __restrict__ x, const float* __restrict__ alpha,
    const float* __restrict__ dw7, const float* __restrict__ dw25,
    const float* __restrict__ dw49)
{
    __shared__ float sx[DC_NT + 2*DC_HALO][DC_DT];
    __shared__ float sw7[DC_DT][7];
    __shared__ float sw25[DC_DT][25];
    __shared__ float sw49[DC_DT][49];
    const int b  = blockIdx.z;
    const int n0 = blockIdx.y * DC_NT;
    const int d0 = blockIdx.x * DC_DT;
    const int tid = threadIdx.x;

    for (int i = tid; i < DC_DT*7;  i += 256) sw7 [i/7 ][i%7 ] = dw7 [(d0 + i/7 )*7  + i%7 ];
    for (int i = tid; i < DC_DT*25; i += 256) sw25[i/25][i%25] = dw25[(d0 + i/25)*25 + i%25];
    for (int i = tid; i < DC_DT*49; i += 256) sw49[i/49][i%49] = dw49[(d0 + i/49)*49 + i%49];

    for (int i = tid; i < (DC_NT + 2*DC_HALO)*DC_DT; i += 256) {
        int r = i / DC_DT, c = i % DC_DT;
        int n = n0 + r - DC_HALO;
        if (n < 0)    n = -n;
        if (n >= SEQ) n = 2*SEQ - 2 - n;
        sx[r][c] = x[((size_t)b*SEQ + n)*D_MODEL + d0 + c];
    }
    __syncthreads();

    const float a0 = alpha[0], a1 = alpha[1], a2 = alpha[2];
    const float mx = fmaxf(a0, fmaxf(a1, a2));
    const float e0 = __expf(a0-mx), e1 = __expf(a1-mx), e2 = __expf(a2-mx);
    const float inv = 1.f/(e0+e1+e2);
    const float w0 = e0*inv, w1 = e1*inv, w2 = e2*inv;

    for (int i = tid; i < DC_NT*DC_DT; i += 256) {
        const int p = i / DC_DT, c = i % DC_DT;
        float t7 = 0.f, t25 = 0.f, t49 = 0.f;
        #pragma unroll
        for (int j = 0; j < 7;  j++) t7  = fmaf(sx[p + DC_HALO - 3  + j][c], sw7 [c][j], t7 );
        #pragma unroll
        for (int j = 0; j < 25; j++) t25 = fmaf(sx[p + DC_HALO - 12 + j][c], sw25[c][j], t25);
        #pragma unroll
        for (int j = 0; j < 49; j++) t49 = fmaf(sx[p + j][c],                sw49[c][j], t49);
        const float tr = w0*t7 + w1*t25 + w2*t49;
        const size_t idx = ((size_t)b*SEQ + n0 + p)*D_MODEL + d0 + c;
        g_Tr[idx] = tr;
        g_S[idx]  = sx[p + DC_HALO][c] - tr;
    }
}

// ---------------- LayerNorm: bf16 out (GEMM A) + optional fp32 out (router) ----------------
__global__ void __launch_bounds__(256) ln_kernel(
    const float* __restrict__ in, const float* __restrict__ gam,
    const float* __restrict__ bet, __nv_bfloat16* __restrict__ outh,
    float* __restrict__ outf)
{
    __shared__ float row[D_MODEL];
    __shared__ float red[256];
    const int t = blockIdx.x, tid = threadIdx.x;
    const float* ip = in + (size_t)t*D_MODEL;
    float s = 0.f;
    for (int d = tid; d < D_MODEL; d += 256) { float v = ip[d]; row[d] = v; s += v; }
    red[tid] = s; __syncthreads();
    for (int o = 128; o > 0; o >>= 1) { if (tid < o) red[tid] += red[tid+o]; __syncthreads(); }
    const float mean = red[0] * (1.f/D_MODEL);
    __syncthreads();
    float vs = 0.f;
    for (int d = tid; d < D_MODEL; d += 256) { float dv = row[d]-mean; vs += dv*dv; }
    red[tid] = vs; __syncthreads();
    for (int o = 128; o > 0; o >>= 1) { if (tid < o) red[tid] += red[tid+o]; __syncthreads(); }
    const float rstd = rsqrtf(red[0] * (1.f/D_MODEL) + LN_EPS);
    for (int d = tid; d < D_MODEL; d += 256) {
        const float v = (row[d]-mean)*rstd*gam[d] + bet[d];
        outh[(size_t)t*D_MODEL + d] = __float2bfloat16(v);
        if (outf) outf[(size_t)t*D_MODEL + d] = v;
    }
}

// ---------------- Router (fp32 xf) ----------------
__global__ void __launch_bounds__(256) router_kernel(
    const float* __restrict__ xf, const float* __restrict__ rw)
{
    const int warp = threadIdx.x / 32, lane = threadIdx.x % 32;
    const int t = blockIdx.x*8 + warp;
    const float* xp = xf + (size_t)t*D_MODEL;
    float logit[NUM_EXPERTS];
    #pragma unroll
    for (int e = 0; e < NUM_EXPERTS; e++) {
        float p = 0.f;
        for (int d = lane; d < D_MODEL; d += 32) p = fmaf(xp[d], rw[e*D_MODEL + d], p);
        #pragma unroll
        for (int o = 16; o > 0; o >>= 1) p += __shfl_xor_sync(0xffffffffu, p, o);
        logit[e] = p;
    }
    if (lane == 0) {
        float mx = logit[0];
        #pragma unroll
        for (int e = 1; e < NUM_EXPERTS; e++) mx = fmaxf(mx, logit[e]);
        float g[NUM_EXPERTS]; float s = 0.f;
        #pragma unroll
        for (int e = 0; e < NUM_EXPERTS; e++) { g[e] = expf(logit[e]-mx); s += g[e]; }
        #pragma unroll
        for (int e = 0; e < NUM_EXPERTS; e++) g[e] /= s;
        int i0 = 0;
        #pragma unroll
        for (int e = 1; e < NUM_EXPERTS; e++) if (g[e] > g[i0]) i0 = e;
        int i1 = -1;
        #pragma unroll
        for (int e = 0; e < NUM_EXPERTS; e++)
            if (e != i0 && (i1 < 0 || g[e] > g[i1])) i1 = e;
        const float s2 = fmaxf(g[i0] + g[i1], 1e-9f);
        float w[NUM_EXPERTS] = {0.f, 0.f, 0.f, 0.f};
        w[i0] = g[i0]/s2; w[i1] = g[i1]/s2;
        #pragma unroll
        for (int e = 0; e < NUM_EXPERTS; e++) {
            g_gates[t*NUM_EXPERTS + e] = g[e];
            g_w[t*NUM_EXPERTS + e]     = w[e];
        }
    }
}

// ---------------- routing lists ----------------
__global__ void __launch_bounds__(128) route_kernel()
{
    const int e = threadIdx.x >> 5, lane = threadIdx.x & 31;
    int cnt = 0;
    for (int base = 0; base < TOKENS; base += 32) {
        const int t = base + lane;
        const bool sel = g_w[t*NUM_EXPERTS + e] > 0.f;
        const unsigned m = __ballot_sync(0xffffffffu, sel);
        if (sel) g_elist[e*TOKENS + cnt + __popc(m & ((1u << lane) - 1u))] = t;
        cnt += __popc(m);
    }
    __syncwarp();
    const int padded = (cnt + 127) & ~127;
    if (cnt > 0) {
        const int last = g_elist[e*TOKENS + cnt - 1];
        for (int i = cnt + lane; i < padded; i += 32) g_elist[e*TOKENS + i] = last;
    }
    if (lane == 0) g_ecnt[e] = cnt;
}

// ---------------- aux ----------------
__global__ void __launch_bounds__(256) aux_kernel(float* __restrict__ out, int out_size)
{
    __shared__ float rg[NUM_EXPERTS][256];
    __shared__ float rc[NUM_EXPERTS][256];
    const int tid = threadIdx.x;
    float gs[NUM_EXPERTS] = {0,0,0,0}, cs[NUM_EXPERTS] = {0,0,0,0};
    for (int t = tid; t < TOKENS; t += 256) {
        #pragma unroll
        for (int e = 0; e < NUM_EXPERTS; e++) {
            gs[e] += g_gates[t*NUM_EXPERTS + e];
            cs[e] += (g_w[t*NUM_EXPERTS + e] > 0.f) ? 1.f : 0.f;
        }
    }
    #pragma unroll
    for (int e = 0; e < NUM_EXPERTS; e++) { rg[e][tid] = gs[e]; rc[e][tid] = cs[e]; }
    __syncthreads();
    for (int o = 128; o > 0; o >>= 1) {
        if (tid < o)
            #pragma unroll
            for (int e = 0; e < NUM_EXPERTS; e++) { rg[e][tid] += rg[e][tid+o]; rc[e][tid] += rc[e][tid+o]; }
        __syncthreads();
    }
    if (tid == 0 && out_size > BND) {
        float aux = 0.f;
        #pragma unroll
        for (int e = 0; e < NUM_EXPERTS; e++)
            aux += (rg[e][0]*(1.f/TOKENS)) * (rc[e][0]*(1.f/TOKENS));
        out[out_size - 1] = (float)NUM_EXPERTS * aux;
    }
}

// ---------------- final ----------------
__global__ void __launch_bounds__(256) final_kernel(
    const float* __restrict__ tw, const float* __restrict__ tb, float* __restrict__ out)
{
    const size_t gid = (size_t)blockIdx.x*256 + threadIdx.x;
    if (gid >= (size_t)BND) return;
    const int d = (int)(gid % D_MODEL);
    const int n = (int)((gid / D_MODEL) % SEQ);
    float t = 0.f;
    #pragma unroll
    for (int j = 0; j < 5; j++) {
        const int nn = n - 2 + j;
        if (nn >= 0 && nn < SEQ)
            t = fmaf(g_Tr[gid + (size_t)(j-2)*D_MODEL], tw[d*5 + j], t);
    }
    out[gid] = g_xs[gid] + t + tb[d];
}

// ---------------- launch ----------------
static void* sym_addr(const void* sym) {
    void* p = nullptr;
    cudaGetSymbolAddress(&p, sym);
    return p;
}

extern "C" void kernel_launch(void* const* d_in, const int* in_sizes, int n_in,
                              void* d_out, int out_size)
{
    const float* x    = (const float*)d_in[0];
    const float* qw   = (const float*)d_in[1];  const float* qb  = (const float*)d_in[2];
    const float* kw   = (const float*)d_in[3];  const float* kb  = (const float*)d_in[4];
    const float* vw   = (const float*)d_in[5];  const float* vb  = (const float*)d_in[6];
    const float* ow   = (const float*)d_in[7];  const float* ob  = (const float*)d_in[8];
    const float* n1g  = (const float*)d_in[9];  const float* n1b = (const float*)d_in[10];
    const float* n2g  = (const float*)d_in[11]; const float* n2b = (const float*)d_in[12];
    const float* alpha= (const float*)d_in[13];
    const float* dw7  = (const float*)d_in[14];
    const float* dw25 = (const float*)d_in[15];
    const float* dw49 = (const float*)d_in[16];
    const float* rw   = (const float*)d_in[17];
    const float* ew1  = (const float*)d_in[18]; const float* eb1 = (const float*)d_in[19];
    const float* ew2  = (const float*)d_in[20]; const float* eb2 = (const float*)d_in[21];
    const float* tw   = (const float*)d_in[22]; const float* tb  = (const float*)d_in[23];
    float* out = (float*)d_out;

    float* pS   = (float*)sym_addr(g_S);
    float* pBuf = (float*)sym_addr(g_buf);
    __nv_bfloat16* pBufH = (__nv_bfloat16*)sym_addr(g_bufh);
    float* pQKV = (float*)sym_addr(g_qkv);
    __nv_bfloat16* pYH = (__nv_bfloat16*)sym_addr(g_yh);
    float* pXs  = (float*)sym_addr(g_xs);
    __nv_bfloat16* pHH = (__nv_bfloat16*)sym_addr(g_hh);
    float* pW   = (float*)sym_addr(g_w);
    int*   pEL  = (int*)sym_addr(g_elist);
    int*   pEC  = (int*)sym_addr(g_ecnt);
    __nv_bfloat16* pRW4 = (__nv_bfloat16*)sym_addr(g_rw4h);
    __nv_bfloat16* pRE1 = (__nv_bfloat16*)sym_addr(g_rew1h);
    __nv_bfloat16* pRE2 = (__nv_bfloat16*)sym_addr(g_rew2h);
    float* pQKVB= (float*)sym_addr(g_qkvb);
    (void)in_sizes; (void)n_in;

    cudaFuncSetAttribute(attn_tc_kernel, cudaFuncAttributeMaxDynamicSharedMemorySize, ATT_SMEM);
    cudaFuncSetAttribute(tc_gemm<0>, cudaFuncAttributeMaxDynamicSharedMemorySize, TCG_SMEM);
    cudaFuncSetAttribute(tc_gemm<1>, cudaFuncAttributeMaxDynamicSharedMemorySize, TCG_SMEM);
    cudaFuncSetAttribute(tc_gemm<2>, cudaFuncAttributeMaxDynamicSharedMemorySize, TCG_SMEM);
    cudaFuncSetAttribute(tc_gemm<3>, cudaFuncAttributeMaxDynamicSharedMemorySize, TCG_SMEM);

    // 0) pre-round weights to bf16 + concat qkv bias
    const int DD4 = D_MODEL*D_MODEL/4;
    const int E14 = NUM_EXPERTS*MOE_HIDDEN*D_MODEL/4;
    const int E24 = NUM_EXPERTS*D_MODEL*MOE_HIDDEN/4;
    round_bf16_kernel<<<(DD4+255)/256, 256>>>(qw, pRW4 + 0*D_MODEL*D_MODEL, DD4);
    round_bf16_kernel<<<(DD4+255)/256, 256>>>(kw, pRW4 + 1*D_MODEL*D_MODEL, DD4);
    round_bf16_kernel<<<(DD4+255)/256, 256>>>(vw, pRW4 + 2*D_MODEL*D_MODEL, DD4);
    round_bf16_kernel<<<(DD4+255)/256, 256>>>(ow, pRW4 + 3*D_MODEL*D_MODEL, DD4);
    round_bf16_kernel<<<(E14+255)/256, 256>>>(ew1, pRE1, E14);
    round_bf16_kernel<<<(E24+255)/256, 256>>>(ew2, pRE2, E24);
    cudaMemcpyAsync(pQKVB,            qb, D_MODEL*4, cudaMemcpyDeviceToDevice);
    cudaMemcpyAsync(pQKVB + D_MODEL,  kb, D_MODEL*4, cudaMemcpyDeviceToDevice);
    cudaMemcpyAsync(pQKVB + 2*D_MODEL,vb, D_MODEL*4, cudaMemcpyDeviceToDevice);

    // 1) decomposition -> g_Tr, g_S
    dim3 dgrid(D_MODEL/DC_DT, SEQ/DC_NT, BATCH);
    decomp_kernel<<<dgrid, 256>>>(x, alpha, dw7, dw25, dw49);

    // 2) LN1(S) -> bf16 Sn
    ln_kernel<<<TOKENS, 256>>>(pS, n1g, n1b, pBufH, nullptr);

    // 3) fused QKV projection: one bf16 GEMM, N=3072
    dim3 gq(QKV_LD/128, TOKENS/128, 1);
    tc_gemm<0><<<gq, 256, TCG_SMEM>>>(pBufH, pRW4, pQKVB, pQKV, D_MODEL, QKV_LD,
                                      nullptr, nullptr, 0, nullptr, nullptr, nullptr,
                                      0, 0, 0);

    // 4) attention (tf32), y -> bf16
    dim3 agrid(BATCH*NHEAD, SEQ/64);
    attn_tc_kernel<<<agrid, 128, ATT_SMEM>>>();

    // 5) O projection + residual S -> g_xs
    dim3 go(D_MODEL/128, TOKENS/128, 1);
    tc_gemm<2><<<go, 256, TCG_SMEM>>>(pYH, pRW4 + (size_t)3*D_MODEL*D_MODEL, ob, pXs,
                                      D_MODEL, D_MODEL,
                                      pS, nullptr, 0, nullptr, nullptr, nullptr,
                                      0, 0, 0);

    // 6) LN2 -> bf16 xf (GEMM) + fp32 xf (router)
    ln_kernel<<<TOKENS, 256>>>(pXs, n2g, n2b, pBufH, pBuf);

    // 7) router (fp32 xf) + routing lists + aux
    router_kernel<<<TOKENS/8, 256>>>(pBuf, rw);
    route_kernel<<<1, 128>>>();
    aux_kernel<<<1, 256>>>(out, out_size);

    // 8) MoE FFN: fused bf16 GEMM1 over all experts (blockIdx.z = expert)
    dim3 gh1(MOE_HIDDEN/128, TOKENS/128, NUM_EXPERTS);
    tc_gemm<1><<<gh1, 256, TCG_SMEM>>>(pBufH, pRE1, eb1, (float*)pHH,
                                       D_MODEL, MOE_HIDDEN,
                                       nullptr, nullptr, 0,
                                       pEL, nullptr, pEC,
                                       (size_t)MOE_HIDDEN*D_MODEL, MOE_HIDDEN,
                                       (size_t)TOKENS*MOE_HIDDEN);
    // GEMM2: per-expert scatter-accumulate (serialized for determinism)
    dim3 gh2(D_MODEL/128, TOKENS/128, 1);
    for (int e = 0; e < NUM_EXPERTS; e++) {
        tc_gemm<3><<<gh2, 256, TCG_SMEM>>>(pHH + (size_t)e*TOKENS*MOE_HIDDEN,
                                           pRE2 + (size_t)e*D_MODEL*MOE_HIDDEN,
                                           eb2 + (size_t)e*D_MODEL, pXs,
                                           MOE_HIDDEN, D_MODEL,
                                           nullptr, pW, e,
                                           nullptr, pEL + e*TOKENS, pEC + e,
                                           0, 0, 0);
    }

    // 9) final
    final_kernel<<<(BND + 255)/256, 256>>>(tw, tb, out);
}

// round 15
// speedup vs baseline: 2.6673x; 1.0239x over previous
#include <cuda_runtime.h>
#include <cuda_bf16.h>
#include <math.h>
#include <stdint.h>

#define D_MODEL 1024
#define NHEAD 16
#define HEAD_DIM 64
#define MOE_HIDDEN 2048
#define NUM_EXPERTS 4
#define BATCH 8
#define SEQ 1024
#define TOKENS (BATCH*SEQ)          /* 8192  */
#define BND (TOKENS*D_MODEL)        /* 8388608 */
#define QKV_LD (3*D_MODEL)
#define LN_EPS 1e-5f

// ---------------- scratch (device globals; no allocation) ----------------
__device__ float g_Tr[BND];
__device__ float g_S[BND];
__device__ float g_buf[BND];                    // LN2 fp32 (router)
__device__ __nv_bfloat16 g_bufh[BND];           // LN bf16 (GEMM A)
__device__ float g_qkv[TOKENS*QKV_LD];          // packed q|k|v per token (fp32)
__device__ __nv_bfloat16 g_yh[BND];             // attention out, bf16 (O-proj A)
__device__ float g_xs[BND];
__device__ __nv_bfloat16 g_hh[NUM_EXPERTS*TOKENS*MOE_HIDDEN];  // per-expert hidden (bf16)
__device__ float g_w[TOKENS*NUM_EXPERTS];
__device__ float g_gates[TOKENS*NUM_EXPERTS];
__device__ int   g_elist[NUM_EXPERTS*TOKENS];
__device__ int   g_ecnt[NUM_EXPERTS];
__device__ float g_qkvb[QKV_LD];                // concat qb|kb|vb (fp32)
// bf16-pre-rounded weights
__device__ __nv_bfloat16 g_rw4h[4*D_MODEL*D_MODEL];       // qw,kw,vw,ow (contiguous)
__device__ __nv_bfloat16 g_rew1h[NUM_EXPERTS*MOE_HIDDEN*D_MODEL];
__device__ __nv_bfloat16 g_rew2h[NUM_EXPERTS*D_MODEL*MOE_HIDDEN];

// ============================================================
// helpers
// ============================================================
__device__ __forceinline__ uint32_t f2tf32(float f) {
    uint32_t u; asm("cvt.rna.tf32.f32 %0, %1;" : "=r"(u) : "f"(f)); return u;
}
__device__ __forceinline__ void mma_tf32(float* c, const uint32_t* a, const uint32_t* b) {
    asm volatile(
        "mma.sync.aligned.m16n8k8.row.col.f32.tf32.tf32.f32 "
        "{%0,%1,%2,%3}, {%4,%5,%6,%7}, {%8,%9}, {%0,%1,%2,%3};"
        : "+f"(c[0]), "+f"(c[1]), "+f"(c[2]), "+f"(c[3])
        : "r"(a[0]), "r"(a[1]), "r"(a[2]), "r"(a[3]), "r"(b[0]), "r"(b[1]));
}
__device__ __forceinline__ void mma_bf16(float* c, const uint32_t* a, const uint32_t* b) {
    asm volatile(
        "mma.sync.aligned.m16n8k16.row.col.f32.bf16.bf16.f32 "
        "{%0,%1,%2,%3}, {%4,%5,%6,%7}, {%8,%9}, {%0,%1,%2,%3};"
        : "+f"(c[0]), "+f"(c[1]), "+f"(c[2]), "+f"(c[3])
        : "r"(a[0]), "r"(a[1]), "r"(a[2]), "r"(a[3]), "r"(b[0]), "r"(b[1]));
}
__device__ __forceinline__ void ldsm_x4(uint32_t* r, uint32_t addr) {
    asm volatile("ldmatrix.sync.aligned.m8n8.x4.shared.b16 {%0,%1,%2,%3}, [%4];"
        : "=r"(r[0]), "=r"(r[1]), "=r"(r[2]), "=r"(r[3]) : "r"(addr));
}
__device__ __forceinline__ void ldsm_x2(uint32_t* r, uint32_t addr) {
    asm volatile("ldmatrix.sync.aligned.m8n8.x2.shared.b16 {%0,%1}, [%2];"
        : "=r"(r[0]), "=r"(r[1]) : "r"(addr));
}
__device__ __forceinline__ uint32_t smem_u32(const void* p) {
    uint32_t a;
    asm("{ .reg .u64 t; cvta.to.shared.u64 t, %1; cvt.u32.u64 %0, t; }" : "=r"(a) : "l"(p));
    return a;
}
__device__ __forceinline__ void cp16(uint32_t dst, const void* src) {
    asm volatile("cp.async.cg.shared.global [%0], [%1], 16;" :: "r"(dst), "l"(src));
}

// ---------------- weight bf16 pre-round ----------------
__global__ void __launch_bounds__(256) round_bf16_kernel(
    const float* __restrict__ src, __nv_bfloat16* __restrict__ dst, int n4)
{
    const int i = blockIdx.x*256 + threadIdx.x;
    if (i < n4) {
        const float4 v = ((const float4*)src)[i];
        __nv_bfloat162 lo = { __float2bfloat16(v.x), __float2bfloat16(v.y) };
        __nv_bfloat162 hi = { __float2bfloat16(v.z), __float2bfloat16(v.w) };
        ((__nv_bfloat162*)dst)[2*i]   = lo;
        ((__nv_bfloat162*)dst)[2*i+1] = hi;
    }
}

// ============================================================
// bf16 mma.sync GEMM: C[m,n] = sum_k A[m,k]*B[n,k]  (A,B bf16; acc fp32)
// cp.async 3-stage pipeline, CTA 128x128, BK=64 elems (32 words),
// 256 thr (8 warps 2x4, warp tile 64x32), LDA=36 words (144B rows,
// ldmatrix conflict-free), 1 sync per 64-K, 2 CTAs/SM.
// EPI: 0 plain fp32, 1 GELU->bf16, 2 +resid fp32, 3 scatter += fp32
// ============================================================
#define TCG_LDA 36
#define ST_WORDS (128*TCG_LDA)            /* 4608 words per matrix per stage */
#define TCG_SMEM (3*2*ST_WORDS*4)         /* 110592 B */

template<int EPI>
__global__ void __launch_bounds__(256, 2) tc_gemm(
    const __nv_bfloat16* __restrict__ A, const __nv_bfloat16* __restrict__ B,
    const float* __restrict__ bias, float* __restrict__ C,
    int K, int Nn,
    const float* __restrict__ resid, const float* __restrict__ wts, int expert,
    const int* __restrict__ aidx, const int* __restrict__ cidx,
    const int* __restrict__ cntp,
    size_t bstride, int bias_stride, size_t cstride)
{
    extern __shared__ uint32_t smu[];
    const int tid = threadIdx.x;
    const int ez = blockIdx.z;
    const int bm = blockIdx.y * 128, bn = blockIdx.x * 128;
    int cnt = 0x7fffffff;
    if (cntp) { cnt = cntp[ez]; if (bm >= ((cnt + 127) & ~127)) return; }
    B    += (size_t)ez * bstride;
    bias += (size_t)ez * bias_stride;
    float* Cf = C + (EPI == 1 ? (size_t)0 : (size_t)ez * cstride);
    __nv_bfloat16* Cb = (__nv_bfloat16*)C + (EPI == 1 ? (size_t)ez * cstride : (size_t)0);
    if (aidx) aidx += ez * TOKENS;

    const int warp = tid >> 5, lane = tid & 31;
    const int wm = (warp >> 2) * 64, wn = (warp & 3) * 32;
    const int g = lane >> 2, t = lane & 3;

    // staging: 128 rows x 8 chunks(16B) per matrix per stage; 4 (row,chunk) pairs/thread
    const int lr8 = tid >> 3;            // base row 0..31
    const int lc8 = tid & 7;             // 16B chunk 0..7
    const __nv_bfloat16* AgP[4];
    const __nv_bfloat16* BgP[4];
    uint32_t oaS[4];
    #pragma unroll
    for (int j = 0; j < 4; j++) {
        const int row = lr8 + 32*j;
        int ra = bm + row;
        if (aidx) ra = aidx[ra];
        AgP[j] = A + (size_t)ra * K + lc8 * 8;
        BgP[j] = B + (size_t)(bn + row) * K + lc8 * 8;
        oaS[j] = (uint32_t)(row*TCG_LDA + lc8*4)*4;
    }

    const uint32_t sbase = smem_u32(smu);
    const uint32_t obB = ST_WORDS*4;
    // ldmatrix per-lane offsets (bytes), rows stride 144B -> conflict-free
    const uint32_t lma = ((wm + (lane & 15))*TCG_LDA + ((lane >> 4) << 2)) * 4;
    const uint32_t lmb = obB + ((wn + (lane & 7))*TCG_LDA + ((lane & 8) ? 4 : 0)) * 4;

    float acc[4][4][4];
    #pragma unroll
    for (int i = 0; i < 4; i++)
        #pragma unroll
        for (int j = 0; j < 4; j++)
            #pragma unroll
            for (int r = 0; r < 4; r++) acc[i][j][r] = 0.f;

    const int NT = K >> 6;                   // BK = 64 bf16 per iter
    #pragma unroll
    for (int s = 0; s < 2; s++) {
        const uint32_t sb = sbase + s*2*ST_WORDS*4;
        const int ko = s*64;
        #pragma unroll
        for (int j = 0; j < 4; j++) {
            cp16(sb + oaS[j], AgP[j] + ko);
            cp16(sb + obB + oaS[j], BgP[j] + ko);
        }
        asm volatile("cp.async.commit_group;");
    }

    int stage = 0;
    for (int kt = 0; kt < NT; kt++) {
        asm volatile("cp.async.wait_group 1;" ::: "memory");
        __syncthreads();
        const uint32_t stb = sbase + stage*2*ST_WORDS*4;

        #pragma unroll
        for (int ks = 0; ks < 4; ks++) {       // each ks = K16 via m16n8k16
            const uint32_t kb4 = (uint32_t)ks * 32;   // 8 k-words = 32 bytes
            uint32_t af[4][4], bf[4][2];
            #pragma unroll
            for (int mf = 0; mf < 4; mf++)
                ldsm_x4(af[mf], stb + lma + (uint32_t)(mf*16*TCG_LDA)*4 + kb4);
            #pragma unroll
            for (int nf = 0; nf < 4; nf++)
                ldsm_x2(bf[nf], stb + lmb + (uint32_t)(nf*8*TCG_LDA)*4 + kb4);
            #pragma unroll
            for (int mf = 0; mf < 4; mf++)
                #pragma unroll
                for (int nf = 0; nf < 4; nf++)
                    mma_bf16(acc[mf][nf], af[mf], bf[nf]);
        }

        if (kt + 2 < NT) {
            const int ns = (stage + 2 >= 3) ? stage - 1 : stage + 2;
            const int ko = (kt + 2) * 64;
            const uint32_t sb = sbase + ns*2*ST_WORDS*4;
            #pragma unroll
            for (int j = 0; j < 4; j++) {
                cp16(sb + oaS[j], AgP[j] + ko);
                cp16(sb + obB + oaS[j], BgP[j] + ko);
            }
            asm volatile("cp.async.commit_group;");
        } else {
            asm volatile("cp.async.commit_group;");
        }
        stage = (stage + 1 == 3) ? 0 : stage + 1;
    }

    // ---- epilogue ----
    #pragma unroll
    for (int mf = 0; mf < 4; mf++) {
        const int mp0 = bm + wm + mf*16 + g;
        const int mp1 = mp0 + 8;
        if (EPI == 3) {
            const int r0 = cidx[mp0], r1 = cidx[mp1];
            const float w0 = wts[r0*NUM_EXPERTS + expert];
            const float w1 = wts[r1*NUM_EXPERTS + expert];
            const bool ok0 = mp0 < cnt, ok1 = mp1 < cnt;
            #pragma unroll
            for (int nf = 0; nf < 4; nf++) {
                const int n0 = bn + wn + nf*8 + 2*t;
                const float b0 = bias[n0], b1 = bias[n0 + 1];
                const float v0 = acc[mf][nf][0] + b0;
                const float v1 = acc[mf][nf][1] + b1;
                const float v2 = acc[mf][nf][2] + b0;
                const float v3 = acc[mf][nf][3] + b1;
                if (ok0) {
                    const size_t i0 = (size_t)r0 * Nn + n0;
                    Cf[i0]   += v0 * w0;
                    Cf[i0+1] += v1 * w0;
                }
                if (ok1) {
                    const size_t i1 = (size_t)r1 * Nn + n0;
                    Cf[i1]   += v2 * w1;
                    Cf[i1+1] += v3 * w1;
                }
            }
        } else {
            #pragma unroll
            for (int nf = 0; nf < 4; nf++) {
                const int n0 = bn + wn + nf*8 + 2*t;
                const float b0 = bias[n0], b1 = bias[n0 + 1];
                float v0 = acc[mf][nf][0] + b0;
                float v1 = acc[mf][nf][1] + b1;
                float v2 = acc[mf][nf][2] + b0;
                float v3 = acc[mf][nf][3] + b1;
                const size_t i0 = (size_t)mp0 * Nn + n0;
                const size_t i1 = (size_t)mp1 * Nn + n0;
                if (EPI == 0) {
                    Cf[i0] = v0; Cf[i0+1] = v1; Cf[i1] = v2; Cf[i1+1] = v3;
                } else if (EPI == 1) {
                    Cb[i0]   = __float2bfloat16(0.5f*v0*(1.0f + erff(v0*0.70710678118654752f)));
                    Cb[i0+1] = __float2bfloat16(0.5f*v1*(1.0f + erff(v1*0.70710678118654752f)));
                    Cb[i1]   = __float2bfloat16(0.5f*v2*(1.0f + erff(v2*0.70710678118654752f)));
                    Cb[i1+1] = __float2bfloat16(0.5f*v3*(1.0f + erff(v3*0.70710678118654752f)));
                } else {
                    Cf[i0] = v0 + resid[i0]; Cf[i0+1] = v1 + resid[i0+1];
                    Cf[i1] = v2 + resid[i1]; Cf[i1+1] = v3 + resid[i1+1];
                }
            }
        }
    }
}

// ============================================================
// Tensor-core ALiBi flash attention (tf32) — q-tile 128 (8 warps).
// Halves K/V L2 re-reads vs q-tile 64; per-warp math bit-identical.
// ============================================================
#define ATT_LDK 68
#define ATT_LDV 69
#define ATT_SMEM ((64*ATT_LDK + 64*ATT_LDV + 128*ATT_LDK)*4)   /* 69888 B */

__global__ void __launch_bounds__(256, 2) attn_tc_kernel()
{
    extern __shared__ uint32_t smA[];
    uint32_t* Ks = smA;
    uint32_t* Vt = smA + 64*ATT_LDK;
    uint32_t* Ps = smA + 64*ATT_LDK + 64*ATT_LDV;     // 128 rows
    const int tid = threadIdx.x;
    const int warp = tid >> 5, lane = tid & 31;
    const int g = lane >> 2, t = lane & 3;
    const int bh = blockIdx.x;
    const int b = bh >> 4, h = bh & 15;
    const int q0 = blockIdx.y * 128;
    const float slope = exp2f(-0.5f*(float)(h + 1));

    for (int i = tid; i < 2048; i += 256) {
        const int row = i >> 4, c4 = (i & 15) * 4;
        const float4 qv = *(const float4*)(g_qkv + ((size_t)(b*SEQ + q0 + row))*QKV_LD + h*64 + c4);
        uint32_t* d = Ps + row*ATT_LDK + c4;
        d[0] = f2tf32(qv.x*0.125f); d[1] = f2tf32(qv.y*0.125f);
        d[2] = f2tf32(qv.z*0.125f); d[3] = f2tf32(qv.w*0.125f);
    }
    __syncthreads();
    uint32_t qf[8][4];
    #pragma unroll
    for (int k = 0; k < 8; k++) {
        const uint32_t* base = Ps + (warp*16 + g)*ATT_LDK + k*8 + t;
        qf[k][0] = base[0]; qf[k][1] = base[8*ATT_LDK];
        qf[k][2] = base[4]; qf[k][3] = base[8*ATT_LDK + 4];
    }

    float o[8][4];
    #pragma unroll
    for (int nf = 0; nf < 8; nf++)
        #pragma unroll
        for (int r = 0; r < 4; r++) o[nf][r] = 0.f;
    float l0 = 0.f, l1 = 0.f;
    const int qg0 = q0 + warp*16 + g, qg1 = qg0 + 8;

    for (int kt = 0; kt < 16; kt++) {
        __syncthreads();
        for (int i = tid; i < 1024; i += 256) {
            const int row = i >> 4, c4 = (i & 15) * 4;
            const size_t gofs = ((size_t)(b*SEQ + kt*64 + row))*QKV_LD + h*64 + c4;
            const float4 kv = *(const float4*)(g_qkv + gofs + D_MODEL);
            uint32_t* dk = Ks + row*ATT_LDK + c4;
            dk[0] = f2tf32(kv.x); dk[1] = f2tf32(kv.y);
            dk[2] = f2tf32(kv.z); dk[3] = f2tf32(kv.w);
            const float4 vv = *(const float4*)(g_qkv + gofs + 2*D_MODEL);
            Vt[(c4+0)*ATT_LDV + row] = f2tf32(vv.x);
            Vt[(c4+1)*ATT_LDV + row] = f2tf32(vv.y);
            Vt[(c4+2)*ATT_LDV + row] = f2tf32(vv.z);
            Vt[(c4+3)*ATT_LDV + row] = f2tf32(vv.w);
        }
        __syncthreads();

        float s[8][4];
        #pragma unroll
        for (int nf = 0; nf < 8; nf++)
            #pragma unroll
            for (int r = 0; r < 4; r++) s[nf][r] = 0.f;
        #pragma unroll
        for (int k = 0; k < 8; k++) {
            uint32_t bf[8][2];
            #pragma unroll
            for (int nf = 0; nf < 8; nf++) {
                const uint32_t* base = Ks + (nf*8 + g)*ATT_LDK + k*8 + t;
                bf[nf][0] = base[0]; bf[nf][1] = base[4];
            }
            #pragma unroll
            for (int nf = 0; nf < 8; nf++) mma_tf32(s[nf], qf[k], bf[nf]);
        }

        #pragma unroll
        for (int nf = 0; nf < 8; nf++) {
            const int jg = kt*64 + nf*8 + 2*t;
            const int d00 = jg - qg0, d10 = jg - qg1;
            const float p00 = __expf(s[nf][0] - slope*(float)(d00   > 0 ? d00   : 0));
            const float p01 = __expf(s[nf][1] - slope*(float)(d00+1 > 0 ? d00+1 : 0));
            const float p10 = __expf(s[nf][2] - slope*(float)(d10   > 0 ? d10   : 0));
            const float p11 = __expf(s[nf][3] - slope*(float)(d10+1 > 0 ? d10+1 : 0));
            l0 += p00 + p01; l1 += p10 + p11;
            uint32_t* pr0 = Ps + (warp*16 + g)*ATT_LDK + nf*8 + 2*t;
            pr0[0] = f2tf32(p00); pr0[1] = f2tf32(p01);
            pr0[8*ATT_LDK] = f2tf32(p10); pr0[8*ATT_LDK + 1] = f2tf32(p11);
        }
        __syncwarp();

        #pragma unroll
        for (int k = 0; k < 8; k++) {
            uint32_t pf[4];
            const uint32_t* pb = Ps + (warp*16 + g)*ATT_LDK + k*8 + t;
            pf[0] = pb[0]; pf[1] = pb[8*ATT_LDK];
            pf[2] = pb[4]; pf[3] = pb[8*ATT_LDK + 4];
            #pragma unroll
            for (int nf = 0; nf < 8; nf++) {
                const uint32_t* vb = Vt + (nf*8 + g)*ATT_LDV + k*8 + t;
                uint32_t bf[2] = { vb[0], vb[4] };
                mma_tf32(o[nf], pf, bf);
            }
        }
    }

    l0 += __shfl_xor_sync(0xffffffffu, l0, 1);
    l0 += __shfl_xor_sync(0xffffffffu, l0, 2);
    l1 += __shfl_xor_sync(0xffffffffu, l1, 1);
    l1 += __shfl_xor_sync(0xffffffffu, l1, 2);
    const float inv0 = 1.f/l0, inv1 = 1.f/l1;
    __nv_bfloat16* y0 = g_yh + ((size_t)(b*SEQ + qg0))*D_MODEL + h*64;
    __nv_bfloat16* y1 = g_yh + ((size_t)(b*SEQ + qg1))*D_MODEL + h*64;
    #pragma unroll
    for (int nf = 0; nf < 8; nf++) {
        const int c = nf*8 + 2*t;
        y0[c]   = __float2bfloat16(o[nf][0]*inv0);
        y0[c+1] = __float2bfloat16(o[nf][1]*inv0);
        y1[c]   = __float2bfloat16(o[nf][2]*inv1);
        y1[c+1] = __float2bfloat16(o[nf][3]*inv1);
    }
}

// ---------------- Decomp1D ----------------
#define DC_NT 128
#define DC_DT 32
#define DC_HALO 24
__global__ void __launch_bounds__(256) decomp_kernel(
    const float* __restrict__ x, const float* __restrict__ alpha,
    const float* __restrict__ dw7, const float* __restrict__ dw25,
    const float* __restrict__ dw49)
{
    __shared__ float sx[DC_NT + 2*DC_HALO][DC_DT];
    __shared__ float sw7[DC_DT][7];
    __shared__ float sw25[DC_DT][25];
    __shared__ float sw49[DC_DT][49];
    const int b  = blockIdx.z;
    const int n0 = blockIdx.y * DC_NT;
    const int d0 = blockIdx.x * DC_DT;
    const int tid = threadIdx.x;

    for (int i = tid; i < DC_DT*7;  i += 256) sw7 [i/7 ][i%7 ] = dw7 [(d0 + i/7 )*7  + i%7 ];
    for (int i = tid; i < DC_DT*25; i += 256) sw25[i/25][i%25] = dw25[(d0 + i/25)*25 + i%25];
    for (int i = tid; i < DC_DT*49; i += 256) sw49[i/49][i%49] = dw49[(d0 + i/49)*49 + i%49];

    for (int i = tid; i < (DC_NT + 2*DC_HALO)*DC_DT; i += 256) {
        int r = i / DC_DT, c = i % DC_DT;
        int n = n0 + r - DC_HALO;
        if (n < 0)    n = -n;
        if (n >= SEQ) n = 2*SEQ - 2 - n;
        sx[r][c] = x[((size_t)b*SEQ + n)*D_MODEL + d0 + c];
    }
    __syncthreads();

    const float a0 = alpha[0], a1 = alpha[1], a2 = alpha[2];
    const float mx = fmaxf(a0, fmaxf(a1, a2));
    const float e0 = __expf(a0-mx), e1 = __expf(a1-mx), e2 = __expf(a2-mx);
    const float inv = 1.f/(e0+e1+e2);
    const float w0 = e0*inv, w1 = e1*inv, w2 = e2*inv;

    for (int i = tid; i < DC_NT*DC_DT; i += 256) {
        const int p = i / DC_DT, c = i % DC_DT;
        float t7 = 0.f, t25 = 0.f, t49 = 0.f;
        #pragma unroll
        for (int j = 0; j < 7;  j++) t7  = fmaf(sx[p + DC_HALO - 3  + j][c], sw7 [c][j], t7 );
        #pragma unroll
        for (int j = 0; j < 25; j++) t25 = fmaf(sx[p + DC_HALO - 12 + j][c], sw25[c][j], t25);
        #pragma unroll
        for (int j = 0; j < 49; j++) t49 = fmaf(sx[p + j][c],                sw49[c][j], t49);
        const float tr = w0*t7 + w1*t25 + w2*t49;
        const size_t idx = ((size_t)b*SEQ + n0 + p)*D_MODEL + d0 + c;
        g_Tr[idx] = tr;
        g_S[idx]  = sx[p + DC_HALO][c] - tr;
    }
}

// ---------------- LayerNorm: bf16 out (GEMM A) + optional fp32 out (router) ----------------
__global__ void __launch_bounds__(256) ln_kernel(
    const float* __restrict__ in, const float* __restrict__ gam,
    const float* __restrict__ bet, __nv_bfloat16* __restrict__ outh,
    float* __restrict__ outf)
{
    __shared__ float row[D_MODEL];
    __shared__ float red[256];
    const int t = blockIdx.x, tid = threadIdx.x;
    const float* ip = in + (size_t)t*D_MODEL;
    float s = 0.f;
    for (int d = tid; d < D_MODEL; d += 256) { float v = ip[d]; row[d] = v; s += v; }
    red[tid] = s; __syncthreads();
    for (int o = 128; o > 0; o >>= 1) { if (tid < o) red[tid] += red[tid+o]; __syncthreads(); }
    const float mean = red[0] * (1.f/D_MODEL);
    __syncthreads();
    float vs = 0.f;
    for (int d = tid; d < D_MODEL; d += 256) { float dv = row[d]-mean; vs += dv*dv; }
    red[tid] = vs; __syncthreads();
    for (int o = 128; o > 0; o >>= 1) { if (tid < o) red[tid] += red[tid+o]; __syncthreads(); }
    const float rstd = rsqrtf(red[0] * (1.f/D_MODEL) + LN_EPS);
    for (int d = tid; d < D_MODEL; d += 256) {
        const float v = (row[d]-mean)*rstd*gam[d] + bet[d];
        outh[(size_t)t*D_MODEL + d] = __float2bfloat16(v);
        if (outf) outf[(size_t)t*D_MODEL + d] = v;
    }
}

// ---------------- Router (fp32 xf) ----------------
__global__ void __launch_bounds__(256) router_kernel(
    const float* __restrict__ xf, const float* __restrict__ rw)
{
    const int warp = threadIdx.x / 32, lane = threadIdx.x % 32;
    const int t = blockIdx.x*8 + warp;
    const float* xp = xf + (size_t)t*D_MODEL;
    float logit[NUM_EXPERTS];
    #pragma unroll
    for (int e = 0; e < NUM_EXPERTS; e++) {
        float p = 0.f;
        for (int d = lane; d < D_MODEL; d += 32) p = fmaf(xp[d], rw[e*D_MODEL + d], p);
        #pragma unroll
        for (int o = 16; o > 0; o >>= 1) p += __shfl_xor_sync(0xffffffffu, p, o);
        logit[e] = p;
    }
    if (lane == 0) {
        float mx = logit[0];
        #pragma unroll
        for (int e = 1; e < NUM_EXPERTS; e++) mx = fmaxf(mx, logit[e]);
        float g[NUM_EXPERTS]; float s = 0.f;
        #pragma unroll
        for (int e = 0; e < NUM_EXPERTS; e++) { g[e] = expf(logit[e]-mx); s += g[e]; }
        #pragma unroll
        for (int e = 0; e < NUM_EXPERTS; e++) g[e] /= s;
        int i0 = 0;
        #pragma unroll
        for (int e = 1; e < NUM_EXPERTS; e++) if (g[e] > g[i0]) i0 = e;
        int i1 = -1;
        #pragma unroll
        for (int e = 0; e < NUM_EXPERTS; e++)
            if (e != i0 && (i1 < 0 || g[e] > g[i1])) i1 = e;
        const float s2 = fmaxf(g[i0] + g[i1], 1e-9f);
        float w[NUM_EXPERTS] = {0.f, 0.f, 0.f, 0.f};
        w[i0] = g[i0]/s2; w[i1] = g[i1]/s2;
        #pragma unroll
        for (int e = 0; e < NUM_EXPERTS; e++) {
            g_gates[t*NUM_EXPERTS + e] = g[e];
            g_w[t*NUM_EXPERTS + e]     = w[e];
        }
    }
}

// ---------------- routing lists ----------------
__global__ void __launch_bounds__(128) route_kernel()
{
    const int e = threadIdx.x >> 5, lane = threadIdx.x & 31;
    int cnt = 0;
    for (int base = 0; base < TOKENS; base += 32) {
        const int t = base + lane;
        const bool sel = g_w[t*NUM_EXPERTS + e] > 0.f;
        const unsigned m = __ballot_sync(0xffffffffu, sel);
        if (sel) g_elist[e*TOKENS + cnt + __popc(m & ((1u << lane) - 1u))] = t;
        cnt += __popc(m);
    }
    __syncwarp();
    const int padded = (cnt + 127) & ~127;
    if (cnt > 0) {
        const int last = g_elist[e*TOKENS + cnt - 1];
        for (int i = cnt + lane; i < padded; i += 32) g_elist[e*TOKENS + i] = last;
    }
    if (lane == 0) g_ecnt[e] = cnt;
}

// ---------------- aux ----------------
__global__ void __launch_bounds__(256) aux_kernel(float* __restrict__ out, int out_size)
{
    __shared__ float rg[NUM_EXPERTS][256];
    __shared__ float rc[NUM_EXPERTS][256];
    const int tid = threadIdx.x;
    float gs[NUM_EXPERTS] = {0,0,0,0}, cs[NUM_EXPERTS] = {0,0,0,0};
    for (int t = tid; t < TOKENS; t += 256) {
        #pragma unroll
        for (int e = 0; e < NUM_EXPERTS; e++) {
            gs[e] += g_gates[t*NUM_EXPERTS + e];
            cs[e] += (g_w[t*NUM_EXPERTS + e] > 0.f) ? 1.f : 0.f;
        }
    }
    #pragma unroll
    for (int e = 0; e < NUM_EXPERTS; e++) { rg[e][tid] = gs[e]; rc[e][tid] = cs[e]; }
    __syncthreads();
    for (int o = 128; o > 0; o >>= 1) {
        if (tid < o)
            #pragma unroll
            for (int e = 0; e < NUM_EXPERTS; e++) { rg[e][tid] += rg[e][tid+o]; rc[e][tid] += rc[e][tid+o]; }
        __syncthreads();
    }
    if (tid == 0 && out_size > BND) {
        float aux = 0.f;
        #pragma unroll
        for (int e = 0; e < NUM_EXPERTS; e++)
            aux += (rg[e][0]*(1.f/TOKENS)) * (rc[e][0]*(1.f/TOKENS));
        out[out_size - 1] = (float)NUM_EXPERTS * aux;
    }
}

// ---------------- final ----------------
__global__ void __launch_bounds__(256) final_kernel(
    const float* __restrict__ tw, const float* __restrict__ tb, float* __restrict__ out)
{
    const size_t gid = (size_t)blockIdx.x*256 + threadIdx.x;
    if (gid >= (size_t)BND) return;
    const int d = (int)(gid % D_MODEL);
    const int n = (int)((gid / D_MODEL) % SEQ);
    float t = 0.f;
    #pragma unroll
    for (int j = 0; j < 5; j++) {
        const int nn = n - 2 + j;
        if (nn >= 0 && nn < SEQ)
            t = fmaf(g_Tr[gid + (size_t)(j-2)*D_MODEL], tw[d*5 + j], t);
    }
    out[gid] = g_xs[gid] + t + tb[d];
}

// ---------------- launch ----------------
static void* sym_addr(const void* sym) {
    void* p = nullptr;
    cudaGetSymbolAddress(&p, sym);
    return p;
}

extern "C" void kernel_launch(void* const* d_in, const int* in_sizes, int n_in,
                              void* d_out, int out_size)
{
    const float* x    = (const float*)d_in[0];
    const float* qw   = (const float*)d_in[1];  const float* qb  = (const float*)d_in[2];
    const float* kw   = (const float*)d_in[3];  const float* kb  = (const float*)d_in[4];
    const float* vw   = (const float*)d_in[5];  const float* vb  = (const float*)d_in[6];
    const float* ow   = (const float*)d_in[7];  const float* ob  = (const float*)d_in[8];
    const float* n1g  = (const float*)d_in[9];  const float* n1b = (const float*)d_in[10];
    const float* n2g  = (const float*)d_in[11]; const float* n2b = (const float*)d_in[12];
    const float* alpha= (const float*)d_in[13];
    const float* dw7  = (const float*)d_in[14];
    const float* dw25 = (const float*)d_in[15];
    const float* dw49 = (const float*)d_in[16];
    const float* rw   = (const float*)d_in[17];
    const float* ew1  = (const float*)d_in[18]; const float* eb1 = (const float*)d_in[19];
    const float* ew2  = (const float*)d_in[20]; const float* eb2 = (const float*)d_in[21];
    const float* tw   = (const float*)d_in[22]; const float* tb  = (const float*)d_in[23];
    float* out = (float*)d_out;

    float* pS   = (float*)sym_addr(g_S);
    float* pBuf = (float*)sym_addr(g_buf);
    __nv_bfloat16* pBufH = (__nv_bfloat16*)sym_addr(g_bufh);
    float* pQKV = (float*)sym_addr(g_qkv);
    __nv_bfloat16* pYH = (__nv_bfloat16*)sym_addr(g_yh);
    float* pXs  = (float*)sym_addr(g_xs);
    __nv_bfloat16* pHH = (__nv_bfloat16*)sym_addr(g_hh);
    float* pW   = (float*)sym_addr(g_w);
    int*   pEL  = (int*)sym_addr(g_elist);
    int*   pEC  = (int*)sym_addr(g_ecnt);
    __nv_bfloat16* pRW4 = (__nv_bfloat16*)sym_addr(g_rw4h);
    __nv_bfloat16* pRE1 = (__nv_bfloat16*)sym_addr(g_rew1h);
    __nv_bfloat16* pRE2 = (__nv_bfloat16*)sym_addr(g_rew2h);
    float* pQKVB= (float*)sym_addr(g_qkvb);
    (void)in_sizes; (void)n_in;

    cudaFuncSetAttribute(attn_tc_kernel, cudaFuncAttributeMaxDynamicSharedMemorySize, ATT_SMEM);
    cudaFuncSetAttribute(tc_gemm<0>, cudaFuncAttributeMaxDynamicSharedMemorySize, TCG_SMEM);
    cudaFuncSetAttribute(tc_gemm<1>, cudaFuncAttributeMaxDynamicSharedMemorySize, TCG_SMEM);
    cudaFuncSetAttribute(tc_gemm<2>, cudaFuncAttributeMaxDynamicSharedMemorySize, TCG_SMEM);
    cudaFuncSetAttribute(tc_gemm<3>, cudaFuncAttributeMaxDynamicSharedMemorySize, TCG_SMEM);

    // 0) pre-round weights to bf16 + concat qkv bias
    const int DD4 = D_MODEL*D_MODEL/4;
    const int E14 = NUM_EXPERTS*MOE_HIDDEN*D_MODEL/4;
    const int E24 = NUM_EXPERTS*D_MODEL*MOE_HIDDEN/4;
    round_bf16_kernel<<<(DD4+255)/256, 256>>>(qw, pRW4 + 0*D_MODEL*D_MODEL, DD4);
    round_bf16_kernel<<<(DD4+255)/256, 256>>>(kw, pRW4 + 1*D_MODEL*D_MODEL, DD4);
    round_bf16_kernel<<<(DD4+255)/256, 256>>>(vw, pRW4 + 2*D_MODEL*D_MODEL, DD4);
    round_bf16_kernel<<<(DD4+255)/256, 256>>>(ow, pRW4 + 3*D_MODEL*D_MODEL, DD4);
    round_bf16_kernel<<<(E14+255)/256, 256>>>(ew1, pRE1, E14);
    round_bf16_kernel<<<(E24+255)/256, 256>>>(ew2, pRE2, E24);
    cudaMemcpyAsync(pQKVB,            qb, D_MODEL*4, cudaMemcpyDeviceToDevice);
    cudaMemcpyAsync(pQKVB + D_MODEL,  kb, D_MODEL*4, cudaMemcpyDeviceToDevice);
    cudaMemcpyAsync(pQKVB + 2*D_MODEL,vb, D_MODEL*4, cudaMemcpyDeviceToDevice);

    // 1) decomposition -> g_Tr, g_S
    dim3 dgrid(D_MODEL/DC_DT, SEQ/DC_NT, BATCH);
    decomp_kernel<<<dgrid, 256>>>(x, alpha, dw7, dw25, dw49);

    // 2) LN1(S) -> bf16 Sn
    ln_kernel<<<TOKENS, 256>>>(pS, n1g, n1b, pBufH, nullptr);

    // 3) fused QKV projection: one bf16 GEMM, N=3072
    dim3 gq(QKV_LD/128, TOKENS/128, 1);
    tc_gemm<0><<<gq, 256, TCG_SMEM>>>(pBufH, pRW4, pQKVB, pQKV, D_MODEL, QKV_LD,
                                      nullptr, nullptr, 0, nullptr, nullptr, nullptr,
                                      0, 0, 0);

    // 4) attention (tf32, q-tile 128), y -> bf16
    dim3 agrid(BATCH*NHEAD, SEQ/128);
    attn_tc_kernel<<<agrid, 256, ATT_SMEM>>>();

    // 5) O projection + residual S -> g_xs
    dim3 go(D_MODEL/128, TOKENS/128, 1);
    tc_gemm<2><<<go, 256, TCG_SMEM>>>(pYH, pRW4 + (size_t)3*D_MODEL*D_MODEL, ob, pXs,
                                      D_MODEL, D_MODEL,
                                      pS, nullptr, 0, nullptr, nullptr, nullptr,
                                      0, 0, 0);

    // 6) LN2 -> bf16 xf (GEMM) + fp32 xf (router)
    ln_kernel<<<TOKENS, 256>>>(pXs, n2g, n2b, pBufH, pBuf);

    // 7) router (fp32 xf) + routing lists + aux
    router_kernel<<<TOKENS/8, 256>>>(pBuf, rw);
    route_kernel<<<1, 128>>>();
    aux_kernel<<<1, 256>>>(out, out_size);

    // 8) MoE FFN: fused bf16 GEMM1 over all experts (blockIdx.z = expert)
    dim3 gh1(MOE_HIDDEN/128, TOKENS/128, NUM_EXPERTS);
    tc_gemm<1><<<gh1, 256, TCG_SMEM>>>(pBufH, pRE1, eb1, (float*)pHH,
                                       D_MODEL, MOE_HIDDEN,
                                       nullptr, nullptr, 0,
                                       pEL, nullptr, pEC,
                                       (size_t)MOE_HIDDEN*D_MODEL, MOE_HIDDEN,
                                       (size_t)TOKENS*MOE_HIDDEN);
    // GEMM2: per-expert scatter-accumulate (serialized for determinism)
    dim3 gh2(D_MODEL/128, TOKENS/128, 1);
    for (int e = 0; e < NUM_EXPERTS; e++) {
        tc_gemm<3><<<gh2, 256, TCG_SMEM>>>(pHH + (size_t)e*TOKENS*MOE_HIDDEN,
                                           pRE2 + (size_t)e*D_MODEL*MOE_HIDDEN,
                                           eb2 + (size_t)e*D_MODEL, pXs,
                                           MOE_HIDDEN, D_MODEL,
                                           nullptr, pW, e,
                                           nullptr, pEL + e*TOKENS, pEC + e,
                                           0, 0, 0);
    }

    // 9) final
    final_kernel<<<(BND + 255)/256, 256>>>(tw, tb, out);
}

// round 16
// speedup vs baseline: 2.7864x; 1.0447x over previous
#include <cuda_runtime.h>
#include <cuda_bf16.h>
#include <math.h>
#include <stdint.h>

#define D_MODEL 1024
#define NHEAD 16
#define HEAD_DIM 64
#define MOE_HIDDEN 2048
#define NUM_EXPERTS 4
#define BATCH 8
#define SEQ 1024
#define TOKENS (BATCH*SEQ)          /* 8192  */
#define BND (TOKENS*D_MODEL)        /* 8388608 */
#define QKV_LD (3*D_MODEL)
#define LN_EPS 1e-5f

// ---------------- scratch (device globals; no allocation) ----------------
__device__ float g_Tr[BND];
__device__ float g_S[BND];
__device__ float g_buf[BND];                    // LN2 fp32 (router)
__device__ __nv_bfloat16 g_bufh[BND];           // LN bf16 (GEMM A)
__device__ float g_qkv[TOKENS*QKV_LD];          // packed q|k|v per token (fp32)
__device__ __nv_bfloat16 g_yh[BND];             // attention out, bf16 (O-proj A)
__device__ float g_xs[BND];
__device__ __nv_bfloat16 g_hh[NUM_EXPERTS*TOKENS*MOE_HIDDEN];  // per-expert hidden (bf16)
__device__ float g_moe[NUM_EXPERTS*TOKENS*D_MODEL];            // per-expert compact GEMM2 out
__device__ float g_w[TOKENS*NUM_EXPERTS];
__device__ float g_gates[TOKENS*NUM_EXPERTS];
__device__ int   g_elist[NUM_EXPERTS*TOKENS];
__device__ int   g_epos[2*TOKENS];              // token -> (e*TOKENS+pos) x2, ascending e
__device__ int   g_ecnt[NUM_EXPERTS];
__device__ float g_qkvb[QKV_LD];                // concat qb|kb|vb (fp32)
// bf16-pre-rounded weights
__device__ __nv_bfloat16 g_rw4h[4*D_MODEL*D_MODEL];       // qw,kw,vw,ow (contiguous)
__device__ __nv_bfloat16 g_rew1h[NUM_EXPERTS*MOE_HIDDEN*D_MODEL];
__device__ __nv_bfloat16 g_rew2h[NUM_EXPERTS*D_MODEL*MOE_HIDDEN];

// ============================================================
// helpers
// ============================================================
__device__ __forceinline__ uint32_t f2tf32(float f) {
    uint32_t u; asm("cvt.rna.tf32.f32 %0, %1;" : "=r"(u) : "f"(f)); return u;
}
__device__ __forceinline__ void mma_tf32(float* c, const uint32_t* a, const uint32_t* b) {
    asm volatile(
        "mma.sync.aligned.m16n8k8.row.col.f32.tf32.tf32.f32 "
        "{%0,%1,%2,%3}, {%4,%5,%6,%7}, {%8,%9}, {%0,%1,%2,%3};"
        : "+f"(c[0]), "+f"(c[1]), "+f"(c[2]), "+f"(c[3])
        : "r"(a[0]), "r"(a[1]), "r"(a[2]), "r"(a[3]), "r"(b[0]), "r"(b[1]));
}
__device__ __forceinline__ void mma_bf16(float* c, const uint32_t* a, const uint32_t* b) {
    asm volatile(
        "mma.sync.aligned.m16n8k16.row.col.f32.bf16.bf16.f32 "
        "{%0,%1,%2,%3}, {%4,%5,%6,%7}, {%8,%9}, {%0,%1,%2,%3};"
        : "+f"(c[0]), "+f"(c[1]), "+f"(c[2]), "+f"(c[3])
        : "r"(a[0]), "r"(a[1]), "r"(a[2]), "r"(a[3]), "r"(b[0]), "r"(b[1]));
}
__device__ __forceinline__ void ldsm_x4(uint32_t* r, uint32_t addr) {
    asm volatile("ldmatrix.sync.aligned.m8n8.x4.shared.b16 {%0,%1,%2,%3}, [%4];"
        : "=r"(r[0]), "=r"(r[1]), "=r"(r[2]), "=r"(r[3]) : "r"(addr));
}
__device__ __forceinline__ void ldsm_x2(uint32_t* r, uint32_t addr) {
    asm volatile("ldmatrix.sync.aligned.m8n8.x2.shared.b16 {%0,%1}, [%2];"
        : "=r"(r[0]), "=r"(r[1]) : "r"(addr));
}
__device__ __forceinline__ uint32_t smem_u32(const void* p) {
    uint32_t a;
    asm("{ .reg .u64 t; cvta.to.shared.u64 t, %1; cvt.u32.u64 %0, t; }" : "=r"(a) : "l"(p));
    return a;
}
__device__ __forceinline__ void cp16(uint32_t dst, const void* src) {
    asm volatile("cp.async.cg.shared.global [%0], [%1], 16;" :: "r"(dst), "l"(src));
}
__device__ __forceinline__ uint32_t pack_bf2(float a, float b) {
    __nv_bfloat162 h = { __float2bfloat16(a), __float2bfloat16(b) };
    return *(uint32_t*)&h;
}

// ---------------- weight bf16 pre-round: 8 floats -> one 16B store ----------------
__global__ void __launch_bounds__(256) round8_kernel(
    const float* __restrict__ src, __nv_bfloat16* __restrict__ dst, int n8)
{
    const int i = blockIdx.x*256 + threadIdx.x;
    if (i < n8) {
        const float4 a = ((const float4*)src)[2*i];
        const float4 b = ((const float4*)src)[2*i+1];
        uint4 o;
        o.x = pack_bf2(a.x, a.y); o.y = pack_bf2(a.z, a.w);
        o.z = pack_bf2(b.x, b.y); o.w = pack_bf2(b.z, b.w);
        ((uint4*)dst)[i] = o;
    }
}
// 4 same-size sources in one launch (blockIdx.y selects)
__global__ void __launch_bounds__(256) round8x4_kernel(
    const float* __restrict__ s0, const float* __restrict__ s1,
    const float* __restrict__ s2, const float* __restrict__ s3,
    __nv_bfloat16* __restrict__ dst, int n8)
{
    const int i = blockIdx.x*256 + threadIdx.x;
    if (i >= n8) return;
    const float* src = (blockIdx.y == 0) ? s0 : (blockIdx.y == 1) ? s1
                     : (blockIdx.y == 2) ? s2 : s3;
    const float4 a = ((const float4*)src)[2*i];
    const float4 b = ((const float4*)src)[2*i+1];
    uint4 o;
    o.x = pack_bf2(a.x, a.y); o.y = pack_bf2(a.z, a.w);
    o.z = pack_bf2(b.x, b.y); o.w = pack_bf2(b.z, b.w);
    ((uint4*)(dst + (size_t)blockIdx.y * n8 * 8))[i] = o;
}

// ============================================================
// bf16 mma.sync GEMM: C[m,n] = sum_k A[m,k]*B[n,k]  (A,B bf16; acc fp32)
// cp.async 3-stage pipeline, CTA 128x128, BK=64, 256 thr (8 warps 2x4,
// warp tile 64x32), LDA=36 words, ldmatrix loads, 2 CTAs/SM.
// Per-blockIdx.z strides for A/B/bias/C (fused expert launches).
// EPI: 0 plain fp32, 1 GELU->bf16, 2 +resid fp32
// ============================================================
#define TCG_LDA 36
#define ST_WORDS (128*TCG_LDA)            /* 4608 words per matrix per stage */
#define TCG_SMEM (3*2*ST_WORDS*4)         /* 110592 B */

template<int EPI>
__global__ void __launch_bounds__(256, 2) tc_gemm(
    const __nv_bfloat16* __restrict__ A, const __nv_bfloat16* __restrict__ B,
    const float* __restrict__ bias, float* __restrict__ C,
    int K, int Nn,
    const float* __restrict__ resid,
    const int* __restrict__ aidx, const int* __restrict__ cntp,
    size_t astride, size_t bstride, int bias_stride, size_t cstride)
{
    extern __shared__ uint32_t smu[];
    const int tid = threadIdx.x;
    const int ez = blockIdx.z;
    const int bm = blockIdx.y * 128, bn = blockIdx.x * 128;
    if (cntp) { const int cnt = cntp[ez]; if (bm >= ((cnt + 127) & ~127)) return; }
    A    += (size_t)ez * astride;
    B    += (size_t)ez * bstride;
    bias += (size_t)ez * bias_stride;
    float* Cf = C + (EPI == 1 ? (size_t)0 : (size_t)ez * cstride);
    __nv_bfloat16* Cb = (__nv_bfloat16*)C + (EPI == 1 ? (size_t)ez * cstride : (size_t)0);
    if (aidx) aidx += ez * TOKENS;

    const int warp = tid >> 5, lane = tid & 31;
    const int wm = (warp >> 2) * 64, wn = (warp & 3) * 32;
    const int g = lane >> 2, t = lane & 3;

    // staging: 128 rows x 8 chunks(16B) per matrix per stage; 4 (row,chunk)/thread
    const int lr8 = tid >> 3;
    const int lc8 = tid & 7;
    const __nv_bfloat16* AgP[4];
    const __nv_bfloat16* BgP[4];
    uint32_t oaS[4];
    #pragma unroll
    for (int j = 0; j < 4; j++) {
        const int row = lr8 + 32*j;
        int ra = bm + row;
        if (aidx) ra = aidx[ra];
        AgP[j] = A + (size_t)ra * K + lc8 * 8;
        BgP[j] = B + (size_t)(bn + row) * K + lc8 * 8;
        oaS[j] = (uint32_t)(row*TCG_LDA + lc8*4)*4;
    }

    const uint32_t sbase = smem_u32(smu);
    const uint32_t obB = ST_WORDS*4;
    const uint32_t lma = ((wm + (lane & 15))*TCG_LDA + ((lane >> 4) << 2)) * 4;
    const uint32_t lmb = obB + ((wn + (lane & 7))*TCG_LDA + ((lane & 8) ? 4 : 0)) * 4;

    float acc[4][4][4];
    #pragma unroll
    for (int i = 0; i < 4; i++)
        #pragma unroll
        for (int j = 0; j < 4; j++)
            #pragma unroll
            for (int r = 0; r < 4; r++) acc[i][j][r] = 0.f;

    const int NT = K >> 6;
    #pragma unroll
    for (int s = 0; s < 2; s++) {
        const uint32_t sb = sbase + s*2*ST_WORDS*4;
        const int ko = s*64;
        #pragma unroll
        for (int j = 0; j < 4; j++) {
            cp16(sb + oaS[j], AgP[j] + ko);
            cp16(sb + obB + oaS[j], BgP[j] + ko);
        }
        asm volatile("cp.async.commit_group;");
    }

    int stage = 0;
    for (int kt = 0; kt < NT; kt++) {
        asm volatile("cp.async.wait_group 1;" ::: "memory");
        __syncthreads();
        const uint32_t stb = sbase + stage*2*ST_WORDS*4;

        #pragma unroll
        for (int ks = 0; ks < 4; ks++) {
            const uint32_t kb4 = (uint32_t)ks * 32;
            uint32_t af[4][4], bf[4][2];
            #pragma unroll
            for (int mf = 0; mf < 4; mf++)
                ldsm_x4(af[mf], stb + lma + (uint32_t)(mf*16*TCG_LDA)*4 + kb4);
            #pragma unroll
            for (int nf = 0; nf < 4; nf++)
                ldsm_x2(bf[nf], stb + lmb + (uint32_t)(nf*8*TCG_LDA)*4 + kb4);
            #pragma unroll
            for (int mf = 0; mf < 4; mf++)
                #pragma unroll
                for (int nf = 0; nf < 4; nf++)
                    mma_bf16(acc[mf][nf], af[mf], bf[nf]);
        }

        if (kt + 2 < NT) {
            const int ns = (stage + 2 >= 3) ? stage - 1 : stage + 2;
            const int ko = (kt + 2) * 64;
            const uint32_t sb = sbase + ns*2*ST_WORDS*4;
            #pragma unroll
            for (int j = 0; j < 4; j++) {
                cp16(sb + oaS[j], AgP[j] + ko);
                cp16(sb + obB + oaS[j], BgP[j] + ko);
            }
            asm volatile("cp.async.commit_group;");
        } else {
            asm volatile("cp.async.commit_group;");
        }
        stage = (stage + 1 == 3) ? 0 : stage + 1;
    }

    // ---- epilogue ----
    #pragma unroll
    for (int mf = 0; mf < 4; mf++) {
        const int mp0 = bm + wm + mf*16 + g;
        const int mp1 = mp0 + 8;
        #pragma unroll
        for (int nf = 0; nf < 4; nf++) {
            const int n0 = bn + wn + nf*8 + 2*t;
            const float b0 = bias[n0], b1 = bias[n0 + 1];
            float v0 = acc[mf][nf][0] + b0;
            float v1 = acc[mf][nf][1] + b1;
            float v2 = acc[mf][nf][2] + b0;
            float v3 = acc[mf][nf][3] + b1;
            const size_t i0 = (size_t)mp0 * Nn + n0;
            const size_t i1 = (size_t)mp1 * Nn + n0;
            if (EPI == 0) {
                Cf[i0] = v0; Cf[i0+1] = v1; Cf[i1] = v2; Cf[i1+1] = v3;
            } else if (EPI == 1) {
                Cb[i0]   = __float2bfloat16(0.5f*v0*(1.0f + erff(v0*0.70710678118654752f)));
                Cb[i0+1] = __float2bfloat16(0.5f*v1*(1.0f + erff(v1*0.70710678118654752f)));
                Cb[i1]   = __float2bfloat16(0.5f*v2*(1.0f + erff(v2*0.70710678118654752f)));
                Cb[i1+1] = __float2bfloat16(0.5f*v3*(1.0f + erff(v3*0.70710678118654752f)));
            } else {
                Cf[i0] = v0 + resid[i0]; Cf[i0+1] = v1 + resid[i0+1];
                Cf[i1] = v2 + resid[i1]; Cf[i1+1] = v3 + resid[i1+1];
            }
        }
    }
}

// ============================================================
// Tensor-core ALiBi flash attention (tf32) — q-tile 128 (8 warps).
// ============================================================
#define ATT_LDK 68
#define ATT_LDV 69
#define ATT_SMEM ((64*ATT_LDK + 64*ATT_LDV + 128*ATT_LDK)*4)   /* 69888 B */

__global__ void __launch_bounds__(256, 2) attn_tc_kernel()
{
    extern __shared__ uint32_t smA[];
    uint32_t* Ks = smA;
    uint32_t* Vt = smA + 64*ATT_LDK;
    uint32_t* Ps = smA + 64*ATT_LDK + 64*ATT_LDV;     // 128 rows
    const int tid = threadIdx.x;
    const int warp = tid >> 5, lane = tid & 31;
    const int g = lane >> 2, t = lane & 3;
    const int bh = blockIdx.x;
    const int b = bh >> 4, h = bh & 15;
    const int q0 = blockIdx.y * 128;
    const float slope = exp2f(-0.5f*(float)(h + 1));

    for (int i = tid; i < 2048; i += 256) {
        const int row = i >> 4, c4 = (i & 15) * 4;
        const float4 qv = *(const float4*)(g_qkv + ((size_t)(b*SEQ + q0 + row))*QKV_LD + h*64 + c4);
        uint32_t* d = Ps + row*ATT_LDK + c4;
        d[0] = f2tf32(qv.x*0.125f); d[1] = f2tf32(qv.y*0.125f);
        d[2] = f2tf32(qv.z*0.125f); d[3] = f2tf32(qv.w*0.125f);
    }
    __syncthreads();
    uint32_t qf[8][4];
    #pragma unroll
    for (int k = 0; k < 8; k++) {
        const uint32_t* base = Ps + (warp*16 + g)*ATT_LDK + k*8 + t;
        qf[k][0] = base[0]; qf[k][1] = base[8*ATT_LDK];
        qf[k][2] = base[4]; qf[k][3] = base[8*ATT_LDK + 4];
    }

    float o[8][4];
    #pragma unroll
    for (int nf = 0; nf < 8; nf++)
        #pragma unroll
        for (int r = 0; r < 4; r++) o[nf][r] = 0.f;
    float l0 = 0.f, l1 = 0.f;
    const int qg0 = q0 + warp*16 + g, qg1 = qg0 + 8;

    for (int kt = 0; kt < 16; kt++) {
        __syncthreads();
        for (int i = tid; i < 1024; i += 256) {
            const int row = i >> 4, c4 = (i & 15) * 4;
            const size_t gofs = ((size_t)(b*SEQ + kt*64 + row))*QKV_LD + h*64 + c4;
            const float4 kv = *(const float4*)(g_qkv + gofs + D_MODEL);
            uint32_t* dk = Ks + row*ATT_LDK + c4;
            dk[0] = f2tf32(kv.x); dk[1] = f2tf32(kv.y);
            dk[2] = f2tf32(kv.z); dk[3] = f2tf32(kv.w);
            const float4 vv = *(const float4*)(g_qkv + gofs + 2*D_MODEL);
            Vt[(c4+0)*ATT_LDV + row] = f2tf32(vv.x);
            Vt[(c4+1)*ATT_LDV + row] = f2tf32(vv.y);
            Vt[(c4+2)*ATT_LDV + row] = f2tf32(vv.z);
            Vt[(c4+3)*ATT_LDV + row] = f2tf32(vv.w);
        }
        __syncthreads();

        float s[8][4];
        #pragma unroll
        for (int nf = 0; nf < 8; nf++)
            #pragma unroll
            for (int r = 0; r < 4; r++) s[nf][r] = 0.f;
        #pragma unroll
        for (int k = 0; k < 8; k++) {
            uint32_t bf[8][2];
            #pragma unroll
            for (int nf = 0; nf < 8; nf++) {
                const uint32_t* base = Ks + (nf*8 + g)*ATT_LDK + k*8 + t;
                bf[nf][0] = base[0]; bf[nf][1] = base[4];
            }
            #pragma unroll
            for (int nf = 0; nf < 8; nf++) mma_tf32(s[nf], qf[k], bf[nf]);
        }

        #pragma unroll
        for (int nf = 0; nf < 8; nf++) {
            const int jg = kt*64 + nf*8 + 2*t;
            const int d00 = jg - qg0, d10 = jg - qg1;
            const float p00 = __expf(s[nf][0] - slope*(float)(d00   > 0 ? d00   : 0));
            const float p01 = __expf(s[nf][1] - slope*(float)(d00+1 > 0 ? d00+1 : 0));
            const float p10 = __expf(s[nf][2] - slope*(float)(d10   > 0 ? d10   : 0));
            const float p11 = __expf(s[nf][3] - slope*(float)(d10+1 > 0 ? d10+1 : 0));
            l0 += p00 + p01; l1 += p10 + p11;
            uint32_t* pr0 = Ps + (warp*16 + g)*ATT_LDK + nf*8 + 2*t;
            pr0[0] = f2tf32(p00); pr0[1] = f2tf32(p01);
            pr0[8*ATT_LDK] = f2tf32(p10); pr0[8*ATT_LDK + 1] = f2tf32(p11);
        }
        __syncwarp();

        #pragma unroll
        for (int k = 0; k < 8; k++) {
            uint32_t pf[4];
            const uint32_t* pb = Ps + (warp*16 + g)*ATT_LDK + k*8 + t;
            pf[0] = pb[0]; pf[1] = pb[8*ATT_LDK];
            pf[2] = pb[4]; pf[3] = pb[8*ATT_LDK + 4];
            #pragma unroll
            for (int nf = 0; nf < 8; nf++) {
                const uint32_t* vb = Vt + (nf*8 + g)*ATT_LDV + k*8 + t;
                uint32_t bf[2] = { vb[0], vb[4] };
                mma_tf32(o[nf], pf, bf);
            }
        }
    }

    l0 += __shfl_xor_sync(0xffffffffu, l0, 1);
    l0 += __shfl_xor_sync(0xffffffffu, l0, 2);
    l1 += __shfl_xor_sync(0xffffffffu, l1, 1);
    l1 += __shfl_xor_sync(0xffffffffu, l1, 2);
    const float inv0 = 1.f/l0, inv1 = 1.f/l1;
    __nv_bfloat16* y0 = g_yh + ((size_t)(b*SEQ + qg0))*D_MODEL + h*64;
    __nv_bfloat16* y1 = g_yh + ((size_t)(b*SEQ + qg1))*D_MODEL + h*64;
    #pragma unroll
    for (int nf = 0; nf < 8; nf++) {
        const int c = nf*8 + 2*t;
        y0[c]   = __float2bfloat16(o[nf][0]*inv0);
        y0[c+1] = __float2bfloat16(o[nf][1]*inv0);
        y1[c]   = __float2bfloat16(o[nf][2]*inv1);
        y1[c+1] = __float2bfloat16(o[nf][3]*inv1);
    }
}

// ---------------- Decomp1D ----------------
#define DC_NT 128
#define DC_DT 32
#define DC_HALO 24
__global__ void __launch_bounds__(256) decomp_kernel(
    const float* __restrict__ x, const float* __restrict__ alpha,
    const float* __restrict__ dw7, const float* __restrict__ dw25,
    const float* __restrict__ dw49)
{
    __shared__ float sx[DC_NT + 2*DC_HALO][DC_DT];
    __shared__ float sw7[DC_DT][7];
    __shared__ float sw25[DC_DT][25];
    __shared__ float sw49[DC_DT][49];
    const int b  = blockIdx.z;
    const int n0 = blockIdx.y * DC_NT;
    const int d0 = blockIdx.x * DC_DT;
    const int tid = threadIdx.x;

    for (int i = tid; i < DC_DT*7;  i += 256) sw7 [i/7 ][i%7 ] = dw7 [(d0 + i/7 )*7  + i%7 ];
    for (int i = tid; i < DC_DT*25; i += 256) sw25[i/25][i%25] = dw25[(d0 + i/25)*25 + i%25];
    for (int i = tid; i < DC_DT*49; i += 256) sw49[i/49][i%49] = dw49[(d0 + i/49)*49 + i%49];

    for (int i = tid; i < (DC_NT + 2*DC_HALO)*DC_DT; i += 256) {
        int r = i / DC_DT, c = i % DC_DT;
        int n = n0 + r - DC_HALO;
        if (n < 0)    n = -n;
        if (n >= SEQ) n = 2*SEQ - 2 - n;
        sx[r][c] = x[((size_t)b*SEQ + n)*D_MODEL + d0 + c];
    }
    __syncthreads();

    const float a0 = alpha[0], a1 = alpha[1], a2 = alpha[2];
    const float mx = fmaxf(a0, fmaxf(a1, a2));
    const float e0 = __expf(a0-mx), e1 = __expf(a1-mx), e2 = __expf(a2-mx);
    const float inv = 1.f/(e0+e1+e2);
    const float w0 = e0*inv, w1 = e1*inv, w2 = e2*inv;

    for (int i = tid; i < DC_NT*DC_DT; i += 256) {
        const int p = i / DC_DT, c = i % DC_DT;
        float t7 = 0.f, t25 = 0.f, t49 = 0.f;
        #pragma unroll
        for (int j = 0; j < 7;  j++) t7  = fmaf(sx[p + DC_HALO - 3  + j][c], sw7 [c][j], t7 );
        #pragma unroll
        for (int j = 0; j < 25; j++) t25 = fmaf(sx[p + DC_HALO - 12 + j][c], sw25[c][j], t25);
        #pragma unroll
        for (int j = 0; j < 49; j++) t49 = fmaf(sx[p + j][c],                sw49[c][j], t49);
        const float tr = w0*t7 + w1*t25 + w2*t49;
        const size_t idx = ((size_t)b*SEQ + n0 + p)*D_MODEL + d0 + c;
        g_Tr[idx] = tr;
        g_S[idx]  = sx[p + DC_HALO][c] - tr;
    }
}

// ---------------- LayerNorm: bf16 out (GEMM A) + optional fp32 out (router) ----------------
__global__ void __launch_bounds__(256) ln_kernel(
    const float* __restrict__ in, const float* __restrict__ gam,
    const float* __restrict__ bet, __nv_bfloat16* __restrict__ outh,
    float* __restrict__ outf)
{
    __shared__ float row[D_MODEL];
    __shared__ float red[256];
    const int t = blockIdx.x, tid = threadIdx.x;
    const float* ip = in + (size_t)t*D_MODEL;
    float s = 0.f;
    for (int d = tid; d < D_MODEL; d += 256) { float v = ip[d]; row[d] = v; s += v; }
    red[tid] = s; __syncthreads();
    for (int o = 128; o > 0; o >>= 1) { if (tid < o) red[tid] += red[tid+o]; __syncthreads(); }
    const float mean = red[0] * (1.f/D_MODEL);
    __syncthreads();
    float vs = 0.f;
    for (int d = tid; d < D_MODEL; d += 256) { float dv = row[d]-mean; vs += dv*dv; }
    red[tid] = vs; __syncthreads();
    for (int o = 128; o > 0; o >>= 1) { if (tid < o) red[tid] += red[tid+o]; __syncthreads(); }
    const float rstd = rsqrtf(red[0] * (1.f/D_MODEL) + LN_EPS);
    for (int d = tid; d < D_MODEL; d += 256) {
        const float v = (row[d]-mean)*rstd*gam[d] + bet[d];
        outh[(size_t)t*D_MODEL + d] = __float2bfloat16(v);
        if (outf) outf[(size_t)t*D_MODEL + d] = v;
    }
}

// ---------------- Router (fp32 xf) ----------------
__global__ void __launch_bounds__(256) router_kernel(
    const float* __restrict__ xf, const float* __restrict__ rw)
{
    const int warp = threadIdx.x / 32, lane = threadIdx.x % 32;
    const int t = blockIdx.x*8 + warp;
    const float* xp = xf + (size_t)t*D_MODEL;
    float logit[NUM_EXPERTS];
    #pragma unroll
    for (int e = 0; e < NUM_EXPERTS; e++) {
        float p = 0.f;
        for (int d = lane; d < D_MODEL; d += 32) p = fmaf(xp[d], rw[e*D_MODEL + d], p);
        #pragma unroll
        for (int o = 16; o > 0; o >>= 1) p += __shfl_xor_sync(0xffffffffu, p, o);
        logit[e] = p;
    }
    if (lane == 0) {
        float mx = logit[0];
        #pragma unroll
        for (int e = 1; e < NUM_EXPERTS; e++) mx = fmaxf(mx, logit[e]);
        float g[NUM_EXPERTS]; float s = 0.f;
        #pragma unroll
        for (int e = 0; e < NUM_EXPERTS; e++) { g[e] = expf(logit[e]-mx); s += g[e]; }
        #pragma unroll
        for (int e = 0; e < NUM_EXPERTS; e++) g[e] /= s;
        int i0 = 0;
        #pragma unroll
        for (int e = 1; e < NUM_EXPERTS; e++) if (g[e] > g[i0]) i0 = e;
        int i1 = -1;
        #pragma unroll
        for (int e = 0; e < NUM_EXPERTS; e++)
            if (e != i0 && (i1 < 0 || g[e] > g[i1])) i1 = e;
        const float s2 = fmaxf(g[i0] + g[i1], 1e-9f);
        float w[NUM_EXPERTS] = {0.f, 0.f, 0.f, 0.f};
        w[i0] = g[i0]/s2; w[i1] = g[i1]/s2;
        #pragma unroll
        for (int e = 0; e < NUM_EXPERTS; e++) {
            g_gates[t*NUM_EXPERTS + e] = g[e];
            g_w[t*NUM_EXPERTS + e]     = w[e];
        }
    }
}

// ---------------- routing lists + inverse (token -> expert,pos) map ----------------
__global__ void __launch_bounds__(128) route_kernel()
{
    const int e = threadIdx.x >> 5, lane = threadIdx.x & 31;
    int cnt = 0;
    for (int base = 0; base < TOKENS; base += 32) {
        const int t = base + lane;
        const bool sel = g_w[t*NUM_EXPERTS + e] > 0.f;
        const unsigned m = __ballot_sync(0xffffffffu, sel);
        if (sel) {
            const int pos = cnt + __popc(m & ((1u << lane) - 1u));
            g_elist[e*TOKENS + pos] = t;
            int lower = 0;
            #pragma unroll
            for (int e2 = 0; e2 < NUM_EXPERTS; e2++)
                if (e2 < e && g_w[t*NUM_EXPERTS + e2] > 0.f) lower++;
            g_epos[2*t + lower] = e*TOKENS + pos;
        }
        cnt += __popc(m);
    }
    __syncwarp();
    const int padded = (cnt + 127) & ~127;
    if (cnt > 0) {
        const int last = g_elist[e*TOKENS + cnt - 1];
        for (int i = cnt + lane; i < padded; i += 32) g_elist[e*TOKENS + i] = last;
    }
    if (lane == 0) g_ecnt[e] = cnt;
}

// ---------------- aux ----------------
__global__ void __launch_bounds__(256) aux_kernel(float* __restrict__ out, int out_size)
{
    __shared__ float rg[NUM_EXPERTS][256];
    __shared__ float rc[NUM_EXPERTS][256];
    const int tid = threadIdx.x;
    float gs[NUM_EXPERTS] = {0,0,0,0}, cs[NUM_EXPERTS] = {0,0,0,0};
    for (int t = tid; t < TOKENS; t += 256) {
        #pragma unroll
        for (int e = 0; e < NUM_EXPERTS; e++) {
            gs[e] += g_gates[t*NUM_EXPERTS + e];
            cs[e] += (g_w[t*NUM_EXPERTS + e] > 0.f) ? 1.f : 0.f;
        }
    }
    #pragma unroll
    for (int e = 0; e < NUM_EXPERTS; e++) { rg[e][tid] = gs[e]; rc[e][tid] = cs[e]; }
    __syncthreads();
    for (int o = 128; o > 0; o >>= 1) {
        if (tid < o)
            #pragma unroll
            for (int e = 0; e < NUM_EXPERTS; e++) { rg[e][tid] += rg[e][tid+o]; rc[e][tid] += rc[e][tid+o]; }
        __syncthreads();
    }
    if (tid == 0 && out_size > BND) {
        float aux = 0.f;
        #pragma unroll
        for (int e = 0; e < NUM_EXPERTS; e++)
            aux += (rg[e][0]*(1.f/TOKENS)) * (rc[e][0]*(1.f/TOKENS));
        out[out_size - 1] = (float)NUM_EXPERTS * aux;
    }
}

// ---------------- final: xs + MoE combine + trend conv + tb ----------------
__global__ void __launch_bounds__(256) final_kernel(
    const float* __restrict__ tw, const float* __restrict__ tb, float* __restrict__ out)
{
    const size_t gid = (size_t)blockIdx.x*256 + threadIdx.x;
    if (gid >= (size_t)BND) return;
    const int d = (int)(gid % D_MODEL);
    const int n = (int)((gid / D_MODEL) % SEQ);
    const int tok = (int)(gid >> 10);
    const int r0 = g_epos[2*tok], r1 = g_epos[2*tok + 1];
    const float w0 = g_w[tok*NUM_EXPERTS + (r0 >> 13)];
    const float w1 = g_w[tok*NUM_EXPERTS + (r1 >> 13)];
    float v = fmaf(g_moe[(size_t)r0*D_MODEL + d], w0, g_xs[gid]);
    v = fmaf(g_moe[(size_t)r1*D_MODEL + d], w1, v);
    float t = 0.f;
    #pragma unroll
    for (int j = 0; j < 5; j++) {
        const int nn = n - 2 + j;
        if (nn >= 0 && nn < SEQ)
            t = fmaf(g_Tr[gid + (size_t)(j-2)*D_MODEL], tw[d*5 + j], t);
    }
    out[gid] = v + t + tb[d];
}

// ---------------- launch ----------------
static void* sym_addr(const void* sym) {
    void* p = nullptr;
    cudaGetSymbolAddress(&p, sym);
    return p;
}

extern "C" void kernel_launch(void* const* d_in, const int* in_sizes, int n_in,
                              void* d_out, int out_size)
{
    const float* x    = (const float*)d_in[0];
    const float* qw   = (const float*)d_in[1];  const float* qb  = (const float*)d_in[2];
    const float* kw   = (const float*)d_in[3];  const float* kb  = (const float*)d_in[4];
    const float* vw   = (const float*)d_in[5];  const float* vb  = (const float*)d_in[6];
    const float* ow   = (const float*)d_in[7];  const float* ob  = (const float*)d_in[8];
    const float* n1g  = (const float*)d_in[9];  const float* n1b = (const float*)d_in[10];
    const float* n2g  = (const float*)d_in[11]; const float* n2b = (const float*)d_in[12];
    const float* alpha= (const float*)d_in[13];
    const float* dw7  = (const float*)d_in[14];
    const float* dw25 = (const float*)d_in[15];
    const float* dw49 = (const float*)d_in[16];
    const float* rw   = (const float*)d_in[17];
    const float* ew1  = (const float*)d_in[18]; const float* eb1 = (const float*)d_in[19];
    const float* ew2  = (const float*)d_in[20]; const float* eb2 = (const float*)d_in[21];
    const float* tw   = (const float*)d_in[22]; const float* tb  = (const float*)d_in[23];
    float* out = (float*)d_out;

    float* pS   = (float*)sym_addr(g_S);
    float* pBuf = (float*)sym_addr(g_buf);
    __nv_bfloat16* pBufH = (__nv_bfloat16*)sym_addr(g_bufh);
    float* pQKV = (float*)sym_addr(g_qkv);
    __nv_bfloat16* pYH = (__nv_bfloat16*)sym_addr(g_yh);
    float* pXs  = (float*)sym_addr(g_xs);
    __nv_bfloat16* pHH = (__nv_bfloat16*)sym_addr(g_hh);
    float* pMoe = (float*)sym_addr(g_moe);
    int*   pEL  = (int*)sym_addr(g_elist);
    int*   pEC  = (int*)sym_addr(g_ecnt);
    __nv_bfloat16* pRW4 = (__nv_bfloat16*)sym_addr(g_rw4h);
    __nv_bfloat16* pRE1 = (__nv_bfloat16*)sym_addr(g_rew1h);
    __nv_bfloat16* pRE2 = (__nv_bfloat16*)sym_addr(g_rew2h);
    float* pQKVB= (float*)sym_addr(g_qkvb);
    (void)in_sizes; (void)n_in;

    cudaFuncSetAttribute(attn_tc_kernel, cudaFuncAttributeMaxDynamicSharedMemorySize, ATT_SMEM);
    cudaFuncSetAttribute(tc_gemm<0>, cudaFuncAttributeMaxDynamicSharedMemorySize, TCG_SMEM);
    cudaFuncSetAttribute(tc_gemm<1>, cudaFuncAttributeMaxDynamicSharedMemorySize, TCG_SMEM);
    cudaFuncSetAttribute(tc_gemm<2>, cudaFuncAttributeMaxDynamicSharedMemorySize, TCG_SMEM);

    // 0) pre-round weights to bf16 (wide stores) + concat qkv bias
    const int DD8 = D_MODEL*D_MODEL/8;                       // 131072
    const int E18 = NUM_EXPERTS*MOE_HIDDEN*D_MODEL/8;
    const int E28 = NUM_EXPERTS*D_MODEL*MOE_HIDDEN/8;
    dim3 grw((DD8+255)/256, 4);
    round8x4_kernel<<<grw, 256>>>(qw, kw, vw, ow, pRW4, DD8);
    round8_kernel<<<(E18+255)/256, 256>>>(ew1, pRE1, E18);
    round8_kernel<<<(E28+255)/256, 256>>>(ew2, pRE2, E28);
    cudaMemcpyAsync(pQKVB,            qb, D_MODEL*4, cudaMemcpyDeviceToDevice);
    cudaMemcpyAsync(pQKVB + D_MODEL,  kb, D_MODEL*4, cudaMemcpyDeviceToDevice);
    cudaMemcpyAsync(pQKVB + 2*D_MODEL,vb, D_MODEL*4, cudaMemcpyDeviceToDevice);

    // 1) decomposition -> g_Tr, g_S
    dim3 dgrid(D_MODEL/DC_DT, SEQ/DC_NT, BATCH);
    decomp_kernel<<<dgrid, 256>>>(x, alpha, dw7, dw25, dw49);

    // 2) LN1(S) -> bf16 Sn
    ln_kernel<<<TOKENS, 256>>>(pS, n1g, n1b, pBufH, nullptr);

    // 3) fused QKV projection: one bf16 GEMM, N=3072
    dim3 gq(QKV_LD/128, TOKENS/128, 1);
    tc_gemm<0><<<gq, 256, TCG_SMEM>>>(pBufH, pRW4, pQKVB, pQKV, D_MODEL, QKV_LD,
                                      nullptr, nullptr, nullptr, 0, 0, 0, 0);

    // 4) attention (tf32, q-tile 128), y -> bf16
    dim3 agrid(BATCH*NHEAD, SEQ/128);
    attn_tc_kernel<<<agrid, 256, ATT_SMEM>>>();

    // 5) O projection + residual S -> g_xs
    dim3 go(D_MODEL/128, TOKENS/128, 1);
    tc_gemm<2><<<go, 256, TCG_SMEM>>>(pYH, pRW4 + (size_t)3*D_MODEL*D_MODEL, ob, pXs,
                                      D_MODEL, D_MODEL,
                                      pS, nullptr, nullptr, 0, 0, 0, 0);

    // 6) LN2 -> bf16 xf (GEMM) + fp32 xf (router)
    ln_kernel<<<TOKENS, 256>>>(pXs, n2g, n2b, pBufH, pBuf);

    // 7) router (fp32 xf) + routing lists + aux
    router_kernel<<<TOKENS/8, 256>>>(pBuf, rw);
    route_kernel<<<1, 128>>>();
    aux_kernel<<<1, 256>>>(out, out_size);

    // 8) MoE FFN: fused bf16 GEMM1 + fused compact GEMM2 (blockIdx.z = expert)
    dim3 gh1(MOE_HIDDEN/128, TOKENS/128, NUM_EXPERTS);
    tc_gemm<1><<<gh1, 256, TCG_SMEM>>>(pBufH, pRE1, eb1, (float*)pHH,
                                       D_MODEL, MOE_HIDDEN,
                                       nullptr, pEL, pEC,
                                       0,
                                       (size_t)MOE_HIDDEN*D_MODEL, MOE_HIDDEN,
                                       (size_t)TOKENS*MOE_HIDDEN);
    dim3 gh2(D_MODEL/128, TOKENS/128, NUM_EXPERTS);
    tc_gemm<0><<<gh2, 256, TCG_SMEM>>>(pHH, pRE2, eb2, pMoe,
                                       MOE_HIDDEN, D_MODEL,
                                       nullptr, nullptr, pEC,
                                       (size_t)TOKENS*MOE_HIDDEN,
                                       (size_t)D_MODEL*MOE_HIDDEN, D_MODEL,
                                       (size_t)TOKENS*D_MODEL);

    // 9) final: xs + MoE combine + trend conv + tb
    final_kernel<<<(BND + 255)/256, 256>>>(tw, tb, out);
}

// round 17
// speedup vs baseline: 2.9443x; 1.0566x over previous
#include <cuda_runtime.h>
#include <cuda_bf16.h>
#include <math.h>
#include <stdint.h>

#define D_MODEL 1024
#define NHEAD 16
#define HEAD_DIM 64
#define MOE_HIDDEN 2048
#define NUM_EXPERTS 4
#define BATCH 8
#define SEQ 1024
#define TOKENS (BATCH*SEQ)          /* 8192  */
#define BND (TOKENS*D_MODEL)        /* 8388608 */
#define QKV_LD (3*D_MODEL)
#define LN_EPS 1e-5f

// ---------------- scratch (device globals; no allocation) ----------------
__device__ float g_Tr[BND];
__device__ float g_S[BND];
__device__ float g_buf[BND];                    // LN2 fp32 (router)
__device__ __nv_bfloat16 g_bufh[BND];           // LN bf16 (GEMM A)
__device__ float g_qkv[TOKENS*QKV_LD];          // packed q|k|v per token (fp32)
__device__ __nv_bfloat16 g_yh[BND];             // attention out, bf16 (O-proj A)
__device__ float g_xs[BND];
__device__ __nv_bfloat16 g_hh[NUM_EXPERTS*TOKENS*MOE_HIDDEN];  // per-expert hidden (bf16)
__device__ float g_moe[NUM_EXPERTS*TOKENS*D_MODEL];            // per-expert compact GEMM2 out
__device__ float g_w[TOKENS*NUM_EXPERTS];
__device__ float g_gates[TOKENS*NUM_EXPERTS];
__device__ int   g_elist[NUM_EXPERTS*TOKENS];
__device__ int   g_epos[2*TOKENS];              // token -> (e*TOKENS+pos) x2, ascending e
__device__ int   g_ecnt[NUM_EXPERTS];
__device__ float g_qkvb[QKV_LD];                // concat qb|kb|vb (fp32)
// bf16-pre-rounded weights
__device__ __nv_bfloat16 g_rw4h[4*D_MODEL*D_MODEL];       // qw,kw,vw,ow (contiguous)
__device__ __nv_bfloat16 g_rew1h[NUM_EXPERTS*MOE_HIDDEN*D_MODEL];
__device__ __nv_bfloat16 g_rew2h[NUM_EXPERTS*D_MODEL*MOE_HIDDEN];

// ============================================================
// helpers
// ============================================================
__device__ __forceinline__ uint32_t f2tf32(float f) {
    uint32_t u; asm("cvt.rna.tf32.f32 %0, %1;" : "=r"(u) : "f"(f)); return u;
}
__device__ __forceinline__ void mma_tf32(float* c, const uint32_t* a, const uint32_t* b) {
    asm volatile(
        "mma.sync.aligned.m16n8k8.row.col.f32.tf32.tf32.f32 "
        "{%0,%1,%2,%3}, {%4,%5,%6,%7}, {%8,%9}, {%0,%1,%2,%3};"
        : "+f"(c[0]), "+f"(c[1]), "+f"(c[2]), "+f"(c[3])
        : "r"(a[0]), "r"(a[1]), "r"(a[2]), "r"(a[3]), "r"(b[0]), "r"(b[1]));
}
__device__ __forceinline__ void mma_bf16(float* c, const uint32_t* a, const uint32_t* b) {
    asm volatile(
        "mma.sync.aligned.m16n8k16.row.col.f32.bf16.bf16.f32 "
        "{%0,%1,%2,%3}, {%4,%5,%6,%7}, {%8,%9}, {%0,%1,%2,%3};"
        : "+f"(c[0]), "+f"(c[1]), "+f"(c[2]), "+f"(c[3])
        : "r"(a[0]), "r"(a[1]), "r"(a[2]), "r"(a[3]), "r"(b[0]), "r"(b[1]));
}
__device__ __forceinline__ void ldsm_x4(uint32_t* r, uint32_t addr) {
    asm volatile("ldmatrix.sync.aligned.m8n8.x4.shared.b16 {%0,%1,%2,%3}, [%4];"
        : "=r"(r[0]), "=r"(r[1]), "=r"(r[2]), "=r"(r[3]) : "r"(addr));
}
__device__ __forceinline__ void ldsm_x2(uint32_t* r, uint32_t addr) {
    asm volatile("ldmatrix.sync.aligned.m8n8.x2.shared.b16 {%0,%1}, [%2];"
        : "=r"(r[0]), "=r"(r[1]) : "r"(addr));
}
__device__ __forceinline__ uint32_t smem_u32(const void* p) {
    uint32_t a;
    asm("{ .reg .u64 t; cvta.to.shared.u64 t, %1; cvt.u32.u64 %0, t; }" : "=r"(a) : "l"(p));
    return a;
}
__device__ __forceinline__ void cp16(uint32_t dst, const void* src) {
    asm volatile("cp.async.cg.shared.global [%0], [%1], 16;" :: "r"(dst), "l"(src));
}
__device__ __forceinline__ uint32_t pack_bf2(float a, float b) {
    __nv_bfloat162 h = { __float2bfloat16(a), __float2bfloat16(b) };
    return *(uint32_t*)&h;
}

// ---------------- weight bf16 pre-round: 8 floats -> one 16B store ----------------
__global__ void __launch_bounds__(256) round8_kernel(
    const float* __restrict__ src, __nv_bfloat16* __restrict__ dst, int n8)
{
    const int i = blockIdx.x*256 + threadIdx.x;
    if (i < n8) {
        const float4 a = ((const float4*)src)[2*i];
        const float4 b = ((const float4*)src)[2*i+1];
        uint4 o;
        o.x = pack_bf2(a.x, a.y); o.y = pack_bf2(a.z, a.w);
        o.z = pack_bf2(b.x, b.y); o.w = pack_bf2(b.z, b.w);
        ((uint4*)dst)[i] = o;
    }
}
__global__ void __launch_bounds__(256) round8x4_kernel(
    const float* __restrict__ s0, const float* __restrict__ s1,
    const float* __restrict__ s2, const float* __restrict__ s3,
    __nv_bfloat16* __restrict__ dst, int n8)
{
    const int i = blockIdx.x*256 + threadIdx.x;
    if (i >= n8) return;
    const float* src = (blockIdx.y == 0) ? s0 : (blockIdx.y == 1) ? s1
                     : (blockIdx.y == 2) ? s2 : s3;
    const float4 a = ((const float4*)src)[2*i];
    const float4 b = ((const float4*)src)[2*i+1];
    uint4 o;
    o.x = pack_bf2(a.x, a.y); o.y = pack_bf2(a.z, a.w);
    o.z = pack_bf2(b.x, b.y); o.w = pack_bf2(b.z, b.w);
    ((uint4*)(dst + (size_t)blockIdx.y * n8 * 8))[i] = o;
}

// ============================================================
// bf16 mma.sync GEMM (unchanged from R16)
// ============================================================
#define TCG_LDA 36
#define ST_WORDS (128*TCG_LDA)
#define TCG_SMEM (3*2*ST_WORDS*4)         /* 110592 B */

template<int EPI>
__global__ void __launch_bounds__(256, 2) tc_gemm(
    const __nv_bfloat16* __restrict__ A, const __nv_bfloat16* __restrict__ B,
    const float* __restrict__ bias, float* __restrict__ C,
    int K, int Nn,
    const float* __restrict__ resid,
    const int* __restrict__ aidx, const int* __restrict__ cntp,
    size_t astride, size_t bstride, int bias_stride, size_t cstride)
{
    extern __shared__ uint32_t smu[];
    const int tid = threadIdx.x;
    const int ez = blockIdx.z;
    const int bm = blockIdx.y * 128, bn = blockIdx.x * 128;
    if (cntp) { const int cnt = cntp[ez]; if (bm >= ((cnt + 127) & ~127)) return; }
    A    += (size_t)ez * astride;
    B    += (size_t)ez * bstride;
    bias += (size_t)ez * bias_stride;
    float* Cf = C + (EPI == 1 ? (size_t)0 : (size_t)ez * cstride);
    __nv_bfloat16* Cb = (__nv_bfloat16*)C + (EPI == 1 ? (size_t)ez * cstride : (size_t)0);
    if (aidx) aidx += ez * TOKENS;

    const int warp = tid >> 5, lane = tid & 31;
    const int wm = (warp >> 2) * 64, wn = (warp & 3) * 32;
    const int g = lane >> 2, t = lane & 3;

    const int lr8 = tid >> 3;
    const int lc8 = tid & 7;
    const __nv_bfloat16* AgP[4];
    const __nv_bfloat16* BgP[4];
    uint32_t oaS[4];
    #pragma unroll
    for (int j = 0; j < 4; j++) {
        const int row = lr8 + 32*j;
        int ra = bm + row;
        if (aidx) ra = aidx[ra];
        AgP[j] = A + (size_t)ra * K + lc8 * 8;
        BgP[j] = B + (size_t)(bn + row) * K + lc8 * 8;
        oaS[j] = (uint32_t)(row*TCG_LDA + lc8*4)*4;
    }

    const uint32_t sbase = smem_u32(smu);
    const uint32_t obB = ST_WORDS*4;
    const uint32_t lma = ((wm + (lane & 15))*TCG_LDA + ((lane >> 4) << 2)) * 4;
    const uint32_t lmb = obB + ((wn + (lane & 7))*TCG_LDA + ((lane & 8) ? 4 : 0)) * 4;

    float acc[4][4][4];
    #pragma unroll
    for (int i = 0; i < 4; i++)
        #pragma unroll
        for (int j = 0; j < 4; j++)
            #pragma unroll
            for (int r = 0; r < 4; r++) acc[i][j][r] = 0.f;

    const int NT = K >> 6;
    #pragma unroll
    for (int s = 0; s < 2; s++) {
        const uint32_t sb = sbase + s*2*ST_WORDS*4;
        const int ko = s*64;
        #pragma unroll
        for (int j = 0; j < 4; j++) {
            cp16(sb + oaS[j], AgP[j] + ko);
            cp16(sb + obB + oaS[j], BgP[j] + ko);
        }
        asm volatile("cp.async.commit_group;");
    }

    int stage = 0;
    for (int kt = 0; kt < NT; kt++) {
        asm volatile("cp.async.wait_group 1;" ::: "memory");
        __syncthreads();
        const uint32_t stb = sbase + stage*2*ST_WORDS*4;

        #pragma unroll
        for (int ks = 0; ks < 4; ks++) {
            const uint32_t kb4 = (uint32_t)ks * 32;
            uint32_t af[4][4], bf[4][2];
            #pragma unroll
            for (int mf = 0; mf < 4; mf++)
                ldsm_x4(af[mf], stb + lma + (uint32_t)(mf*16*TCG_LDA)*4 + kb4);
            #pragma unroll
            for (int nf = 0; nf < 4; nf++)
                ldsm_x2(bf[nf], stb + lmb + (uint32_t)(nf*8*TCG_LDA)*4 + kb4);
            #pragma unroll
            for (int mf = 0; mf < 4; mf++)
                #pragma unroll
                for (int nf = 0; nf < 4; nf++)
                    mma_bf16(acc[mf][nf], af[mf], bf[nf]);
        }

        if (kt + 2 < NT) {
            const int ns = (stage + 2 >= 3) ? stage - 1 : stage + 2;
            const int ko = (kt + 2) * 64;
            const uint32_t sb = sbase + ns*2*ST_WORDS*4;
            #pragma unroll
            for (int j = 0; j < 4; j++) {
                cp16(sb + oaS[j], AgP[j] + ko);
                cp16(sb + obB + oaS[j], BgP[j] + ko);
            }
            asm volatile("cp.async.commit_group;");
        } else {
            asm volatile("cp.async.commit_group;");
        }
        stage = (stage + 1 == 3) ? 0 : stage + 1;
    }

    // ---- epilogue ----
    #pragma unroll
    for (int mf = 0; mf < 4; mf++) {
        const int mp0 = bm + wm + mf*16 + g;
        const int mp1 = mp0 + 8;
        #pragma unroll
        for (int nf = 0; nf < 4; nf++) {
            const int n0 = bn + wn + nf*8 + 2*t;
            const float b0 = bias[n0], b1 = bias[n0 + 1];
            float v0 = acc[mf][nf][0] + b0;
            float v1 = acc[mf][nf][1] + b1;
            float v2 = acc[mf][nf][2] + b0;
            float v3 = acc[mf][nf][3] + b1;
            const size_t i0 = (size_t)mp0 * Nn + n0;
            const size_t i1 = (size_t)mp1 * Nn + n0;
            if (EPI == 0) {
                Cf[i0] = v0; Cf[i0+1] = v1; Cf[i1] = v2; Cf[i1+1] = v3;
            } else if (EPI == 1) {
                Cb[i0]   = __float2bfloat16(0.5f*v0*(1.0f + erff(v0*0.70710678118654752f)));
                Cb[i0+1] = __float2bfloat16(0.5f*v1*(1.0f + erff(v1*0.70710678118654752f)));
                Cb[i1]   = __float2bfloat16(0.5f*v2*(1.0f + erff(v2*0.70710678118654752f)));
                Cb[i1+1] = __float2bfloat16(0.5f*v3*(1.0f + erff(v3*0.70710678118654752f)));
            } else {
                Cf[i0] = v0 + resid[i0]; Cf[i0+1] = v1 + resid[i0+1];
                Cf[i1] = v2 + resid[i1]; Cf[i1+1] = v3 + resid[i1+1];
            }
        }
    }
}

// ============================================================
// Tensor-core ALiBi flash attention (tf32) — unchanged (R16)
// ============================================================
#define ATT_LDK 68
#define ATT_LDV 69
#define ATT_SMEM ((64*ATT_LDK + 64*ATT_LDV + 128*ATT_LDK)*4)   /* 69888 B */

__global__ void __launch_bounds__(256, 2) attn_tc_kernel()
{
    extern __shared__ uint32_t smA[];
    uint32_t* Ks = smA;
    uint32_t* Vt = smA + 64*ATT_LDK;
    uint32_t* Ps = smA + 64*ATT_LDK + 64*ATT_LDV;     // 128 rows
    const int tid = threadIdx.x;
    const int warp = tid >> 5, lane = tid & 31;
    const int g = lane >> 2, t = lane & 3;
    const int bh = blockIdx.x;
    const int b = bh >> 4, h = bh & 15;
    const int q0 = blockIdx.y * 128;
    const float slope = exp2f(-0.5f*(float)(h + 1));

    for (int i = tid; i < 2048; i += 256) {
        const int row = i >> 4, c4 = (i & 15) * 4;
        const float4 qv = *(const float4*)(g_qkv + ((size_t)(b*SEQ + q0 + row))*QKV_LD + h*64 + c4);
        uint32_t* d = Ps + row*ATT_LDK + c4;
        d[0] = f2tf32(qv.x*0.125f); d[1] = f2tf32(qv.y*0.125f);
        d[2] = f2tf32(qv.z*0.125f); d[3] = f2tf32(qv.w*0.125f);
    }
    __syncthreads();
    uint32_t qf[8][4];
    #pragma unroll
    for (int k = 0; k < 8; k++) {
        const uint32_t* base = Ps + (warp*16 + g)*ATT_LDK + k*8 + t;
        qf[k][0] = base[0]; qf[k][1] = base[8*ATT_LDK];
        qf[k][2] = base[4]; qf[k][3] = base[8*ATT_LDK + 4];
    }

    float o[8][4];
    #pragma unroll
    for (int nf = 0; nf < 8; nf++)
        #pragma unroll
        for (int r = 0; r < 4; r++) o[nf][r] = 0.f;
    float l0 = 0.f, l1 = 0.f;
    const int qg0 = q0 + warp*16 + g, qg1 = qg0 + 8;

    for (int kt = 0; kt < 16; kt++) {
        __syncthreads();
        for (int i = tid; i < 1024; i += 256) {
            const int row = i >> 4, c4 = (i & 15) * 4;
            const size_t gofs = ((size_t)(b*SEQ + kt*64 + row))*QKV_LD + h*64 + c4;
            const float4 kv = *(const float4*)(g_qkv + gofs + D_MODEL);
            uint32_t* dk = Ks + row*ATT_LDK + c4;
            dk[0] = f2tf32(kv.x); dk[1] = f2tf32(kv.y);
            dk[2] = f2tf32(kv.z); dk[3] = f2tf32(kv.w);
            const float4 vv = *(const float4*)(g_qkv + gofs + 2*D_MODEL);
            Vt[(c4+0)*ATT_LDV + row] = f2tf32(vv.x);
            Vt[(c4+1)*ATT_LDV + row] = f2tf32(vv.y);
            Vt[(c4+2)*ATT_LDV + row] = f2tf32(vv.z);
            Vt[(c4+3)*ATT_LDV + row] = f2tf32(vv.w);
        }
        __syncthreads();

        float s[8][4];
        #pragma unroll
        for (int nf = 0; nf < 8; nf++)
            #pragma unroll
            for (int r = 0; r < 4; r++) s[nf][r] = 0.f;
        #pragma unroll
        for (int k = 0; k < 8; k++) {
            uint32_t bf[8][2];
            #pragma unroll
            for (int nf = 0; nf < 8; nf++) {
                const uint32_t* base = Ks + (nf*8 + g)*ATT_LDK + k*8 + t;
                bf[nf][0] = base[0]; bf[nf][1] = base[4];
            }
            #pragma unroll
            for (int nf = 0; nf < 8; nf++) mma_tf32(s[nf], qf[k], bf[nf]);
        }

        #pragma unroll
        for (int nf = 0; nf < 8; nf++) {
            const int jg = kt*64 + nf*8 + 2*t;
            const int d00 = jg - qg0, d10 = jg - qg1;
            const float p00 = __expf(s[nf][0] - slope*(float)(d00   > 0 ? d00   : 0));
            const float p01 = __expf(s[nf][1] - slope*(float)(d00+1 > 0 ? d00+1 : 0));
            const float p10 = __expf(s[nf][2] - slope*(float)(d10   > 0 ? d10   : 0));
            const float p11 = __expf(s[nf][3] - slope*(float)(d10+1 > 0 ? d10+1 : 0));
            l0 += p00 + p01; l1 += p10 + p11;
            uint32_t* pr0 = Ps + (warp*16 + g)*ATT_LDK + nf*8 + 2*t;
            pr0[0] = f2tf32(p00); pr0[1] = f2tf32(p01);
            pr0[8*ATT_LDK] = f2tf32(p10); pr0[8*ATT_LDK + 1] = f2tf32(p11);
        }
        __syncwarp();

        #pragma unroll
        for (int k = 0; k < 8; k++) {
            uint32_t pf[4];
            const uint32_t* pb = Ps + (warp*16 + g)*ATT_LDK + k*8 + t;
            pf[0] = pb[0]; pf[1] = pb[8*ATT_LDK];
            pf[2] = pb[4]; pf[3] = pb[8*ATT_LDK + 4];
            #pragma unroll
            for (int nf = 0; nf < 8; nf++) {
                const uint32_t* vb = Vt + (nf*8 + g)*ATT_LDV + k*8 + t;
                uint32_t bf[2] = { vb[0], vb[4] };
                mma_tf32(o[nf], pf, bf);
            }
        }
    }

    l0 += __shfl_xor_sync(0xffffffffu, l0, 1);
    l0 += __shfl_xor_sync(0xffffffffu, l0, 2);
    l1 += __shfl_xor_sync(0xffffffffu, l1, 1);
    l1 += __shfl_xor_sync(0xffffffffu, l1, 2);
    const float inv0 = 1.f/l0, inv1 = 1.f/l1;
    __nv_bfloat16* y0 = g_yh + ((size_t)(b*SEQ + qg0))*D_MODEL + h*64;
    __nv_bfloat16* y1 = g_yh + ((size_t)(b*SEQ + qg1))*D_MODEL + h*64;
    #pragma unroll
    for (int nf = 0; nf < 8; nf++) {
        const int c = nf*8 + 2*t;
        y0[c]   = __float2bfloat16(o[nf][0]*inv0);
        y0[c+1] = __float2bfloat16(o[nf][1]*inv0);
        y1[c]   = __float2bfloat16(o[nf][2]*inv1);
        y1[c+1] = __float2bfloat16(o[nf][3]*inv1);
    }
}

// ---------------- Decomp1D v2: combined 49-tap kernel, register weights ----------------
#define DC_NT 128
#define DC_DT 32
#define DC_HALO 24
__global__ void __launch_bounds__(256) decomp_kernel(
    const float* __restrict__ x, const float* __restrict__ alpha,
    const float* __restrict__ dw7, const float* __restrict__ dw25,
    const float* __restrict__ dw49)
{
    __shared__ float sx[DC_NT + 2*DC_HALO][DC_DT];   // 176 x 32
    __shared__ float sW[DC_DT][49];
    const int b  = blockIdx.z;
    const int n0 = blockIdx.y * DC_NT;
    const int d0 = blockIdx.x * DC_DT;
    const int tid = threadIdx.x;

    for (int i = tid; i < (DC_NT + 2*DC_HALO)*DC_DT; i += 256) {
        int r = i / DC_DT, c = i % DC_DT;
        int n = n0 + r - DC_HALO;
        if (n < 0)    n = -n;              // reflect (edge excluded)
        if (n >= SEQ) n = 2*SEQ - 2 - n;
        sx[r][c] = x[((size_t)b*SEQ + n)*D_MODEL + d0 + c];
    }

    const float a0 = alpha[0], a1 = alpha[1], a2 = alpha[2];
    const float mx = fmaxf(a0, fmaxf(a1, a2));
    const float e0 = __expf(a0-mx), e1 = __expf(a1-mx), e2 = __expf(a2-mx);
    const float inv = 1.f/(e0+e1+e2);
    const float w0 = e0*inv, w1 = e1*inv, w2 = e2*inv;

    // combined kernel: W[j] = w2*k49[j] + w1*k25[j-12] + w0*k7[j-21]
    for (int i = tid; i < DC_DT*49; i += 256) {
        const int d = i / 49, j = i % 49;
        float W = w2 * dw49[(d0 + d)*49 + j];
        if (j >= 12 && j <= 36) W = fmaf(w1, dw25[(d0 + d)*25 + (j - 12)], W);
        if (j >= 21 && j <= 27) W = fmaf(w0, dw7 [(d0 + d)*7  + (j - 21)], W);
        sW[d][j] = W;
    }
    __syncthreads();

    const int c  = tid & 31;           // channel (lane-distinct -> conflict-free)
    const int pb = (tid >> 5) * 16;    // 16 consecutive outputs per thread
    float w[49];
    #pragma unroll
    for (int j = 0; j < 49; j++) w[j] = sW[c][j];
    float acc[16];
    #pragma unroll
    for (int o = 0; o < 16; o++) acc[o] = 0.f;

    #pragma unroll
    for (int s = 0; s < 64; s++) {
        const float v = sx[pb + s][c];
        #pragma unroll
        for (int o = 0; o < 16; o++) {
            const int j = s - o;
            if (j >= 0 && j < 49) acc[o] = fmaf(v, w[j], acc[o]);
        }
    }

    #pragma unroll
    for (int o = 0; o < 16; o++) {
        const size_t idx = ((size_t)b*SEQ + n0 + pb + o)*D_MODEL + d0 + c;
        g_Tr[idx] = acc[o];
        g_S[idx]  = sx[pb + o + DC_HALO][c] - acc[o];
    }
}

// ---------------- LayerNorm v2: warp-per-row, registers, shuffle reduce ----------------
__global__ void __launch_bounds__(256) ln_kernel(
    const float* __restrict__ in, const float* __restrict__ gam,
    const float* __restrict__ bet, __nv_bfloat16* __restrict__ outh,
    float* __restrict__ outf)
{
    const int warp = threadIdx.x >> 5, lane = threadIdx.x & 31;
    const int t = blockIdx.x*8 + warp;
    const float* ip = in + (size_t)t*D_MODEL;
    float4 v[8];
    float s = 0.f;
    #pragma unroll
    for (int i = 0; i < 8; i++) {
        v[i] = ((const float4*)ip)[lane + i*32];
        s += (v[i].x + v[i].y) + (v[i].z + v[i].w);
    }
    #pragma unroll
    for (int o = 16; o > 0; o >>= 1) s += __shfl_xor_sync(0xffffffffu, s, o);
    const float mean = s * (1.f/D_MODEL);
    float vs = 0.f;
    #pragma unroll
    for (int i = 0; i < 8; i++) {
        const float dx = v[i].x-mean, dy = v[i].y-mean, dz = v[i].z-mean, dw = v[i].w-mean;
        vs += (dx*dx + dy*dy) + (dz*dz + dw*dw);
    }
    #pragma unroll
    for (int o = 16; o > 0; o >>= 1) vs += __shfl_xor_sync(0xffffffffu, vs, o);
    const float rstd = rsqrtf(vs * (1.f/D_MODEL) + LN_EPS);

    __nv_bfloat16* oh = outh + (size_t)t*D_MODEL;
    float* of = outf ? outf + (size_t)t*D_MODEL : nullptr;
    #pragma unroll
    for (int i = 0; i < 8; i++) {
        const int d4 = (lane + i*32) * 4;
        const float r0 = (v[i].x-mean)*rstd*gam[d4]   + bet[d4];
        const float r1 = (v[i].y-mean)*rstd*gam[d4+1] + bet[d4+1];
        const float r2 = (v[i].z-mean)*rstd*gam[d4+2] + bet[d4+2];
        const float r3 = (v[i].w-mean)*rstd*gam[d4+3] + bet[d4+3];
        uint2 pk = { pack_bf2(r0, r1), pack_bf2(r2, r3) };
        ((uint2*)oh)[lane + i*32] = pk;
        if (of) {
            float4 fv = { r0, r1, r2, r3 };
            ((float4*)of)[lane + i*32] = fv;
        }
    }
}

// ---------------- Router (fp32 xf) ----------------
__global__ void __launch_bounds__(256) router_kernel(
    const float* __restrict__ xf, const float* __restrict__ rw)
{
    const int warp = threadIdx.x / 32, lane = threadIdx.x % 32;
    const int t = blockIdx.x*8 + warp;
    const float* xp = xf + (size_t)t*D_MODEL;
    float logit[NUM_EXPERTS];
    #pragma unroll
    for (int e = 0; e < NUM_EXPERTS; e++) {
        float p = 0.f;
        for (int d = lane; d < D_MODEL; d += 32) p = fmaf(xp[d], rw[e*D_MODEL + d], p);
        #pragma unroll
        for (int o = 16; o > 0; o >>= 1) p += __shfl_xor_sync(0xffffffffu, p, o);
        logit[e] = p;
    }
    if (lane == 0) {
        float mx = logit[0];
        #pragma unroll
        for (int e = 1; e < NUM_EXPERTS; e++) mx = fmaxf(mx, logit[e]);
        float g[NUM_EXPERTS]; float s = 0.f;
        #pragma unroll
        for (int e = 0; e < NUM_EXPERTS; e++) { g[e] = expf(logit[e]-mx); s += g[e]; }
        #pragma unroll
        for (int e = 0; e < NUM_EXPERTS; e++) g[e] /= s;
        int i0 = 0;
        #pragma unroll
        for (int e = 1; e < NUM_EXPERTS; e++) if (g[e] > g[i0]) i0 = e;
        int i1 = -1;
        #pragma unroll
        for (int e = 0; e < NUM_EXPERTS; e++)
            if (e != i0 && (i1 < 0 || g[e] > g[i1])) i1 = e;
        const float s2 = fmaxf(g[i0] + g[i1], 1e-9f);
        float w[NUM_EXPERTS] = {0.f, 0.f, 0.f, 0.f};
        w[i0] = g[i0]/s2; w[i1] = g[i1]/s2;
        #pragma unroll
        for (int e = 0; e < NUM_EXPERTS; e++) {
            g_gates[t*NUM_EXPERTS + e] = g[e];
            g_w[t*NUM_EXPERTS + e]     = w[e];
        }
    }
}

// ---------------- routing lists + inverse (token -> expert,pos) map ----------------
__global__ void __launch_bounds__(128) route_kernel()
{
    const int e = threadIdx.x >> 5, lane = threadIdx.x & 31;
    int cnt = 0;
    for (int base = 0; base < TOKENS; base += 32) {
        const int t = base + lane;
        const bool sel = g_w[t*NUM_EXPERTS + e] > 0.f;
        const unsigned m = __ballot_sync(0xffffffffu, sel);
        if (sel) {
            const int pos = cnt + __popc(m & ((1u << lane) - 1u));
            g_elist[e*TOKENS + pos] = t;
            int lower = 0;
            #pragma unroll
            for (int e2 = 0; e2 < NUM_EXPERTS; e2++)
                if (e2 < e && g_w[t*NUM_EXPERTS + e2] > 0.f) lower++;
            g_epos[2*t + lower] = e*TOKENS + pos;
        }
        cnt += __popc(m);
    }
    __syncwarp();
    const int padded = (cnt + 127) & ~127;
    if (cnt > 0) {
        const int last = g_elist[e*TOKENS + cnt - 1];
        for (int i = cnt + lane; i < padded; i += 32) g_elist[e*TOKENS + i] = last;
    }
    if (lane == 0) g_ecnt[e] = cnt;
}

// ---------------- aux ----------------
__global__ void __launch_bounds__(256) aux_kernel(float* __restrict__ out, int out_size)
{
    __shared__ float rg[NUM_EXPERTS][256];
    __shared__ float rc[NUM_EXPERTS][256];
    const int tid = threadIdx.x;
    float gs[NUM_EXPERTS] = {0,0,0,0}, cs[NUM_EXPERTS] = {0,0,0,0};
    for (int t = tid; t < TOKENS; t += 256) {
        #pragma unroll
        for (int e = 0; e < NUM_EXPERTS; e++) {
            gs[e] += g_gates[t*NUM_EXPERTS + e];
            cs[e] += (g_w[t*NUM_EXPERTS + e] > 0.f) ? 1.f : 0.f;
        }
    }
    #pragma unroll
    for (int e = 0; e < NUM_EXPERTS; e++) { rg[e][tid] = gs[e]; rc[e][tid] = cs[e]; }
    __syncthreads();
    for (int o = 128; o > 0; o >>= 1) {
        if (tid < o)
            #pragma unroll
            for (int e = 0; e < NUM_EXPERTS; e++) { rg[e][tid] += rg[e][tid+o]; rc[e][tid] += rc[e][tid+o]; }
        __syncthreads();
    }
    if (tid == 0 && out_size > BND) {
        float aux = 0.f;
        #pragma unroll
        for (int e = 0; e < NUM_EXPERTS; e++)
            aux += (rg[e][0]*(1.f/TOKENS)) * (rc[e][0]*(1.f/TOKENS));
        out[out_size - 1] = (float)NUM_EXPERTS * aux;
    }
}

// ---------------- final: xs + MoE combine + trend conv + tb ----------------
__global__ void __launch_bounds__(256) final_kernel(
    const float* __restrict__ tw, const float* __restrict__ tb, float* __restrict__ out)
{
    const size_t gid = (size_t)blockIdx.x*256 + threadIdx.x;
    if (gid >= (size_t)BND) return;
    const int d = (int)(gid % D_MODEL);
    const int n = (int)((gid / D_MODEL) % SEQ);
    const int tok = (int)(gid >> 10);
    const int r0 = g_epos[2*tok], r1 = g_epos[2*tok + 1];
    const float w0 = g_w[tok*NUM_EXPERTS + (r0 >> 13)];
    const float w1 = g_w[tok*NUM_EXPERTS + (r1 >> 13)];
    float v = fmaf(g_moe[(size_t)r0*D_MODEL + d], w0, g_xs[gid]);
    v = fmaf(g_moe[(size_t)r1*D_MODEL + d], w1, v);
    float t = 0.f;
    #pragma unroll
    for (int j = 0; j < 5; j++) {
        const int nn = n - 2 + j;
        if (nn >= 0 && nn < SEQ)
            t = fmaf(g_Tr[gid + (size_t)(j-2)*D_MODEL], tw[d*5 + j], t);
    }
    out[gid] = v + t + tb[d];
}

// ---------------- launch ----------------
static void* sym_addr(const void* sym) {
    void* p = nullptr;
    cudaGetSymbolAddress(&p, sym);
    return p;
}

extern "C" void kernel_launch(void* const* d_in, const int* in_sizes, int n_in,
                              void* d_out, int out_size)
{
    const float* x    = (const float*)d_in[0];
    const float* qw   = (const float*)d_in[1];  const float* qb  = (const float*)d_in[2];
    const float* kw   = (const float*)d_in[3];  const float* kb  = (const float*)d_in[4];
    const float* vw   = (const float*)d_in[5];  const float* vb  = (const float*)d_in[6];
    const float* ow   = (const float*)d_in[7];  const float* ob  = (const float*)d_in[8];
    const float* n1g  = (const float*)d_in[9];  const float* n1b = (const float*)d_in[10];
    const float* n2g  = (const float*)d_in[11]; const float* n2b = (const float*)d_in[12];
    const float* alpha= (const float*)d_in[13];
    const float* dw7  = (const float*)d_in[14];
    const float* dw25 = (const float*)d_in[15];
    const float* dw49 = (const float*)d_in[16];
    const float* rw   = (const float*)d_in[17];
    const float* ew1  = (const float*)d_in[18]; const float* eb1 = (const float*)d_in[19];
    const float* ew2  = (const float*)d_in[20]; const float* eb2 = (const float*)d_in[21];
    const float* tw   = (const float*)d_in[22]; const float* tb  = (const float*)d_in[23];
    float* out = (float*)d_out;

    float* pS   = (float*)sym_addr(g_S);
    float* pBuf = (float*)sym_addr(g_buf);
    __nv_bfloat16* pBufH = (__nv_bfloat16*)sym_addr(g_bufh);
    float* pQKV = (float*)sym_addr(g_qkv);
    __nv_bfloat16* pYH = (__nv_bfloat16*)sym_addr(g_yh);
    float* pXs  = (float*)sym_addr(g_xs);
    __nv_bfloat16* pHH = (__nv_bfloat16*)sym_addr(g_hh);
    float* pMoe = (float*)sym_addr(g_moe);
    int*   pEL  = (int*)sym_addr(g_elist);
    int*   pEC  = (int*)sym_addr(g_ecnt);
    __nv_bfloat16* pRW4 = (__nv_bfloat16*)sym_addr(g_rw4h);
    __nv_bfloat16* pRE1 = (__nv_bfloat16*)sym_addr(g_rew1h);
    __nv_bfloat16* pRE2 = (__nv_bfloat16*)sym_addr(g_rew2h);
    float* pQKVB= (float*)sym_addr(g_qkvb);
    (void)in_sizes; (void)n_in;

    cudaFuncSetAttribute(attn_tc_kernel, cudaFuncAttributeMaxDynamicSharedMemorySize, ATT_SMEM);
    cudaFuncSetAttribute(tc_gemm<0>, cudaFuncAttributeMaxDynamicSharedMemorySize, TCG_SMEM);
    cudaFuncSetAttribute(tc_gemm<1>, cudaFuncAttributeMaxDynamicSharedMemorySize, TCG_SMEM);
    cudaFuncSetAttribute(tc_gemm<2>, cudaFuncAttributeMaxDynamicSharedMemorySize, TCG_SMEM);

    // 0) pre-round weights to bf16 (wide stores) + concat qkv bias
    const int DD8 = D_MODEL*D_MODEL/8;
    const int E18 = NUM_EXPERTS*MOE_HIDDEN*D_MODEL/8;
    const int E28 = NUM_EXPERTS*D_MODEL*MOE_HIDDEN/8;
    dim3 grw((DD8+255)/256, 4);
    round8x4_kernel<<<grw, 256>>>(qw, kw, vw, ow, pRW4, DD8);
    round8_kernel<<<(E18+255)/256, 256>>>(ew1, pRE1, E18);
    round8_kernel<<<(E28+255)/256, 256>>>(ew2, pRE2, E28);
    cudaMemcpyAsync(pQKVB,            qb, D_MODEL*4, cudaMemcpyDeviceToDevice);
    cudaMemcpyAsync(pQKVB + D_MODEL,  kb, D_MODEL*4, cudaMemcpyDeviceToDevice);
    cudaMemcpyAsync(pQKVB + 2*D_MODEL,vb, D_MODEL*4, cudaMemcpyDeviceToDevice);

    // 1) decomposition (combined 49-tap) -> g_Tr, g_S
    dim3 dgrid(D_MODEL/DC_DT, SEQ/DC_NT, BATCH);
    decomp_kernel<<<dgrid, 256>>>(x, alpha, dw7, dw25, dw49);

    // 2) LN1(S) -> bf16 Sn  (warp-per-row)
    ln_kernel<<<TOKENS/8, 256>>>(pS, n1g, n1b, pBufH, nullptr);

    // 3) fused QKV projection: one bf16 GEMM, N=3072
    dim3 gq(QKV_LD/128, TOKENS/128, 1);
    tc_gemm<0><<<gq, 256, TCG_SMEM>>>(pBufH, pRW4, pQKVB, pQKV, D_MODEL, QKV_LD,
                                      nullptr, nullptr, nullptr, 0, 0, 0, 0);

    // 4) attention (tf32, q-tile 128), y -> bf16
    dim3 agrid(BATCH*NHEAD, SEQ/128);
    attn_tc_kernel<<<agrid, 256, ATT_SMEM>>>();

    // 5) O projection + residual S -> g_xs
    dim3 go(D_MODEL/128, TOKENS/128, 1);
    tc_gemm<2><<<go, 256, TCG_SMEM>>>(pYH, pRW4 + (size_t)3*D_MODEL*D_MODEL, ob, pXs,
                                      D_MODEL, D_MODEL,
                                      pS, nullptr, nullptr, 0, 0, 0, 0);

    // 6) LN2 -> bf16 xf (GEMM) + fp32 xf (router)
    ln_kernel<<<TOKENS/8, 256>>>(pXs, n2g, n2b, pBufH, pBuf);

    // 7) router (fp32 xf) + routing lists + aux
    router_kernel<<<TOKENS/8, 256>>>(pBuf, rw);
    route_kernel<<<1, 128>>>();
    aux_kernel<<<1, 256>>>(out, out_size);

    // 8) MoE FFN: fused bf16 GEMM1 + fused compact GEMM2 (blockIdx.z = expert)
    dim3 gh1(MOE_HIDDEN/128, TOKENS/128, NUM_EXPERTS);
    tc_gemm<1><<<gh1, 256, TCG_SMEM>>>(pBufH, pRE1, eb1, (float*)pHH,
                                       D_MODEL, MOE_HIDDEN,
                                       nullptr, pEL, pEC,
                                       0,
                                       (size_t)MOE_HIDDEN*D_MODEL, MOE_HIDDEN,
                                       (size_t)TOKENS*MOE_HIDDEN);
    dim3 gh2(D_MODEL/128, TOKENS/128, NUM_EXPERTS);
    tc_gemm<0><<<gh2, 256, TCG_SMEM>>>(pHH, pRE2, eb2, pMoe,
                                       MOE_HIDDEN, D_MODEL,
                                       nullptr, nullptr, pEC,
                                       (size_t)TOKENS*MOE_HIDDEN,
                                       (size_t)D_MODEL*MOE_HIDDEN, D_MODEL,
                                       (size_t)TOKENS*D_MODEL);

    // 9) final: xs + MoE combine + trend conv + tb
    final_kernel<<<(BND + 255)/256, 256>>>(tw, tb, out);
}